// round 5
// baseline (speedup 1.0000x reference)
#include <cuda_runtime.h>
#include <math.h>
#include <stdint.h>

// ---------------------------------------------------------------------------
// Shapes (fixed): L=12, E=128, H=4, D=32, F=512, B=64, CIN=256, N=257
// Tokens T = B*N = 16448 = 64 * 257
// ---------------------------------------------------------------------------
#define TOKENS 16448
#define NTOK 257
#define BATCH 64

// scratch (device globals; allocation is forbidden)
__device__ float g_x  [TOKENS * 128];   // residual stream
__device__ float g_qkv[TOKENS * 384];
__device__ float g_o  [TOKENS * 128];   // attention output
__device__ float g_ffn[TOKENS * 512];   // ffn hidden

__device__ __forceinline__ float warp_sum(float v) {
    #pragma unroll
    for (int o = 16; o; o >>= 1) v += __shfl_xor_sync(0xffffffffu, v, o);
    return v;
}
__device__ __forceinline__ float warp_max(float v) {
    #pragma unroll
    for (int o = 16; o; o >>= 1) v = fmaxf(v, __shfl_xor_sync(0xffffffffu, v, o));
    return v;
}

__device__ __forceinline__ uint32_t to_tf32(float f) {
    uint32_t u;
    asm("cvt.rna.tf32.f32 %0, %1;" : "=r"(u) : "f"(f));
    return u;
}

// D = A(16x8, row) * B(8x8, col) + D, tf32 in, f32 accum
__device__ __forceinline__ void mma_tf32(float c[4], const uint32_t a[4], const uint32_t b[2]) {
    asm volatile(
        "mma.sync.aligned.m16n8k8.row.col.f32.tf32.tf32.f32 "
        "{%0,%1,%2,%3}, {%4,%5,%6,%7}, {%8,%9}, {%0,%1,%2,%3};"
        : "+f"(c[0]), "+f"(c[1]), "+f"(c[2]), "+f"(c[3])
        : "r"(a[0]), "r"(a[1]), "r"(a[2]), "r"(a[3]), "r"(b[0]), "r"(b[1]));
}

#define SK 36   // padded k-stride: bank = (4g+c)%32 -> conflict-free fragment LDS

// ---------------------------------------------------------------------------
// K=128 GEMM with optional fused LayerNorm on A rows (K == LN axis == 128).
// C[M,N] = LN(A)[M,128] @ W[N,128]^T + bias, fused epilogue.
// MODE 0: +bias   MODE 1: gelu(+bias)   MODE 2: +bias + residual
// Block tile 64 x 128; whole K resident in smem; single __syncthreads.
// 256 threads = 8 warps in 2x4, warp tile 32x32 (2x4 m16n8k8).
// ---------------------------------------------------------------------------
template <int MODE, bool DO_LN>
__global__ __launch_bounds__(256)
void gemm_k128(const float* __restrict__ A, const float* __restrict__ W,
               const float* __restrict__ lns, const float* __restrict__ lnb,
               const float* __restrict__ bias, const float* __restrict__ res,
               float* __restrict__ C, int N)
{
    __shared__ uint32_t As[64][SK * 4];    // 64 rows x 128 cols (stride 144)
    __shared__ uint32_t Bs[128][SK * 4];   // 128 rows x 128 cols
    const int tid = threadIdx.x;
    const int lane = tid & 31, wid = tid >> 5;
    const int warp_m = wid >> 2, warp_n = wid & 3;
    const int m0 = blockIdx.y * 64, n0 = blockIdx.x * 128;
    const int g = lane >> 2, cl = lane & 3;

    // ---- phase 1: A rows + (optional) LN, 4 threads per row ----
    {
        const int row = tid >> 2, q = tid & 3;
        const float* ar = A + (size_t)(m0 + row) * 128 + q * 32;
        float4 v[8];
        #pragma unroll
        for (int j = 0; j < 8; j++) v[j] = ((const float4*)ar)[j];

        float mean = 0.f, rstd;
        if (DO_LN) {
            float s = 0.f;
            #pragma unroll
            for (int j = 0; j < 8; j++) s += v[j].x + v[j].y + v[j].z + v[j].w;
            s += __shfl_xor_sync(0xffffffffu, s, 1);
            s += __shfl_xor_sync(0xffffffffu, s, 2);
            mean = s * (1.f / 128.f);
            float sq = 0.f;
            #pragma unroll
            for (int j = 0; j < 8; j++) {
                float a = v[j].x - mean, b = v[j].y - mean,
                      c = v[j].z - mean, d = v[j].w - mean;
                sq += a * a + b * b + c * c + d * d;
            }
            sq += __shfl_xor_sync(0xffffffffu, sq, 1);
            sq += __shfl_xor_sync(0xffffffffu, sq, 2);
            rstd = rsqrtf(sq * (1.f / 128.f) + 1e-5f);
        }
        uint32_t* dst = &As[row][q * 32];
        #pragma unroll
        for (int j = 0; j < 8; j++) {
            float x0 = v[j].x, x1 = v[j].y, x2 = v[j].z, x3 = v[j].w;
            if (DO_LN) {
                const float4 sv = ((const float4*)(lns + q * 32))[j];
                const float4 bv = ((const float4*)(lnb + q * 32))[j];
                x0 = (x0 - mean) * rstd * sv.x + bv.x;
                x1 = (x1 - mean) * rstd * sv.y + bv.y;
                x2 = (x2 - mean) * rstd * sv.z + bv.z;
                x3 = (x3 - mean) * rstd * sv.w + bv.w;
            }
            uint4 u = make_uint4(to_tf32(x0), to_tf32(x1), to_tf32(x2), to_tf32(x3));
            *(uint4*)(dst + 4 * j) = u;
        }
    }

    // ---- phase 2: B tile (full 128 x 128) ----
    #pragma unroll
    for (int it = 0; it < 16; it++) {
        int idx = tid + it * 256;
        int row = idx >> 5, c4 = (idx & 31) * 4;
        float4 v = *(const float4*)(W + (size_t)(n0 + row) * 128 + c4);
        uint4 u = make_uint4(to_tf32(v.x), to_tf32(v.y), to_tf32(v.z), to_tf32(v.w));
        *(uint4*)(&Bs[row][c4]) = u;
    }
    __syncthreads();

    // ---- mainloop: 16 k-steps of 8 ----
    float acc[2][4][4];
    #pragma unroll
    for (int i = 0; i < 2; i++)
        #pragma unroll
        for (int j = 0; j < 4; j++)
            #pragma unroll
            for (int r = 0; r < 4; r++) acc[i][j][r] = 0.f;

    #pragma unroll
    for (int ks = 0; ks < 16; ks++) {
        const int kk = ks * 8;
        uint32_t af[2][4], bf[4][2];
        #pragma unroll
        for (int mt = 0; mt < 2; mt++) {
            int r = warp_m * 32 + mt * 16 + g;
            af[mt][0] = As[r][kk + cl];
            af[mt][1] = As[r + 8][kk + cl];
            af[mt][2] = As[r][kk + 4 + cl];
            af[mt][3] = As[r + 8][kk + 4 + cl];
        }
        #pragma unroll
        for (int nt = 0; nt < 4; nt++) {
            int n = warp_n * 32 + nt * 8 + g;
            bf[nt][0] = Bs[n][kk + cl];
            bf[nt][1] = Bs[n][kk + 4 + cl];
        }
        #pragma unroll
        for (int mt = 0; mt < 2; mt++)
            #pragma unroll
            for (int nt = 0; nt < 4; nt++)
                mma_tf32(acc[mt][nt], af[mt], bf[nt]);
    }

    // ---- epilogue ----
    #pragma unroll
    for (int mt = 0; mt < 2; mt++) {
        int r = m0 + warp_m * 32 + mt * 16 + g;
        #pragma unroll
        for (int nt = 0; nt < 4; nt++) {
            int n = n0 + warp_n * 32 + nt * 8 + cl * 2;
            float b0 = bias[n], b1 = bias[n + 1];
            float v[4] = {acc[mt][nt][0] + b0, acc[mt][nt][1] + b1,
                          acc[mt][nt][2] + b0, acc[mt][nt][3] + b1};
            if (MODE == 1) {
                #pragma unroll
                for (int i = 0; i < 4; i++)
                    v[i] = v[i] * 0.5f * (1.0f + erff(v[i] * 0.70710678118654752f));
            }
            if (MODE == 2) {
                float2 r0 = *(const float2*)(res + (size_t)r * N + n);
                float2 r1 = *(const float2*)(res + (size_t)(r + 8) * N + n);
                v[0] += r0.x; v[1] += r0.y; v[2] += r1.x; v[3] += r1.y;
            }
            *(float2*)(C + (size_t)r * N + n)       = make_float2(v[0], v[1]);
            *(float2*)(C + (size_t)(r + 8) * N + n) = make_float2(v[2], v[3]);
        }
    }
}

// ---------------------------------------------------------------------------
// Chunked GEMM (for K=512 ffn2): C = A @ W^T + bias (+res). K%32==0.
// ---------------------------------------------------------------------------
template <int MODE>
__global__ __launch_bounds__(256)
void gemm_mma(const float* __restrict__ A, const float* __restrict__ W,
              const float* __restrict__ bias, const float* __restrict__ res,
              float* __restrict__ C, int M, int N, int K)
{
    __shared__ uint32_t As[64][SK];
    __shared__ uint32_t Bs[128][SK];
    const int tid = threadIdx.x;
    const int lane = tid & 31, wid = tid >> 5;
    const int warp_m = wid >> 2, warp_n = wid & 3;
    const int m0 = blockIdx.y * 64, n0 = blockIdx.x * 128;
    const int g = lane >> 2, cl = lane & 3;

    float acc[2][4][4];
    #pragma unroll
    for (int i = 0; i < 2; i++)
        #pragma unroll
        for (int j = 0; j < 4; j++)
            #pragma unroll
            for (int r = 0; r < 4; r++) acc[i][j][r] = 0.f;

    for (int k0 = 0; k0 < K; k0 += 32) {
        #pragma unroll
        for (int it = 0; it < 2; it++) {
            int e = tid + it * 256;
            int row = e >> 3, c4 = (e & 7) * 4;
            float4 v = *(const float4*)(A + (size_t)(m0 + row) * K + k0 + c4);
            As[row][c4 + 0] = to_tf32(v.x);
            As[row][c4 + 1] = to_tf32(v.y);
            As[row][c4 + 2] = to_tf32(v.z);
            As[row][c4 + 3] = to_tf32(v.w);
        }
        #pragma unroll
        for (int it = 0; it < 4; it++) {
            int e = tid + it * 256;
            int row = e >> 3, c4 = (e & 7) * 4;
            float4 v = *(const float4*)(W + (size_t)(n0 + row) * K + k0 + c4);
            Bs[row][c4 + 0] = to_tf32(v.x);
            Bs[row][c4 + 1] = to_tf32(v.y);
            Bs[row][c4 + 2] = to_tf32(v.z);
            Bs[row][c4 + 3] = to_tf32(v.w);
        }
        __syncthreads();

        #pragma unroll
        for (int ks = 0; ks < 4; ks++) {
            const int kk = ks * 8;
            uint32_t af[2][4], bf[4][2];
            #pragma unroll
            for (int mt = 0; mt < 2; mt++) {
                int r = warp_m * 32 + mt * 16 + g;
                af[mt][0] = As[r][kk + cl];
                af[mt][1] = As[r + 8][kk + cl];
                af[mt][2] = As[r][kk + 4 + cl];
                af[mt][3] = As[r + 8][kk + 4 + cl];
            }
            #pragma unroll
            for (int nt = 0; nt < 4; nt++) {
                int n = warp_n * 32 + nt * 8 + g;
                bf[nt][0] = Bs[n][kk + cl];
                bf[nt][1] = Bs[n][kk + 4 + cl];
            }
            #pragma unroll
            for (int mt = 0; mt < 2; mt++)
                #pragma unroll
                for (int nt = 0; nt < 4; nt++)
                    mma_tf32(acc[mt][nt], af[mt], bf[nt]);
        }
        __syncthreads();
    }

    #pragma unroll
    for (int mt = 0; mt < 2; mt++) {
        int r = m0 + warp_m * 32 + mt * 16 + g;
        #pragma unroll
        for (int nt = 0; nt < 4; nt++) {
            int n = n0 + warp_n * 32 + nt * 8 + cl * 2;
            float b0 = bias[n], b1 = bias[n + 1];
            float v[4] = {acc[mt][nt][0] + b0, acc[mt][nt][1] + b1,
                          acc[mt][nt][2] + b0, acc[mt][nt][3] + b1};
            if (MODE == 1) {
                #pragma unroll
                for (int i = 0; i < 4; i++)
                    v[i] = v[i] * 0.5f * (1.0f + erff(v[i] * 0.70710678118654752f));
            }
            if (MODE == 2) {
                float2 r0 = *(const float2*)(res + (size_t)r * N + n);
                float2 r1 = *(const float2*)(res + (size_t)(r + 8) * N + n);
                v[0] += r0.x; v[1] += r0.y; v[2] += r1.x; v[3] += r1.y;
            }
            *(float2*)(C + (size_t)r * N + n)       = make_float2(v[0], v[1]);
            *(float2*)(C + (size_t)(r + 8) * N + n) = make_float2(v[2], v[3]);
        }
    }
}

// ---------------------------------------------------------------------------
// Conv 3x3 s2 p1 as implicit GEMM on tensor cores: M=16384, N=128, K=2304.
// ---------------------------------------------------------------------------
__global__ __launch_bounds__(256)
void conv_mma(const float* __restrict__ feat, const float* __restrict__ W,
              const float* __restrict__ cb, const float* __restrict__ pos,
              float* __restrict__ x)
{
    __shared__ uint32_t As[64][SK];
    __shared__ uint32_t Bs[128][SK];
    const int K = 2304;
    const int tid = threadIdx.x;
    const int lane = tid & 31, wid = tid >> 5;
    const int warp_m = wid >> 2, warp_n = wid & 3;
    const int m0 = blockIdx.y * 64;
    const int g = lane >> 2, cl = lane & 3;

    float acc[2][4][4];
    #pragma unroll
    for (int i = 0; i < 2; i++)
        #pragma unroll
        for (int j = 0; j < 4; j++)
            #pragma unroll
            for (int r = 0; r < 4; r++) acc[i][j][r] = 0.f;

    for (int k0 = 0; k0 < K; k0 += 32) {
        #pragma unroll
        for (int it = 0; it < 8; it++) {
            int e = tid + it * 256;
            int ml = e >> 5, kl = e & 31;
            int m = m0 + ml;
            int k = k0 + kl;
            int b = m >> 8, p = m & 255;
            int y = p >> 4, xx = p & 15;
            int c = k / 9, rr = k - c * 9;
            int ky = rr / 3, kx = rr - ky * 3;
            int iy = y * 2 - 1 + ky;
            int ix = xx * 2 - 1 + kx;
            float v = 0.f;
            if (iy >= 0 && iy < 32 && ix >= 0 && ix < 32)
                v = feat[(((size_t)b * 256 + c) * 32 + iy) * 32 + ix];
            As[ml][kl] = to_tf32(v);
        }
        #pragma unroll
        for (int it = 0; it < 4; it++) {
            int e = tid + it * 256;
            int row = e >> 3, c4 = (e & 7) * 4;
            float4 v = *(const float4*)(W + (size_t)row * K + k0 + c4);
            Bs[row][c4 + 0] = to_tf32(v.x);
            Bs[row][c4 + 1] = to_tf32(v.y);
            Bs[row][c4 + 2] = to_tf32(v.z);
            Bs[row][c4 + 3] = to_tf32(v.w);
        }
        __syncthreads();

        #pragma unroll
        for (int ks = 0; ks < 4; ks++) {
            const int kk = ks * 8;
            uint32_t af[2][4], bf[4][2];
            #pragma unroll
            for (int mt = 0; mt < 2; mt++) {
                int r = warp_m * 32 + mt * 16 + g;
                af[mt][0] = As[r][kk + cl];
                af[mt][1] = As[r + 8][kk + cl];
                af[mt][2] = As[r][kk + 4 + cl];
                af[mt][3] = As[r + 8][kk + 4 + cl];
            }
            #pragma unroll
            for (int nt = 0; nt < 4; nt++) {
                int n = warp_n * 32 + nt * 8 + g;
                bf[nt][0] = Bs[n][kk + cl];
                bf[nt][1] = Bs[n][kk + 4 + cl];
            }
            #pragma unroll
            for (int mt = 0; mt < 2; mt++)
                #pragma unroll
                for (int nt = 0; nt < 4; nt++)
                    mma_tf32(acc[mt][nt], af[mt], bf[nt]);
        }
        __syncthreads();
    }

    #pragma unroll
    for (int mt = 0; mt < 2; mt++) {
        int r = m0 + warp_m * 32 + mt * 16 + g;
        #pragma unroll
        for (int rr = 0; rr < 2; rr++) {
            int m = r + rr * 8;
            int b = m >> 8, p = m & 255;
            float* dst = x + ((size_t)b * NTOK + p + 1) * 128;
            const float* pp = pos + (size_t)(p + 1) * 128;
            #pragma unroll
            for (int nt = 0; nt < 4; nt++) {
                int n = warp_n * 32 + nt * 8 + cl * 2;
                float v0 = acc[mt][nt][rr * 2 + 0] + cb[n] + pp[n];
                float v1 = acc[mt][nt][rr * 2 + 1] + cb[n + 1] + pp[n + 1];
                *(float2*)(dst + n) = make_float2(v0, v1);
            }
        }
    }
}

// cls token rows: x[b,0,:] = cls + pos[0]
__global__ void cls_kernel(const float* __restrict__ cls,
                           const float* __restrict__ pos, float* __restrict__ x)
{
    int b = blockIdx.x, e = threadIdx.x;
    x[(size_t)b * NTOK * 128 + e] = cls[e] + pos[e];
}

// ---------------------------------------------------------------------------
// Attention (R3 proven version): block per (b,h,z). K,V cached in smem.
// 4 queries per warp; grid.z=3 covers 9 query-tiles of 32.
// ---------------------------------------------------------------------------
#define ATT_SMEM ((2 * 257 * 33 + 32 * 264) * 4)

__global__ __launch_bounds__(256)
void attn_kernel(const float* __restrict__ qkv, float* __restrict__ o)
{
    extern __shared__ float sm[];
    float* Ks = sm;                 // [257][33]
    float* Vs = sm + 257 * 33;      // [257][33]
    float* Ps = sm + 2 * 257 * 33;  // [32][264]
    int b = blockIdx.x, h = blockIdx.y, z = blockIdx.z;
    int tid = threadIdx.x, w = tid >> 5, lane = tid & 31;
    const float* base = qkv + (size_t)b * NTOK * 384 + h * 32;

    for (int i = tid; i < 257 * 32; i += 256) {
        int m = i >> 5, d = i & 31;
        Ks[m * 33 + d] = base[(size_t)m * 384 + 128 + d];
        Vs[m * 33 + d] = base[(size_t)m * 384 + 256 + d];
    }
    __syncthreads();

    const float scale = 0.17677669529663687f;  // 1/sqrt(32)
    for (int t = z * 3; t < z * 3 + 3; t++) {
        if (t * 32 >= NTOK) break;
        int qbase = t * 32 + w * 4;
        float qd[4];
        bool val[4];
        #pragma unroll
        for (int qq = 0; qq < 4; qq++) {
            int n = qbase + qq;
            val[qq] = n < NTOK;
            qd[qq] = val[qq] ? base[(size_t)n * 384 + lane] : 0.f;
        }
        float sc[4][9];
        #pragma unroll
        for (int qq = 0; qq < 4; qq++)
            #pragma unroll
            for (int j = 0; j < 9; j++) sc[qq][j] = 0.f;

        #pragma unroll 4
        for (int d = 0; d < 32; d++) {
            float qv[4];
            #pragma unroll
            for (int qq = 0; qq < 4; qq++)
                qv[qq] = __shfl_sync(0xffffffffu, qd[qq], d);
            #pragma unroll
            for (int j = 0; j < 8; j++) {
                float kv = Ks[(lane + 32 * j) * 33 + d];
                #pragma unroll
                for (int qq = 0; qq < 4; qq++) sc[qq][j] += qv[qq] * kv;
            }
            float kv8 = Ks[256 * 33 + d];
            #pragma unroll
            for (int qq = 0; qq < 4; qq++) sc[qq][8] += qv[qq] * kv8;
        }

        #pragma unroll
        for (int qq = 0; qq < 4; qq++) {
            float mx = -1e30f;
            #pragma unroll
            for (int j = 0; j < 9; j++) {
                bool ok = (lane + 32 * j) < NTOK;
                sc[qq][j] = ok ? sc[qq][j] * scale : -1e30f;
                mx = fmaxf(mx, sc[qq][j]);
            }
            mx = warp_max(mx);
            float lsum = 0.f;
            #pragma unroll
            for (int j = 0; j < 9; j++) {
                bool ok = (lane + 32 * j) < NTOK;
                sc[qq][j] = ok ? __expf(sc[qq][j] - mx) : 0.f;
                lsum += sc[qq][j];
            }
            float inv = 1.f / warp_sum(lsum);
            #pragma unroll
            for (int j = 0; j < 9; j++) {
                int m = lane + 32 * j;
                if (m < NTOK) Ps[(w * 4 + qq) * 264 + m] = sc[qq][j] * inv;
            }
        }
        __syncwarp();

        float acc[4] = {0.f, 0.f, 0.f, 0.f};
        #pragma unroll 4
        for (int m = 0; m < NTOK; m++) {
            float v = Vs[m * 33 + lane];
            #pragma unroll
            for (int qq = 0; qq < 4; qq++)
                acc[qq] += Ps[(w * 4 + qq) * 264 + m] * v;
        }
        #pragma unroll
        for (int qq = 0; qq < 4; qq++)
            if (val[qq])
                o[((size_t)b * NTOK + qbase + qq) * 128 + h * 32 + lane] = acc[qq];
        __syncwarp();
    }
}

// ---------------------------------------------------------------------------
// Head: final LN (eps 1e-6) on token 0 of each batch, out_feat + fc.
// ---------------------------------------------------------------------------
__global__ __launch_bounds__(128)
void head_kernel(const float* __restrict__ x, const float* __restrict__ fns,
                 const float* __restrict__ fnb, const float* __restrict__ fcw,
                 const float* __restrict__ fcb, float* __restrict__ out)
{
    __shared__ float red[4];
    __shared__ float fsh[128];
    int b = blockIdx.x, t = threadIdx.x, w = t >> 5, lane = t & 31;
    float v = x[(size_t)b * NTOK * 128 + t];

    float s = warp_sum(v);
    if (lane == 0) red[w] = s;
    __syncthreads();
    float mean = (red[0] + red[1] + red[2] + red[3]) * (1.f / 128.f);
    __syncthreads();
    float d = v - mean;
    float sq = warp_sum(d * d);
    if (lane == 0) red[w] = sq;
    __syncthreads();
    float var = (red[0] + red[1] + red[2] + red[3]) * (1.f / 128.f);
    float rstd = rsqrtf(var + 1e-6f);
    float f = d * rstd * fns[t] + fnb[t];
    out[128 + (size_t)b * 128 + t] = f;
    fsh[t] = f;
    __syncthreads();
    if (t < 2) {
        float a = fcb[t];
        for (int e = 0; e < 128; e++) a += fsh[e] * fcw[t * 128 + e];
        out[b * 2 + t] = a;
    }
}

// ---------------------------------------------------------------------------
extern "C" void kernel_launch(void* const* d_in, const int* in_sizes, int n_in,
                              void* d_out, int out_size)
{
    const float* feat    = (const float*)d_in[0];
    const float* conv_w  = (const float*)d_in[1];
    const float* conv_b  = (const float*)d_in[2];
    const float* pos_emb = (const float*)d_in[3];
    const float* cls_tok = (const float*)d_in[4];
    const float* ln1_s   = (const float*)d_in[5];
    const float* ln1_b   = (const float*)d_in[6];
    const float* qkv_w   = (const float*)d_in[7];
    const float* qkv_b   = (const float*)d_in[8];
    const float* proj_w  = (const float*)d_in[9];
    const float* proj_b  = (const float*)d_in[10];
    const float* ln2_s   = (const float*)d_in[11];
    const float* ln2_b   = (const float*)d_in[12];
    const float* ffn1_w  = (const float*)d_in[13];
    const float* ffn1_b  = (const float*)d_in[14];
    const float* ffn2_w  = (const float*)d_in[15];
    const float* ffn2_b  = (const float*)d_in[16];
    const float* fn_s    = (const float*)d_in[17];
    const float* fn_b    = (const float*)d_in[18];
    const float* fc_w    = (const float*)d_in[19];
    const float* fc_b    = (const float*)d_in[20];
    float* out = (float*)d_out;

    float *px, *pq, *po, *pf;
    cudaGetSymbolAddress((void**)&px, g_x);
    cudaGetSymbolAddress((void**)&pq, g_qkv);
    cudaGetSymbolAddress((void**)&po, g_o);
    cudaGetSymbolAddress((void**)&pf, g_ffn);

    cudaFuncSetAttribute(attn_kernel, cudaFuncAttributeMaxDynamicSharedMemorySize, ATT_SMEM);

    cls_kernel<<<BATCH, 128>>>(cls_tok, pos_emb, px);
    conv_mma<<<dim3(1, 256), 256>>>(feat, conv_w, conv_b, pos_emb, px);

    for (int l = 0; l < 12; l++) {
        gemm_k128<0, true><<<dim3(3, 257), 256>>>(
            px, qkv_w + (size_t)l * 384 * 128,
            ln1_s + l * 128, ln1_b + l * 128,
            qkv_b + l * 384, nullptr, pq, 384);
        attn_kernel<<<dim3(BATCH, 4, 3), 256, ATT_SMEM>>>(pq, po);
        gemm_k128<2, false><<<dim3(1, 257), 256>>>(
            po, proj_w + (size_t)l * 128 * 128,
            nullptr, nullptr,
            proj_b + l * 128, px, px, 128);
        gemm_k128<1, true><<<dim3(4, 257), 256>>>(
            px, ffn1_w + (size_t)l * 512 * 128,
            ln2_s + l * 128, ln2_b + l * 128,
            ffn1_b + l * 512, nullptr, pf, 512);
        gemm_mma<2><<<dim3(1, 257), 256>>>(
            pf, ffn2_w + (size_t)l * 128 * 512, ffn2_b + l * 128, px, px,
            TOKENS, 128, 512);
    }

    head_kernel<<<BATCH, 128>>>(px, fn_s, fn_b, fc_w, fc_b, out);
}

// round 6
// speedup vs baseline: 1.3832x; 1.3832x over previous
#include <cuda_runtime.h>
#include <math.h>
#include <stdint.h>

// ---------------------------------------------------------------------------
// Shapes (fixed): L=12, E=128, H=4, D=32, F=512, B=64, CIN=256, N=257
// Tokens T = B*N = 16448 = 64 * 257
// ---------------------------------------------------------------------------
#define TOKENS 16448
#define NTOK 257
#define BATCH 64

// scratch (device globals; allocation is forbidden)
__device__ float g_x  [TOKENS * 128];   // residual stream
__device__ float g_h  [TOKENS * 128];   // post-LN
__device__ float g_qkv[TOKENS * 384];
__device__ float g_o  [TOKENS * 128];   // attention output
__device__ float g_ffn[TOKENS * 512];   // ffn hidden

__device__ __forceinline__ float warp_sum(float v) {
    #pragma unroll
    for (int o = 16; o; o >>= 1) v += __shfl_xor_sync(0xffffffffu, v, o);
    return v;
}
__device__ __forceinline__ float warp_max(float v) {
    #pragma unroll
    for (int o = 16; o; o >>= 1) v = fmaxf(v, __shfl_xor_sync(0xffffffffu, v, o));
    return v;
}

__device__ __forceinline__ uint32_t to_tf32(float f) {
    uint32_t u;
    asm("cvt.rna.tf32.f32 %0, %1;" : "=r"(u) : "f"(f));
    return u;
}

// D = A(16x8, row) * B(8x8, col) + D, tf32 in, f32 accum
__device__ __forceinline__ void mma_tf32(float c[4], const uint32_t a[4], const uint32_t b[2]) {
    asm volatile(
        "mma.sync.aligned.m16n8k8.row.col.f32.tf32.tf32.f32 "
        "{%0,%1,%2,%3}, {%4,%5,%6,%7}, {%8,%9}, {%0,%1,%2,%3};"
        : "+f"(c[0]), "+f"(c[1]), "+f"(c[2]), "+f"(c[3])
        : "r"(a[0]), "r"(a[1]), "r"(a[2]), "r"(a[3]), "r"(b[0]), "r"(b[1]));
}

#define SK 36   // padded k-stride: conflict-free fragment LDS

// ---------------------------------------------------------------------------
// Pipelined tensor-core GEMM: C[M,N] = A[M,K] @ W[N,K]^T + bias, fused epi.
// MODE 0: +bias   MODE 1: gelu(+bias)   MODE 2: +bias + residual
// Block tile 64x128, K-chunk 32, double-buffered smem, register prefetch.
// 256 threads = 8 warps in 2x4, warp tile 32x32.
// ---------------------------------------------------------------------------
template <int MODE>
__global__ __launch_bounds__(256)
void gemm_mma(const float* __restrict__ A, const float* __restrict__ W,
              const float* __restrict__ bias, const float* __restrict__ res,
              float* __restrict__ C, int M, int N, int K)
{
    __shared__ uint32_t As[2][64][SK];
    __shared__ uint32_t Bs[2][128][SK];
    const int tid = threadIdx.x;
    const int lane = tid & 31, wid = tid >> 5;
    const int warp_m = wid >> 2, warp_n = wid & 3;
    const int m0 = blockIdx.y * 64, n0 = blockIdx.x * 128;
    const int g = lane >> 2, cl = lane & 3;

    const int arow = tid >> 3, ac4 = (tid & 7) * 4;     // A: 2 float4/thread
    const float* Aptr0 = A + (size_t)(m0 + arow) * K + ac4;
    const float* Aptr1 = A + (size_t)(m0 + arow + 32) * K + ac4;
    const float* Wp[4];
    #pragma unroll
    for (int it = 0; it < 4; it++)
        Wp[it] = W + (size_t)(n0 + arow + it * 32) * K + ac4;

    float4 ra[2], rb[4];
    ra[0] = *(const float4*)Aptr0;
    ra[1] = *(const float4*)Aptr1;
    #pragma unroll
    for (int it = 0; it < 4; it++) rb[it] = *(const float4*)Wp[it];

    float acc[2][4][4];
    #pragma unroll
    for (int i = 0; i < 2; i++)
        #pragma unroll
        for (int j = 0; j < 4; j++)
            #pragma unroll
            for (int r = 0; r < 4; r++) acc[i][j][r] = 0.f;

    const int nc = K >> 5;
    for (int c = 0; c < nc; c++) {
        const int buf = c & 1;
        // store current chunk (regs -> smem, cvt to tf32)
        #pragma unroll
        for (int it = 0; it < 2; it++) {
            float4 v = ra[it];
            uint32_t* d = &As[buf][arow + it * 32][ac4];
            d[0] = to_tf32(v.x); d[1] = to_tf32(v.y);
            d[2] = to_tf32(v.z); d[3] = to_tf32(v.w);
        }
        #pragma unroll
        for (int it = 0; it < 4; it++) {
            float4 v = rb[it];
            uint32_t* d = &Bs[buf][arow + it * 32][ac4];
            d[0] = to_tf32(v.x); d[1] = to_tf32(v.y);
            d[2] = to_tf32(v.z); d[3] = to_tf32(v.w);
        }
        __syncthreads();

        // prefetch next chunk into regs (overlaps with mma below)
        if (c + 1 < nc) {
            int off = (c + 1) * 32;
            ra[0] = *(const float4*)(Aptr0 + off);
            ra[1] = *(const float4*)(Aptr1 + off);
            #pragma unroll
            for (int it = 0; it < 4; it++)
                rb[it] = *(const float4*)(Wp[it] + off);
        }

        #pragma unroll
        for (int ks = 0; ks < 4; ks++) {
            const int kk = ks * 8;
            uint32_t af[2][4], bf[4][2];
            #pragma unroll
            for (int mt = 0; mt < 2; mt++) {
                int r = warp_m * 32 + mt * 16 + g;
                af[mt][0] = As[buf][r][kk + cl];
                af[mt][1] = As[buf][r + 8][kk + cl];
                af[mt][2] = As[buf][r][kk + 4 + cl];
                af[mt][3] = As[buf][r + 8][kk + 4 + cl];
            }
            #pragma unroll
            for (int nt = 0; nt < 4; nt++) {
                int n = warp_n * 32 + nt * 8 + g;
                bf[nt][0] = Bs[buf][n][kk + cl];
                bf[nt][1] = Bs[buf][n][kk + 4 + cl];
            }
            #pragma unroll
            for (int mt = 0; mt < 2; mt++)
                #pragma unroll
                for (int nt = 0; nt < 4; nt++)
                    mma_tf32(acc[mt][nt], af[mt], bf[nt]);
        }
    }

    #pragma unroll
    for (int mt = 0; mt < 2; mt++) {
        int r = m0 + warp_m * 32 + mt * 16 + g;
        #pragma unroll
        for (int nt = 0; nt < 4; nt++) {
            int n = n0 + warp_n * 32 + nt * 8 + cl * 2;
            float b0 = bias[n], b1 = bias[n + 1];
            float v[4] = {acc[mt][nt][0] + b0, acc[mt][nt][1] + b1,
                          acc[mt][nt][2] + b0, acc[mt][nt][3] + b1};
            if (MODE == 1) {
                #pragma unroll
                for (int i = 0; i < 4; i++)
                    v[i] = v[i] * 0.5f * (1.0f + erff(v[i] * 0.70710678118654752f));
            }
            if (MODE == 2) {
                float2 r0 = *(const float2*)(res + (size_t)r * N + n);
                float2 r1 = *(const float2*)(res + (size_t)(r + 8) * N + n);
                v[0] += r0.x; v[1] += r0.y; v[2] += r1.x; v[3] += r1.y;
            }
            *(float2*)(C + (size_t)r * N + n)       = make_float2(v[0], v[1]);
            *(float2*)(C + (size_t)(r + 8) * N + n) = make_float2(v[2], v[3]);
        }
    }
}

// ---------------------------------------------------------------------------
// Conv 3x3 s2 p1 as implicit GEMM on tensor cores: M=16384, N=128, K=2304.
// ---------------------------------------------------------------------------
__global__ __launch_bounds__(256)
void conv_mma(const float* __restrict__ feat, const float* __restrict__ W,
              const float* __restrict__ cb, const float* __restrict__ pos,
              float* __restrict__ x)
{
    __shared__ uint32_t As[64][SK];
    __shared__ uint32_t Bs[128][SK];
    const int K = 2304;
    const int tid = threadIdx.x;
    const int lane = tid & 31, wid = tid >> 5;
    const int warp_m = wid >> 2, warp_n = wid & 3;
    const int m0 = blockIdx.y * 64;
    const int g = lane >> 2, cl = lane & 3;

    float acc[2][4][4];
    #pragma unroll
    for (int i = 0; i < 2; i++)
        #pragma unroll
        for (int j = 0; j < 4; j++)
            #pragma unroll
            for (int r = 0; r < 4; r++) acc[i][j][r] = 0.f;

    for (int k0 = 0; k0 < K; k0 += 32) {
        #pragma unroll
        for (int it = 0; it < 8; it++) {
            int e = tid + it * 256;
            int ml = e >> 5, kl = e & 31;
            int m = m0 + ml;
            int k = k0 + kl;
            int b = m >> 8, p = m & 255;
            int y = p >> 4, xx = p & 15;
            int c = k / 9, rr = k - c * 9;
            int ky = rr / 3, kx = rr - ky * 3;
            int iy = y * 2 - 1 + ky;
            int ix = xx * 2 - 1 + kx;
            float v = 0.f;
            if (iy >= 0 && iy < 32 && ix >= 0 && ix < 32)
                v = feat[(((size_t)b * 256 + c) * 32 + iy) * 32 + ix];
            As[ml][kl] = to_tf32(v);
        }
        #pragma unroll
        for (int it = 0; it < 4; it++) {
            int e = tid + it * 256;
            int row = e >> 3, c4 = (e & 7) * 4;
            float4 v = *(const float4*)(W + (size_t)row * K + k0 + c4);
            Bs[row][c4 + 0] = to_tf32(v.x);
            Bs[row][c4 + 1] = to_tf32(v.y);
            Bs[row][c4 + 2] = to_tf32(v.z);
            Bs[row][c4 + 3] = to_tf32(v.w);
        }
        __syncthreads();

        #pragma unroll
        for (int ks = 0; ks < 4; ks++) {
            const int kk = ks * 8;
            uint32_t af[2][4], bf[4][2];
            #pragma unroll
            for (int mt = 0; mt < 2; mt++) {
                int r = warp_m * 32 + mt * 16 + g;
                af[mt][0] = As[r][kk + cl];
                af[mt][1] = As[r + 8][kk + cl];
                af[mt][2] = As[r][kk + 4 + cl];
                af[mt][3] = As[r + 8][kk + 4 + cl];
            }
            #pragma unroll
            for (int nt = 0; nt < 4; nt++) {
                int n = warp_n * 32 + nt * 8 + g;
                bf[nt][0] = Bs[n][kk + cl];
                bf[nt][1] = Bs[n][kk + 4 + cl];
            }
            #pragma unroll
            for (int mt = 0; mt < 2; mt++)
                #pragma unroll
                for (int nt = 0; nt < 4; nt++)
                    mma_tf32(acc[mt][nt], af[mt], bf[nt]);
        }
        __syncthreads();
    }

    #pragma unroll
    for (int mt = 0; mt < 2; mt++) {
        int r = m0 + warp_m * 32 + mt * 16 + g;
        #pragma unroll
        for (int rr = 0; rr < 2; rr++) {
            int m = r + rr * 8;
            int b = m >> 8, p = m & 255;
            float* dst = x + ((size_t)b * NTOK + p + 1) * 128;
            const float* pp = pos + (size_t)(p + 1) * 128;
            #pragma unroll
            for (int nt = 0; nt < 4; nt++) {
                int n = warp_n * 32 + nt * 8 + cl * 2;
                float v0 = acc[mt][nt][rr * 2 + 0] + cb[n] + pp[n];
                float v1 = acc[mt][nt][rr * 2 + 1] + cb[n + 1] + pp[n + 1];
                *(float2*)(dst + n) = make_float2(v0, v1);
            }
        }
    }
}

// cls token rows: x[b,0,:] = cls + pos[0]
__global__ void cls_kernel(const float* __restrict__ cls,
                           const float* __restrict__ pos, float* __restrict__ x)
{
    int b = blockIdx.x, e = threadIdx.x;
    x[(size_t)b * NTOK * 128 + e] = cls[e] + pos[e];
}

// ---------------------------------------------------------------------------
// LayerNorm over E=128: 1 warp per token, float4 lanes.
// ---------------------------------------------------------------------------
__global__ __launch_bounds__(256)
void ln_kernel(const float* __restrict__ x, float* __restrict__ h,
               const float* __restrict__ s, const float* __restrict__ b, float eps)
{
    int tok = blockIdx.x * 8 + (threadIdx.x >> 5);
    int lane = threadIdx.x & 31;
    if (tok >= TOKENS) return;
    const float4* xr = (const float4*)(x + (size_t)tok * 128);
    float4 v = xr[lane];
    float mean = warp_sum(v.x + v.y + v.z + v.w) * (1.f / 128.f);
    float dx = v.x - mean, dy = v.y - mean, dz = v.z - mean, dw = v.w - mean;
    float var = warp_sum(dx * dx + dy * dy + dz * dz + dw * dw) * (1.f / 128.f);
    float rstd = rsqrtf(var + eps);
    float4 sv = ((const float4*)s)[lane];
    float4 bv = ((const float4*)b)[lane];
    float4 o;
    o.x = dx * rstd * sv.x + bv.x;
    o.y = dy * rstd * sv.y + bv.y;
    o.z = dz * rstd * sv.z + bv.z;
    o.w = dw * rstd * sv.w + bv.w;
    ((float4*)(h + (size_t)tok * 128))[lane] = o;
}

// ---------------------------------------------------------------------------
// Attention: block per (b,h,z). K,V cached in smem. 4 queries per warp.
// QK: key-256 hoisted out of the d-loop (saves 128 wasted FMA/tile).
// PV: float4 broadcast loads of P, 8-key unroll (16 LDS per 32 FMA).
// ---------------------------------------------------------------------------
#define PS_OFF 16964   // 16B-aligned float offset for Ps
#define ATT_SMEM ((PS_OFF + 32 * 264) * 4)

__global__ __launch_bounds__(256)
void attn_kernel(const float* __restrict__ qkv, float* __restrict__ o)
{
    extern __shared__ float sm[];
    float* Ks = sm;                 // [257][33]
    float* Vs = sm + 257 * 33;      // [257][33]
    float* Ps = sm + PS_OFF;        // [32][264], 16B-aligned rows
    int b = blockIdx.x, h = blockIdx.y, z = blockIdx.z;
    int tid = threadIdx.x, w = tid >> 5, lane = tid & 31;
    const float* base = qkv + (size_t)b * NTOK * 384 + h * 32;

    for (int i = tid; i < 257 * 32; i += 256) {
        int m = i >> 5, d = i & 31;
        Ks[m * 33 + d] = base[(size_t)m * 384 + 128 + d];
        Vs[m * 33 + d] = base[(size_t)m * 384 + 256 + d];
    }
    __syncthreads();

    const float scale = 0.17677669529663687f;  // 1/sqrt(32)
    const float k256 = Ks[256 * 33 + lane];
    for (int t = z * 3; t < z * 3 + 3; t++) {
        if (t * 32 >= NTOK) break;
        int qbase = t * 32 + w * 4;
        float qd[4];
        bool val[4];
        #pragma unroll
        for (int qq = 0; qq < 4; qq++) {
            int n = qbase + qq;
            val[qq] = n < NTOK;
            qd[qq] = val[qq] ? base[(size_t)n * 384 + lane] : 0.f;
        }
        float sc[4][9];
        #pragma unroll
        for (int qq = 0; qq < 4; qq++)
            #pragma unroll
            for (int j = 0; j < 8; j++) sc[qq][j] = 0.f;

        #pragma unroll 4
        for (int d = 0; d < 32; d++) {
            float qv[4];
            #pragma unroll
            for (int qq = 0; qq < 4; qq++)
                qv[qq] = __shfl_sync(0xffffffffu, qd[qq], d);
            #pragma unroll
            for (int j = 0; j < 8; j++) {
                float kv = Ks[(lane + 32 * j) * 33 + d];
                #pragma unroll
                for (int qq = 0; qq < 4; qq++) sc[qq][j] += qv[qq] * kv;
            }
        }
        // key 256 handled once via warp reduction (lane d = lane)
        #pragma unroll
        for (int qq = 0; qq < 4; qq++)
            sc[qq][8] = warp_sum(qd[qq] * k256);

        #pragma unroll
        for (int qq = 0; qq < 4; qq++) {
            float mx = -1e30f;
            #pragma unroll
            for (int j = 0; j < 9; j++) {
                bool ok = (lane + 32 * j) < NTOK;
                sc[qq][j] = ok ? sc[qq][j] * scale : -1e30f;
                mx = fmaxf(mx, sc[qq][j]);
            }
            mx = warp_max(mx);
            float lsum = 0.f;
            #pragma unroll
            for (int j = 0; j < 9; j++) {
                bool ok = (lane + 32 * j) < NTOK;
                sc[qq][j] = ok ? __expf(sc[qq][j] - mx) : 0.f;
                lsum += sc[qq][j];
            }
            float inv = 1.f / warp_sum(lsum);
            #pragma unroll
            for (int j = 0; j < 9; j++) {
                int m = lane + 32 * j;
                if (m < NTOK) Ps[(w * 4 + qq) * 264 + m] = sc[qq][j] * inv;
            }
        }
        __syncwarp();

        // PV: lane owns d=lane; float4 broadcast loads of P, 8-key unroll
        float acc[4] = {0.f, 0.f, 0.f, 0.f};
        for (int m = 0; m < 256; m += 8) {
            float v0 = Vs[(m + 0) * 33 + lane];
            float v1 = Vs[(m + 1) * 33 + lane];
            float v2 = Vs[(m + 2) * 33 + lane];
            float v3 = Vs[(m + 3) * 33 + lane];
            float v4 = Vs[(m + 4) * 33 + lane];
            float v5 = Vs[(m + 5) * 33 + lane];
            float v6 = Vs[(m + 6) * 33 + lane];
            float v7 = Vs[(m + 7) * 33 + lane];
            #pragma unroll
            for (int qq = 0; qq < 4; qq++) {
                const float* pr = Ps + (w * 4 + qq) * 264 + m;
                float4 p0 = *(const float4*)pr;
                float4 p1 = *(const float4*)(pr + 4);
                acc[qq] += p0.x * v0; acc[qq] += p0.y * v1;
                acc[qq] += p0.z * v2; acc[qq] += p0.w * v3;
                acc[qq] += p1.x * v4; acc[qq] += p1.y * v5;
                acc[qq] += p1.z * v6; acc[qq] += p1.w * v7;
            }
        }
        {
            float v = Vs[256 * 33 + lane];
            #pragma unroll
            for (int qq = 0; qq < 4; qq++)
                acc[qq] += Ps[(w * 4 + qq) * 264 + 256] * v;
        }
        #pragma unroll
        for (int qq = 0; qq < 4; qq++)
            if (val[qq])
                o[((size_t)b * NTOK + qbase + qq) * 128 + h * 32 + lane] = acc[qq];
        __syncwarp();
    }
}

// ---------------------------------------------------------------------------
// Head: final LN (eps 1e-6) on token 0 of each batch, out_feat + fc.
// out layout: d_out[0:128) = out (64x2), d_out[128:8320) = out_feat (64x128)
// ---------------------------------------------------------------------------
__global__ __launch_bounds__(128)
void head_kernel(const float* __restrict__ x, const float* __restrict__ fns,
                 const float* __restrict__ fnb, const float* __restrict__ fcw,
                 const float* __restrict__ fcb, float* __restrict__ out)
{
    __shared__ float red[4];
    __shared__ float fsh[128];
    int b = blockIdx.x, t = threadIdx.x, w = t >> 5, lane = t & 31;
    float v = x[(size_t)b * NTOK * 128 + t];

    float s = warp_sum(v);
    if (lane == 0) red[w] = s;
    __syncthreads();
    float mean = (red[0] + red[1] + red[2] + red[3]) * (1.f / 128.f);
    __syncthreads();
    float d = v - mean;
    float sq = warp_sum(d * d);
    if (lane == 0) red[w] = sq;
    __syncthreads();
    float var = (red[0] + red[1] + red[2] + red[3]) * (1.f / 128.f);
    float rstd = rsqrtf(var + 1e-6f);
    float f = d * rstd * fns[t] + fnb[t];
    out[128 + (size_t)b * 128 + t] = f;
    fsh[t] = f;
    __syncthreads();
    if (t < 2) {
        float a = fcb[t];
        for (int e = 0; e < 128; e++) a += fsh[e] * fcw[t * 128 + e];
        out[b * 2 + t] = a;
    }
}

// ---------------------------------------------------------------------------
extern "C" void kernel_launch(void* const* d_in, const int* in_sizes, int n_in,
                              void* d_out, int out_size)
{
    const float* feat    = (const float*)d_in[0];
    const float* conv_w  = (const float*)d_in[1];
    const float* conv_b  = (const float*)d_in[2];
    const float* pos_emb = (const float*)d_in[3];
    const float* cls_tok = (const float*)d_in[4];
    const float* ln1_s   = (const float*)d_in[5];
    const float* ln1_b   = (const float*)d_in[6];
    const float* qkv_w   = (const float*)d_in[7];
    const float* qkv_b   = (const float*)d_in[8];
    const float* proj_w  = (const float*)d_in[9];
    const float* proj_b  = (const float*)d_in[10];
    const float* ln2_s   = (const float*)d_in[11];
    const float* ln2_b   = (const float*)d_in[12];
    const float* ffn1_w  = (const float*)d_in[13];
    const float* ffn1_b  = (const float*)d_in[14];
    const float* ffn2_w  = (const float*)d_in[15];
    const float* ffn2_b  = (const float*)d_in[16];
    const float* fn_s    = (const float*)d_in[17];
    const float* fn_b    = (const float*)d_in[18];
    const float* fc_w    = (const float*)d_in[19];
    const float* fc_b    = (const float*)d_in[20];
    float* out = (float*)d_out;

    float *px, *ph, *pq, *po, *pf;
    cudaGetSymbolAddress((void**)&px, g_x);
    cudaGetSymbolAddress((void**)&ph, g_h);
    cudaGetSymbolAddress((void**)&pq, g_qkv);
    cudaGetSymbolAddress((void**)&po, g_o);
    cudaGetSymbolAddress((void**)&pf, g_ffn);

    cudaFuncSetAttribute(attn_kernel, cudaFuncAttributeMaxDynamicSharedMemorySize, ATT_SMEM);

    cls_kernel<<<BATCH, 128>>>(cls_tok, pos_emb, px);
    conv_mma<<<dim3(1, 256), 256>>>(feat, conv_w, conv_b, pos_emb, px);

    for (int l = 0; l < 12; l++) {
        ln_kernel<<<TOKENS / 8, 256>>>(px, ph, ln1_s + l * 128, ln1_b + l * 128, 1e-5f);
        gemm_mma<0><<<dim3(3, 257), 256>>>(
            ph, qkv_w + (size_t)l * 384 * 128, qkv_b + l * 384, nullptr, pq,
            TOKENS, 384, 128);
        attn_kernel<<<dim3(BATCH, 4, 3), 256, ATT_SMEM>>>(pq, po);
        gemm_mma<2><<<dim3(1, 257), 256>>>(
            po, proj_w + (size_t)l * 128 * 128, proj_b + l * 128, px, px,
            TOKENS, 128, 128);
        ln_kernel<<<TOKENS / 8, 256>>>(px, ph, ln2_s + l * 128, ln2_b + l * 128, 1e-5f);
        gemm_mma<1><<<dim3(4, 257), 256>>>(
            ph, ffn1_w + (size_t)l * 512 * 128, ffn1_b + l * 512, nullptr, pf,
            TOKENS, 512, 128);
        gemm_mma<2><<<dim3(1, 257), 256>>>(
            pf, ffn2_w + (size_t)l * 128 * 512, ffn2_b + l * 128, px, px,
            TOKENS, 128, 512);
    }

    head_kernel<<<BATCH, 128>>>(px, fn_s, fn_b, fc_w, fc_b, out);
}

// round 7
// speedup vs baseline: 1.4084x; 1.0182x over previous
#include <cuda_runtime.h>
#include <math.h>
#include <stdint.h>

// ---------------------------------------------------------------------------
// Shapes (fixed): L=12, E=128, H=4, D=32, F=512, B=64, CIN=256, N=257
// Tokens T = B*N = 16448 = 64 * 257
// ---------------------------------------------------------------------------
#define TOKENS 16448
#define NTOK 257
#define BATCH 64

// scratch (device globals; allocation is forbidden)
__device__ float g_x  [TOKENS * 128];   // residual stream
__device__ float g_h  [TOKENS * 128];   // post-LN
__device__ float g_qkv[TOKENS * 384];
__device__ float g_o  [TOKENS * 128];   // attention output
__device__ float g_ffn[TOKENS * 512];   // ffn hidden

__device__ __forceinline__ float warp_sum(float v) {
    #pragma unroll
    for (int o = 16; o; o >>= 1) v += __shfl_xor_sync(0xffffffffu, v, o);
    return v;
}
__device__ __forceinline__ float warp_max(float v) {
    #pragma unroll
    for (int o = 16; o; o >>= 1) v = fmaxf(v, __shfl_xor_sync(0xffffffffu, v, o));
    return v;
}

__device__ __forceinline__ uint32_t to_tf32(float f) {
    uint32_t u;
    asm("cvt.rna.tf32.f32 %0, %1;" : "=r"(u) : "f"(f));
    return u;
}

// D = A(16x8, row) * B(8x8, col) + D, tf32 in, f32 accum
__device__ __forceinline__ void mma_tf32(float c[4], const uint32_t a[4], const uint32_t b[2]) {
    asm volatile(
        "mma.sync.aligned.m16n8k8.row.col.f32.tf32.tf32.f32 "
        "{%0,%1,%2,%3}, {%4,%5,%6,%7}, {%8,%9}, {%0,%1,%2,%3};"
        : "+f"(c[0]), "+f"(c[1]), "+f"(c[2]), "+f"(c[3])
        : "r"(a[0]), "r"(a[1]), "r"(a[2]), "r"(a[3]), "r"(b[0]), "r"(b[1]));
}

__device__ __forceinline__ void cp16(void* smem, const void* g) {
    uint32_t s = (uint32_t)__cvta_generic_to_shared(smem);
    asm volatile("cp.async.cg.shared.global [%0], [%1], 16;" :: "r"(s), "l"(g));
}
__device__ __forceinline__ void cp_commit() {
    asm volatile("cp.async.commit_group;");
}
__device__ __forceinline__ void cp_wait0() {
    asm volatile("cp.async.wait_group 0;");
}

#define SK 36   // padded k-stride: conflict-free fragment LDS

// ---------------------------------------------------------------------------
// cp.async double-buffered tensor-core GEMM. C = A @ W^T + bias, fused epi.
// MODE 0: +bias   MODE 1: gelu(+bias)   MODE 2: +bias+res
// MODE 3: +bias+res, and ALSO writes LN(C) to Hout (N must be 128 = LN axis)
// Block tile 64x128, K-chunk 32. smem holds raw fp32; cvt to tf32 at
// fragment-read time (keeps RNA rounding identical to previous rounds).
// ---------------------------------------------------------------------------
template <int MODE>
__global__ __launch_bounds__(256)
void gemm_mma(const float* __restrict__ A, const float* __restrict__ W,
              const float* __restrict__ lns, const float* __restrict__ lnb,
              const float* __restrict__ bias, const float* __restrict__ res,
              float* __restrict__ C, float* __restrict__ Hout,
              int M, int N, int K)
{
    __shared__ float As[2][64][SK];
    __shared__ float Bs[2][128][SK];
    const int tid = threadIdx.x;
    const int lane = tid & 31, wid = tid >> 5;
    const int warp_m = wid >> 2, warp_n = wid & 3;
    const int m0 = blockIdx.y * 64, n0 = blockIdx.x * 128;
    const int g = lane >> 2, cl = lane & 3;

    const int arow = tid >> 3, ac4 = (tid & 7) * 4;
    const float* Ap0 = A + (size_t)(m0 + arow) * K + ac4;
    const float* Ap1 = A + (size_t)(m0 + arow + 32) * K + ac4;
    const float* Wp0 = W + (size_t)(n0 + arow) * K + ac4;
    const float* Wp1 = W + (size_t)(n0 + arow + 32) * K + ac4;
    const float* Wp2 = W + (size_t)(n0 + arow + 64) * K + ac4;
    const float* Wp3 = W + (size_t)(n0 + arow + 96) * K + ac4;

    const int nc = K >> 5;

    // issue stage 0
    {
        cp16(&As[0][arow][ac4], Ap0);
        cp16(&As[0][arow + 32][ac4], Ap1);
        cp16(&Bs[0][arow][ac4], Wp0);
        cp16(&Bs[0][arow + 32][ac4], Wp1);
        cp16(&Bs[0][arow + 64][ac4], Wp2);
        cp16(&Bs[0][arow + 96][ac4], Wp3);
        cp_commit();
    }

    float acc[2][4][4];
    #pragma unroll
    for (int i = 0; i < 2; i++)
        #pragma unroll
        for (int j = 0; j < 4; j++)
            #pragma unroll
            for (int r = 0; r < 4; r++) acc[i][j][r] = 0.f;

    for (int c = 0; c < nc; c++) {
        const int buf = c & 1;
        cp_wait0();
        __syncthreads();

        if (c + 1 < nc) {
            const int nb = buf ^ 1, off = (c + 1) * 32;
            cp16(&As[nb][arow][ac4], Ap0 + off);
            cp16(&As[nb][arow + 32][ac4], Ap1 + off);
            cp16(&Bs[nb][arow][ac4], Wp0 + off);
            cp16(&Bs[nb][arow + 32][ac4], Wp1 + off);
            cp16(&Bs[nb][arow + 64][ac4], Wp2 + off);
            cp16(&Bs[nb][arow + 96][ac4], Wp3 + off);
            cp_commit();
        }

        #pragma unroll
        for (int ks = 0; ks < 4; ks++) {
            const int kk = ks * 8;
            uint32_t af[2][4], bf[4][2];
            #pragma unroll
            for (int mt = 0; mt < 2; mt++) {
                int r = warp_m * 32 + mt * 16 + g;
                af[mt][0] = to_tf32(As[buf][r][kk + cl]);
                af[mt][1] = to_tf32(As[buf][r + 8][kk + cl]);
                af[mt][2] = to_tf32(As[buf][r][kk + 4 + cl]);
                af[mt][3] = to_tf32(As[buf][r + 8][kk + 4 + cl]);
            }
            #pragma unroll
            for (int nt = 0; nt < 4; nt++) {
                int n = warp_n * 32 + nt * 8 + g;
                bf[nt][0] = to_tf32(Bs[buf][n][kk + cl]);
                bf[nt][1] = to_tf32(Bs[buf][n][kk + 4 + cl]);
            }
            #pragma unroll
            for (int mt = 0; mt < 2; mt++)
                #pragma unroll
                for (int nt = 0; nt < 4; nt++)
                    mma_tf32(acc[mt][nt], af[mt], bf[nt]);
        }
    }

    // ---- epilogue: bias (+gelu / +res), held in acc ----
    #pragma unroll
    for (int mt = 0; mt < 2; mt++) {
        int r = m0 + warp_m * 32 + mt * 16 + g;
        #pragma unroll
        for (int nt = 0; nt < 4; nt++) {
            int n = n0 + warp_n * 32 + nt * 8 + cl * 2;
            float b0 = bias[n], b1 = bias[n + 1];
            acc[mt][nt][0] += b0; acc[mt][nt][1] += b1;
            acc[mt][nt][2] += b0; acc[mt][nt][3] += b1;
            if (MODE == 1) {
                #pragma unroll
                for (int i = 0; i < 4; i++)
                    acc[mt][nt][i] = acc[mt][nt][i] * 0.5f *
                        (1.0f + erff(acc[mt][nt][i] * 0.70710678118654752f));
            }
            if (MODE >= 2) {
                float2 r0 = *(const float2*)(res + (size_t)r * N + n);
                float2 r1 = *(const float2*)(res + (size_t)(r + 8) * N + n);
                acc[mt][nt][0] += r0.x; acc[mt][nt][1] += r0.y;
                acc[mt][nt][2] += r1.x; acc[mt][nt][3] += r1.y;
            }
        }
    }

    if (MODE == 3) {
        // block-level row LN over N=128 (grid.x==1). Reuse pipeline smem.
        __syncthreads();
        float* rsum = (float*)As;            // [64][17]
        float* rsq  = rsum + 64 * 17;        // [64][17]
        float* st   = rsq + 64 * 17;         // [64][2]
        const int slot = warp_n * 4 + cl;
        #pragma unroll
        for (int mt = 0; mt < 2; mt++)
            #pragma unroll
            for (int rh = 0; rh < 2; rh++) {
                int lr = warp_m * 32 + mt * 16 + rh * 8 + g;
                float s = 0.f, q = 0.f;
                #pragma unroll
                for (int nt = 0; nt < 4; nt++) {
                    float v0 = acc[mt][nt][2 * rh], v1 = acc[mt][nt][2 * rh + 1];
                    s += v0 + v1; q += v0 * v0 + v1 * v1;
                }
                rsum[lr * 17 + slot] = s;
                rsq[lr * 17 + slot] = q;
            }
        __syncthreads();
        if (tid < 64) {
            float s = 0.f, q = 0.f;
            #pragma unroll
            for (int i = 0; i < 16; i++) {
                s += rsum[tid * 17 + i];
                q += rsq[tid * 17 + i];
            }
            float mean = s * (1.f / 128.f);
            float var = q * (1.f / 128.f) - mean * mean;
            st[tid * 2]     = mean;
            st[tid * 2 + 1] = rsqrtf(var + 1e-5f);
        }
        __syncthreads();
        #pragma unroll
        for (int mt = 0; mt < 2; mt++) {
            #pragma unroll
            for (int rh = 0; rh < 2; rh++) {
                int lr = warp_m * 32 + mt * 16 + rh * 8 + g;
                int r = m0 + lr;
                float mean = st[lr * 2], rstd = st[lr * 2 + 1];
                #pragma unroll
                for (int nt = 0; nt < 4; nt++) {
                    int n = n0 + warp_n * 32 + nt * 8 + cl * 2;
                    float v0 = acc[mt][nt][2 * rh], v1 = acc[mt][nt][2 * rh + 1];
                    *(float2*)(C + (size_t)r * N + n) = make_float2(v0, v1);
                    float h0 = (v0 - mean) * rstd * lns[n] + lnb[n];
                    float h1 = (v1 - mean) * rstd * lns[n + 1] + lnb[n + 1];
                    *(float2*)(Hout + (size_t)r * N + n) = make_float2(h0, h1);
                }
            }
        }
    } else {
        #pragma unroll
        for (int mt = 0; mt < 2; mt++) {
            int r = m0 + warp_m * 32 + mt * 16 + g;
            #pragma unroll
            for (int nt = 0; nt < 4; nt++) {
                int n = n0 + warp_n * 32 + nt * 8 + cl * 2;
                *(float2*)(C + (size_t)r * N + n) =
                    make_float2(acc[mt][nt][0], acc[mt][nt][1]);
                *(float2*)(C + (size_t)(r + 8) * N + n) =
                    make_float2(acc[mt][nt][2], acc[mt][nt][3]);
            }
        }
    }
}

// ---------------------------------------------------------------------------
// Conv 3x3 s2 p1 as implicit GEMM on tensor cores: M=16384, N=128, K=2304.
// ---------------------------------------------------------------------------
__global__ __launch_bounds__(256)
void conv_mma(const float* __restrict__ feat, const float* __restrict__ W,
              const float* __restrict__ cb, const float* __restrict__ pos,
              float* __restrict__ x)
{
    __shared__ uint32_t As[64][SK];
    __shared__ uint32_t Bs[128][SK];
    const int K = 2304;
    const int tid = threadIdx.x;
    const int lane = tid & 31, wid = tid >> 5;
    const int warp_m = wid >> 2, warp_n = wid & 3;
    const int m0 = blockIdx.y * 64;
    const int g = lane >> 2, cl = lane & 3;

    float acc[2][4][4];
    #pragma unroll
    for (int i = 0; i < 2; i++)
        #pragma unroll
        for (int j = 0; j < 4; j++)
            #pragma unroll
            for (int r = 0; r < 4; r++) acc[i][j][r] = 0.f;

    for (int k0 = 0; k0 < K; k0 += 32) {
        #pragma unroll
        for (int it = 0; it < 8; it++) {
            int e = tid + it * 256;
            int ml = e >> 5, kl = e & 31;
            int m = m0 + ml;
            int k = k0 + kl;
            int b = m >> 8, p = m & 255;
            int y = p >> 4, xx = p & 15;
            int c = k / 9, rr = k - c * 9;
            int ky = rr / 3, kx = rr - ky * 3;
            int iy = y * 2 - 1 + ky;
            int ix = xx * 2 - 1 + kx;
            float v = 0.f;
            if (iy >= 0 && iy < 32 && ix >= 0 && ix < 32)
                v = feat[(((size_t)b * 256 + c) * 32 + iy) * 32 + ix];
            As[ml][kl] = to_tf32(v);
        }
        #pragma unroll
        for (int it = 0; it < 4; it++) {
            int e = tid + it * 256;
            int row = e >> 3, c4 = (e & 7) * 4;
            float4 v = *(const float4*)(W + (size_t)row * K + k0 + c4);
            Bs[row][c4 + 0] = to_tf32(v.x);
            Bs[row][c4 + 1] = to_tf32(v.y);
            Bs[row][c4 + 2] = to_tf32(v.z);
            Bs[row][c4 + 3] = to_tf32(v.w);
        }
        __syncthreads();

        #pragma unroll
        for (int ks = 0; ks < 4; ks++) {
            const int kk = ks * 8;
            uint32_t af[2][4], bf[4][2];
            #pragma unroll
            for (int mt = 0; mt < 2; mt++) {
                int r = warp_m * 32 + mt * 16 + g;
                af[mt][0] = As[r][kk + cl];
                af[mt][1] = As[r + 8][kk + cl];
                af[mt][2] = As[r][kk + 4 + cl];
                af[mt][3] = As[r + 8][kk + 4 + cl];
            }
            #pragma unroll
            for (int nt = 0; nt < 4; nt++) {
                int n = warp_n * 32 + nt * 8 + g;
                bf[nt][0] = Bs[n][kk + cl];
                bf[nt][1] = Bs[n][kk + 4 + cl];
            }
            #pragma unroll
            for (int mt = 0; mt < 2; mt++)
                #pragma unroll
                for (int nt = 0; nt < 4; nt++)
                    mma_tf32(acc[mt][nt], af[mt], bf[nt]);
        }
        __syncthreads();
    }

    #pragma unroll
    for (int mt = 0; mt < 2; mt++) {
        int r = m0 + warp_m * 32 + mt * 16 + g;
        #pragma unroll
        for (int rr = 0; rr < 2; rr++) {
            int m = r + rr * 8;
            int b = m >> 8, p = m & 255;
            float* dst = x + ((size_t)b * NTOK + p + 1) * 128;
            const float* pp = pos + (size_t)(p + 1) * 128;
            #pragma unroll
            for (int nt = 0; nt < 4; nt++) {
                int n = warp_n * 32 + nt * 8 + cl * 2;
                float v0 = acc[mt][nt][rr * 2 + 0] + cb[n] + pp[n];
                float v1 = acc[mt][nt][rr * 2 + 1] + cb[n + 1] + pp[n + 1];
                *(float2*)(dst + n) = make_float2(v0, v1);
            }
        }
    }
}

// cls token rows: x[b,0,:] = cls + pos[0]
__global__ void cls_kernel(const float* __restrict__ cls,
                           const float* __restrict__ pos, float* __restrict__ x)
{
    int b = blockIdx.x, e = threadIdx.x;
    x[(size_t)b * NTOK * 128 + e] = cls[e] + pos[e];
}

// ---------------------------------------------------------------------------
// LayerNorm over E=128 (used once, before layer 0).
// ---------------------------------------------------------------------------
__global__ __launch_bounds__(256)
void ln_kernel(const float* __restrict__ x, float* __restrict__ h,
               const float* __restrict__ s, const float* __restrict__ b, float eps)
{
    int tok = blockIdx.x * 8 + (threadIdx.x >> 5);
    int lane = threadIdx.x & 31;
    if (tok >= TOKENS) return;
    const float4* xr = (const float4*)(x + (size_t)tok * 128);
    float4 v = xr[lane];
    float mean = warp_sum(v.x + v.y + v.z + v.w) * (1.f / 128.f);
    float dx = v.x - mean, dy = v.y - mean, dz = v.z - mean, dw = v.w - mean;
    float var = warp_sum(dx * dx + dy * dy + dz * dz + dw * dw) * (1.f / 128.f);
    float rstd = rsqrtf(var + eps);
    float4 sv = ((const float4*)s)[lane];
    float4 bv = ((const float4*)b)[lane];
    float4 o;
    o.x = dx * rstd * sv.x + bv.x;
    o.y = dy * rstd * sv.y + bv.y;
    o.z = dz * rstd * sv.z + bv.z;
    o.w = dw * rstd * sv.w + bv.w;
    ((float4*)(h + (size_t)tok * 128))[lane] = o;
}

// ---------------------------------------------------------------------------
// Attention (R6 proven): block per (b,h,z), K,V in smem, 4 queries/warp,
// key-256 hoisted, float4 P loads in PV.
// ---------------------------------------------------------------------------
#define PS_OFF 16964   // 16B-aligned float offset for Ps
#define ATT_SMEM ((PS_OFF + 32 * 264) * 4)

__global__ __launch_bounds__(256)
void attn_kernel(const float* __restrict__ qkv, float* __restrict__ o)
{
    extern __shared__ float sm[];
    float* Ks = sm;                 // [257][33]
    float* Vs = sm + 257 * 33;      // [257][33]
    float* Ps = sm + PS_OFF;        // [32][264]
    int b = blockIdx.x, h = blockIdx.y, z = blockIdx.z;
    int tid = threadIdx.x, w = tid >> 5, lane = tid & 31;
    const float* base = qkv + (size_t)b * NTOK * 384 + h * 32;

    for (int i = tid; i < 257 * 32; i += 256) {
        int m = i >> 5, d = i & 31;
        Ks[m * 33 + d] = base[(size_t)m * 384 + 128 + d];
        Vs[m * 33 + d] = base[(size_t)m * 384 + 256 + d];
    }
    __syncthreads();

    const float scale = 0.17677669529663687f;  // 1/sqrt(32)
    const float k256 = Ks[256 * 33 + lane];
    for (int t = z * 3; t < z * 3 + 3; t++) {
        if (t * 32 >= NTOK) break;
        int qbase = t * 32 + w * 4;
        float qd[4];
        bool val[4];
        #pragma unroll
        for (int qq = 0; qq < 4; qq++) {
            int n = qbase + qq;
            val[qq] = n < NTOK;
            qd[qq] = val[qq] ? base[(size_t)n * 384 + lane] : 0.f;
        }
        float sc[4][9];
        #pragma unroll
        for (int qq = 0; qq < 4; qq++)
            #pragma unroll
            for (int j = 0; j < 8; j++) sc[qq][j] = 0.f;

        #pragma unroll 4
        for (int d = 0; d < 32; d++) {
            float qv[4];
            #pragma unroll
            for (int qq = 0; qq < 4; qq++)
                qv[qq] = __shfl_sync(0xffffffffu, qd[qq], d);
            #pragma unroll
            for (int j = 0; j < 8; j++) {
                float kv = Ks[(lane + 32 * j) * 33 + d];
                #pragma unroll
                for (int qq = 0; qq < 4; qq++) sc[qq][j] += qv[qq] * kv;
            }
        }
        #pragma unroll
        for (int qq = 0; qq < 4; qq++)
            sc[qq][8] = warp_sum(qd[qq] * k256);

        #pragma unroll
        for (int qq = 0; qq < 4; qq++) {
            float mx = -1e30f;
            #pragma unroll
            for (int j = 0; j < 9; j++) {
                bool ok = (lane + 32 * j) < NTOK;
                sc[qq][j] = ok ? sc[qq][j] * scale : -1e30f;
                mx = fmaxf(mx, sc[qq][j]);
            }
            mx = warp_max(mx);
            float lsum = 0.f;
            #pragma unroll
            for (int j = 0; j < 9; j++) {
                bool ok = (lane + 32 * j) < NTOK;
                sc[qq][j] = ok ? __expf(sc[qq][j] - mx) : 0.f;
                lsum += sc[qq][j];
            }
            float inv = 1.f / warp_sum(lsum);
            #pragma unroll
            for (int j = 0; j < 9; j++) {
                int m = lane + 32 * j;
                if (m < NTOK) Ps[(w * 4 + qq) * 264 + m] = sc[qq][j] * inv;
            }
        }
        __syncwarp();

        float acc[4] = {0.f, 0.f, 0.f, 0.f};
        for (int m = 0; m < 256; m += 8) {
            float v0 = Vs[(m + 0) * 33 + lane];
            float v1 = Vs[(m + 1) * 33 + lane];
            float v2 = Vs[(m + 2) * 33 + lane];
            float v3 = Vs[(m + 3) * 33 + lane];
            float v4 = Vs[(m + 4) * 33 + lane];
            float v5 = Vs[(m + 5) * 33 + lane];
            float v6 = Vs[(m + 6) * 33 + lane];
            float v7 = Vs[(m + 7) * 33 + lane];
            #pragma unroll
            for (int qq = 0; qq < 4; qq++) {
                const float* pr = Ps + (w * 4 + qq) * 264 + m;
                float4 p0 = *(const float4*)pr;
                float4 p1 = *(const float4*)(pr + 4);
                acc[qq] += p0.x * v0; acc[qq] += p0.y * v1;
                acc[qq] += p0.z * v2; acc[qq] += p0.w * v3;
                acc[qq] += p1.x * v4; acc[qq] += p1.y * v5;
                acc[qq] += p1.z * v6; acc[qq] += p1.w * v7;
            }
        }
        {
            float v = Vs[256 * 33 + lane];
            #pragma unroll
            for (int qq = 0; qq < 4; qq++)
                acc[qq] += Ps[(w * 4 + qq) * 264 + 256] * v;
        }
        #pragma unroll
        for (int qq = 0; qq < 4; qq++)
            if (val[qq])
                o[((size_t)b * NTOK + qbase + qq) * 128 + h * 32 + lane] = acc[qq];
        __syncwarp();
    }
}

// ---------------------------------------------------------------------------
// Head: final LN (eps 1e-6) on token 0 of each batch, out_feat + fc.
// ---------------------------------------------------------------------------
__global__ __launch_bounds__(128)
void head_kernel(const float* __restrict__ x, const float* __restrict__ fns,
                 const float* __restrict__ fnb, const float* __restrict__ fcw,
                 const float* __restrict__ fcb, float* __restrict__ out)
{
    __shared__ float red[4];
    __shared__ float fsh[128];
    int b = blockIdx.x, t = threadIdx.x, w = t >> 5, lane = t & 31;
    float v = x[(size_t)b * NTOK * 128 + t];

    float s = warp_sum(v);
    if (lane == 0) red[w] = s;
    __syncthreads();
    float mean = (red[0] + red[1] + red[2] + red[3]) * (1.f / 128.f);
    __syncthreads();
    float d = v - mean;
    float sq = warp_sum(d * d);
    if (lane == 0) red[w] = sq;
    __syncthreads();
    float var = (red[0] + red[1] + red[2] + red[3]) * (1.f / 128.f);
    float rstd = rsqrtf(var + 1e-6f);
    float f = d * rstd * fns[t] + fnb[t];
    out[128 + (size_t)b * 128 + t] = f;
    fsh[t] = f;
    __syncthreads();
    if (t < 2) {
        float a = fcb[t];
        for (int e = 0; e < 128; e++) a += fsh[e] * fcw[t * 128 + e];
        out[b * 2 + t] = a;
    }
}

// ---------------------------------------------------------------------------
extern "C" void kernel_launch(void* const* d_in, const int* in_sizes, int n_in,
                              void* d_out, int out_size)
{
    const float* feat    = (const float*)d_in[0];
    const float* conv_w  = (const float*)d_in[1];
    const float* conv_b  = (const float*)d_in[2];
    const float* pos_emb = (const float*)d_in[3];
    const float* cls_tok = (const float*)d_in[4];
    const float* ln1_s   = (const float*)d_in[5];
    const float* ln1_b   = (const float*)d_in[6];
    const float* qkv_w   = (const float*)d_in[7];
    const float* qkv_b   = (const float*)d_in[8];
    const float* proj_w  = (const float*)d_in[9];
    const float* proj_b  = (const float*)d_in[10];
    const float* ln2_s   = (const float*)d_in[11];
    const float* ln2_b   = (const float*)d_in[12];
    const float* ffn1_w  = (const float*)d_in[13];
    const float* ffn1_b  = (const float*)d_in[14];
    const float* ffn2_w  = (const float*)d_in[15];
    const float* ffn2_b  = (const float*)d_in[16];
    const float* fn_s    = (const float*)d_in[17];
    const float* fn_b    = (const float*)d_in[18];
    const float* fc_w    = (const float*)d_in[19];
    const float* fc_b    = (const float*)d_in[20];
    float* out = (float*)d_out;

    float *px, *ph, *pq, *po, *pf;
    cudaGetSymbolAddress((void**)&px, g_x);
    cudaGetSymbolAddress((void**)&ph, g_h);
    cudaGetSymbolAddress((void**)&pq, g_qkv);
    cudaGetSymbolAddress((void**)&po, g_o);
    cudaGetSymbolAddress((void**)&pf, g_ffn);

    cudaFuncSetAttribute(attn_kernel, cudaFuncAttributeMaxDynamicSharedMemorySize, ATT_SMEM);

    cls_kernel<<<BATCH, 128>>>(cls_tok, pos_emb, px);
    conv_mma<<<dim3(1, 256), 256>>>(feat, conv_w, conv_b, pos_emb, px);
    // initial LN (layer 0 ln1); subsequent LNs are fused into gemm epilogues
    ln_kernel<<<TOKENS / 8, 256>>>(px, ph, ln1_s, ln1_b, 1e-5f);

    for (int l = 0; l < 12; l++) {
        gemm_mma<0><<<dim3(3, 257), 256>>>(
            ph, qkv_w + (size_t)l * 384 * 128, nullptr, nullptr,
            qkv_b + l * 384, nullptr, pq, nullptr, TOKENS, 384, 128);
        attn_kernel<<<dim3(BATCH, 4, 3), 256, ATT_SMEM>>>(pq, po);
        // proj + residual, fused ln2 -> ph
        gemm_mma<3><<<dim3(1, 257), 256>>>(
            po, proj_w + (size_t)l * 128 * 128, ln2_s + l * 128, ln2_b + l * 128,
            proj_b + l * 128, px, px, ph, TOKENS, 128, 128);
        gemm_mma<1><<<dim3(4, 257), 256>>>(
            ph, ffn1_w + (size_t)l * 512 * 128, nullptr, nullptr,
            ffn1_b + l * 512, nullptr, pf, nullptr, TOKENS, 512, 128);
        if (l < 11) {
            // ffn2 + residual, fused next-layer ln1 -> ph
            gemm_mma<3><<<dim3(1, 257), 256>>>(
                pf, ffn2_w + (size_t)l * 128 * 512,
                ln1_s + (l + 1) * 128, ln1_b + (l + 1) * 128,
                ffn2_b + l * 128, px, px, ph, TOKENS, 128, 512);
        } else {
            gemm_mma<2><<<dim3(1, 257), 256>>>(
                pf, ffn2_w + (size_t)l * 128 * 512, nullptr, nullptr,
                ffn2_b + l * 128, px, px, nullptr, TOKENS, 128, 512);
        }
    }

    head_kernel<<<BATCH, 128>>>(px, fn_s, fn_b, fc_w, fc_b, out);
}

// round 8
// speedup vs baseline: 1.5340x; 1.0892x over previous
#include <cuda_runtime.h>
#include <math.h>
#include <stdint.h>

// ---------------------------------------------------------------------------
// Shapes (fixed): L=12, E=128, H=4, D=32, F=512, B=64, CIN=256, N=257
// Tokens T = B*N = 16448 = 64 * 257
// ---------------------------------------------------------------------------
#define TOKENS 16448
#define NTOK 257
#define BATCH 64

// scratch (device globals; allocation is forbidden)
__device__ float g_x  [TOKENS * 128];   // residual stream
__device__ float g_h  [TOKENS * 128];   // post-LN
__device__ float g_qkv[TOKENS * 384];
__device__ float g_o  [TOKENS * 128];   // attention output
__device__ float g_ffn[TOKENS * 512];   // ffn hidden

__device__ __forceinline__ float warp_sum(float v) {
    #pragma unroll
    for (int o = 16; o; o >>= 1) v += __shfl_xor_sync(0xffffffffu, v, o);
    return v;
}
__device__ __forceinline__ float warp_max(float v) {
    #pragma unroll
    for (int o = 16; o; o >>= 1) v = fmaxf(v, __shfl_xor_sync(0xffffffffu, v, o));
    return v;
}

__device__ __forceinline__ uint32_t to_tf32(float f) {
    uint32_t u;
    asm("cvt.rna.tf32.f32 %0, %1;" : "=r"(u) : "f"(f));
    return u;
}

// D = A(16x8, row) * B(8x8, col) + D, tf32 in, f32 accum
__device__ __forceinline__ void mma_tf32(float c[4], const uint32_t a[4], const uint32_t b[2]) {
    asm volatile(
        "mma.sync.aligned.m16n8k8.row.col.f32.tf32.tf32.f32 "
        "{%0,%1,%2,%3}, {%4,%5,%6,%7}, {%8,%9}, {%0,%1,%2,%3};"
        : "+f"(c[0]), "+f"(c[1]), "+f"(c[2]), "+f"(c[3])
        : "r"(a[0]), "r"(a[1]), "r"(a[2]), "r"(a[3]), "r"(b[0]), "r"(b[1]));
}

__device__ __forceinline__ void cp16(void* smem, const void* g) {
    uint32_t s = (uint32_t)__cvta_generic_to_shared(smem);
    asm volatile("cp.async.cg.shared.global [%0], [%1], 16;" :: "r"(s), "l"(g));
}
__device__ __forceinline__ void cp_commit() {
    asm volatile("cp.async.commit_group;");
}
__device__ __forceinline__ void cp_wait0() {
    asm volatile("cp.async.wait_group 0;");
}

#define SK 36   // padded k-stride: conflict-free fragment LDS

// ---------------------------------------------------------------------------
// cp.async double-buffered tensor-core GEMM. C = A @ W^T + bias, fused epi.
// MODE 0: +bias   MODE 1: gelu(+bias)   MODE 2: +bias+res
// MODE 3: +bias+res, and ALSO writes LN(C) to Hout (N must be 128 = LN axis)
// ---------------------------------------------------------------------------
template <int MODE>
__global__ __launch_bounds__(256)
void gemm_mma(const float* __restrict__ A, const float* __restrict__ W,
              const float* __restrict__ lns, const float* __restrict__ lnb,
              const float* __restrict__ bias, const float* __restrict__ res,
              float* __restrict__ C, float* __restrict__ Hout,
              int M, int N, int K)
{
    __shared__ float As[2][64][SK];
    __shared__ float Bs[2][128][SK];
    const int tid = threadIdx.x;
    const int lane = tid & 31, wid = tid >> 5;
    const int warp_m = wid >> 2, warp_n = wid & 3;
    const int m0 = blockIdx.y * 64, n0 = blockIdx.x * 128;
    const int g = lane >> 2, cl = lane & 3;

    const int arow = tid >> 3, ac4 = (tid & 7) * 4;
    const float* Ap0 = A + (size_t)(m0 + arow) * K + ac4;
    const float* Ap1 = A + (size_t)(m0 + arow + 32) * K + ac4;
    const float* Wp0 = W + (size_t)(n0 + arow) * K + ac4;
    const float* Wp1 = W + (size_t)(n0 + arow + 32) * K + ac4;
    const float* Wp2 = W + (size_t)(n0 + arow + 64) * K + ac4;
    const float* Wp3 = W + (size_t)(n0 + arow + 96) * K + ac4;

    const int nc = K >> 5;

    {
        cp16(&As[0][arow][ac4], Ap0);
        cp16(&As[0][arow + 32][ac4], Ap1);
        cp16(&Bs[0][arow][ac4], Wp0);
        cp16(&Bs[0][arow + 32][ac4], Wp1);
        cp16(&Bs[0][arow + 64][ac4], Wp2);
        cp16(&Bs[0][arow + 96][ac4], Wp3);
        cp_commit();
    }

    float acc[2][4][4];
    #pragma unroll
    for (int i = 0; i < 2; i++)
        #pragma unroll
        for (int j = 0; j < 4; j++)
            #pragma unroll
            for (int r = 0; r < 4; r++) acc[i][j][r] = 0.f;

    for (int c = 0; c < nc; c++) {
        const int buf = c & 1;
        cp_wait0();
        __syncthreads();

        if (c + 1 < nc) {
            const int nb = buf ^ 1, off = (c + 1) * 32;
            cp16(&As[nb][arow][ac4], Ap0 + off);
            cp16(&As[nb][arow + 32][ac4], Ap1 + off);
            cp16(&Bs[nb][arow][ac4], Wp0 + off);
            cp16(&Bs[nb][arow + 32][ac4], Wp1 + off);
            cp16(&Bs[nb][arow + 64][ac4], Wp2 + off);
            cp16(&Bs[nb][arow + 96][ac4], Wp3 + off);
            cp_commit();
        }

        #pragma unroll
        for (int ks = 0; ks < 4; ks++) {
            const int kk = ks * 8;
            uint32_t af[2][4], bf[4][2];
            #pragma unroll
            for (int mt = 0; mt < 2; mt++) {
                int r = warp_m * 32 + mt * 16 + g;
                af[mt][0] = to_tf32(As[buf][r][kk + cl]);
                af[mt][1] = to_tf32(As[buf][r + 8][kk + cl]);
                af[mt][2] = to_tf32(As[buf][r][kk + 4 + cl]);
                af[mt][3] = to_tf32(As[buf][r + 8][kk + 4 + cl]);
            }
            #pragma unroll
            for (int nt = 0; nt < 4; nt++) {
                int n = warp_n * 32 + nt * 8 + g;
                bf[nt][0] = to_tf32(Bs[buf][n][kk + cl]);
                bf[nt][1] = to_tf32(Bs[buf][n][kk + 4 + cl]);
            }
            #pragma unroll
            for (int mt = 0; mt < 2; mt++)
                #pragma unroll
                for (int nt = 0; nt < 4; nt++)
                    mma_tf32(acc[mt][nt], af[mt], bf[nt]);
        }
    }

    #pragma unroll
    for (int mt = 0; mt < 2; mt++) {
        int r = m0 + warp_m * 32 + mt * 16 + g;
        #pragma unroll
        for (int nt = 0; nt < 4; nt++) {
            int n = n0 + warp_n * 32 + nt * 8 + cl * 2;
            float b0 = bias[n], b1 = bias[n + 1];
            acc[mt][nt][0] += b0; acc[mt][nt][1] += b1;
            acc[mt][nt][2] += b0; acc[mt][nt][3] += b1;
            if (MODE == 1) {
                #pragma unroll
                for (int i = 0; i < 4; i++)
                    acc[mt][nt][i] = acc[mt][nt][i] * 0.5f *
                        (1.0f + erff(acc[mt][nt][i] * 0.70710678118654752f));
            }
            if (MODE >= 2) {
                float2 r0 = *(const float2*)(res + (size_t)r * N + n);
                float2 r1 = *(const float2*)(res + (size_t)(r + 8) * N + n);
                acc[mt][nt][0] += r0.x; acc[mt][nt][1] += r0.y;
                acc[mt][nt][2] += r1.x; acc[mt][nt][3] += r1.y;
            }
        }
    }

    if (MODE == 3) {
        __syncthreads();
        float* rsum = (float*)As;            // [64][17]
        float* rsq  = rsum + 64 * 17;        // [64][17]
        float* st   = rsq + 64 * 17;         // [64][2]
        const int slot = warp_n * 4 + cl;
        #pragma unroll
        for (int mt = 0; mt < 2; mt++)
            #pragma unroll
            for (int rh = 0; rh < 2; rh++) {
                int lr = warp_m * 32 + mt * 16 + rh * 8 + g;
                float s = 0.f, q = 0.f;
                #pragma unroll
                for (int nt = 0; nt < 4; nt++) {
                    float v0 = acc[mt][nt][2 * rh], v1 = acc[mt][nt][2 * rh + 1];
                    s += v0 + v1; q += v0 * v0 + v1 * v1;
                }
                rsum[lr * 17 + slot] = s;
                rsq[lr * 17 + slot] = q;
            }
        __syncthreads();
        if (tid < 64) {
            float s = 0.f, q = 0.f;
            #pragma unroll
            for (int i = 0; i < 16; i++) {
                s += rsum[tid * 17 + i];
                q += rsq[tid * 17 + i];
            }
            float mean = s * (1.f / 128.f);
            float var = q * (1.f / 128.f) - mean * mean;
            st[tid * 2]     = mean;
            st[tid * 2 + 1] = rsqrtf(var + 1e-5f);
        }
        __syncthreads();
        #pragma unroll
        for (int mt = 0; mt < 2; mt++) {
            #pragma unroll
            for (int rh = 0; rh < 2; rh++) {
                int lr = warp_m * 32 + mt * 16 + rh * 8 + g;
                int r = m0 + lr;
                float mean = st[lr * 2], rstd = st[lr * 2 + 1];
                #pragma unroll
                for (int nt = 0; nt < 4; nt++) {
                    int n = n0 + warp_n * 32 + nt * 8 + cl * 2;
                    float v0 = acc[mt][nt][2 * rh], v1 = acc[mt][nt][2 * rh + 1];
                    *(float2*)(C + (size_t)r * N + n) = make_float2(v0, v1);
                    float h0 = (v0 - mean) * rstd * lns[n] + lnb[n];
                    float h1 = (v1 - mean) * rstd * lns[n + 1] + lnb[n + 1];
                    *(float2*)(Hout + (size_t)r * N + n) = make_float2(h0, h1);
                }
            }
        }
    } else {
        #pragma unroll
        for (int mt = 0; mt < 2; mt++) {
            int r = m0 + warp_m * 32 + mt * 16 + g;
            #pragma unroll
            for (int nt = 0; nt < 4; nt++) {
                int n = n0 + warp_n * 32 + nt * 8 + cl * 2;
                *(float2*)(C + (size_t)r * N + n) =
                    make_float2(acc[mt][nt][0], acc[mt][nt][1]);
                *(float2*)(C + (size_t)(r + 8) * N + n) =
                    make_float2(acc[mt][nt][2], acc[mt][nt][3]);
            }
        }
    }
}

// ---------------------------------------------------------------------------
// Conv 3x3 s2 p1 as implicit GEMM on tensor cores: M=16384, N=128, K=2304.
// ---------------------------------------------------------------------------
__global__ __launch_bounds__(256)
void conv_mma(const float* __restrict__ feat, const float* __restrict__ W,
              const float* __restrict__ cb, const float* __restrict__ pos,
              float* __restrict__ x)
{
    __shared__ uint32_t As[64][SK];
    __shared__ uint32_t Bs[128][SK];
    const int K = 2304;
    const int tid = threadIdx.x;
    const int lane = tid & 31, wid = tid >> 5;
    const int warp_m = wid >> 2, warp_n = wid & 3;
    const int m0 = blockIdx.y * 64;
    const int g = lane >> 2, cl = lane & 3;

    float acc[2][4][4];
    #pragma unroll
    for (int i = 0; i < 2; i++)
        #pragma unroll
        for (int j = 0; j < 4; j++)
            #pragma unroll
            for (int r = 0; r < 4; r++) acc[i][j][r] = 0.f;

    for (int k0 = 0; k0 < K; k0 += 32) {
        #pragma unroll
        for (int it = 0; it < 8; it++) {
            int e = tid + it * 256;
            int ml = e >> 5, kl = e & 31;
            int m = m0 + ml;
            int k = k0 + kl;
            int b = m >> 8, p = m & 255;
            int y = p >> 4, xx = p & 15;
            int c = k / 9, rr = k - c * 9;
            int ky = rr / 3, kx = rr - ky * 3;
            int iy = y * 2 - 1 + ky;
            int ix = xx * 2 - 1 + kx;
            float v = 0.f;
            if (iy >= 0 && iy < 32 && ix >= 0 && ix < 32)
                v = feat[(((size_t)b * 256 + c) * 32 + iy) * 32 + ix];
            As[ml][kl] = to_tf32(v);
        }
        #pragma unroll
        for (int it = 0; it < 4; it++) {
            int e = tid + it * 256;
            int row = e >> 3, c4 = (e & 7) * 4;
            float4 v = *(const float4*)(W + (size_t)row * K + k0 + c4);
            Bs[row][c4 + 0] = to_tf32(v.x);
            Bs[row][c4 + 1] = to_tf32(v.y);
            Bs[row][c4 + 2] = to_tf32(v.z);
            Bs[row][c4 + 3] = to_tf32(v.w);
        }
        __syncthreads();

        #pragma unroll
        for (int ks = 0; ks < 4; ks++) {
            const int kk = ks * 8;
            uint32_t af[2][4], bf[4][2];
            #pragma unroll
            for (int mt = 0; mt < 2; mt++) {
                int r = warp_m * 32 + mt * 16 + g;
                af[mt][0] = As[r][kk + cl];
                af[mt][1] = As[r + 8][kk + cl];
                af[mt][2] = As[r][kk + 4 + cl];
                af[mt][3] = As[r + 8][kk + 4 + cl];
            }
            #pragma unroll
            for (int nt = 0; nt < 4; nt++) {
                int n = warp_n * 32 + nt * 8 + g;
                bf[nt][0] = Bs[n][kk + cl];
                bf[nt][1] = Bs[n][kk + 4 + cl];
            }
            #pragma unroll
            for (int mt = 0; mt < 2; mt++)
                #pragma unroll
                for (int nt = 0; nt < 4; nt++)
                    mma_tf32(acc[mt][nt], af[mt], bf[nt]);
        }
        __syncthreads();
    }

    #pragma unroll
    for (int mt = 0; mt < 2; mt++) {
        int r = m0 + warp_m * 32 + mt * 16 + g;
        #pragma unroll
        for (int rr = 0; rr < 2; rr++) {
            int m = r + rr * 8;
            int b = m >> 8, p = m & 255;
            float* dst = x + ((size_t)b * NTOK + p + 1) * 128;
            const float* pp = pos + (size_t)(p + 1) * 128;
            #pragma unroll
            for (int nt = 0; nt < 4; nt++) {
                int n = warp_n * 32 + nt * 8 + cl * 2;
                float v0 = acc[mt][nt][rr * 2 + 0] + cb[n] + pp[n];
                float v1 = acc[mt][nt][rr * 2 + 1] + cb[n + 1] + pp[n + 1];
                *(float2*)(dst + n) = make_float2(v0, v1);
            }
        }
    }
}

// cls token rows: x[b,0,:] = cls + pos[0]
__global__ void cls_kernel(const float* __restrict__ cls,
                           const float* __restrict__ pos, float* __restrict__ x)
{
    int b = blockIdx.x, e = threadIdx.x;
    x[(size_t)b * NTOK * 128 + e] = cls[e] + pos[e];
}

// ---------------------------------------------------------------------------
// LayerNorm over E=128 (used once, before layer 0).
// ---------------------------------------------------------------------------
__global__ __launch_bounds__(256)
void ln_kernel(const float* __restrict__ x, float* __restrict__ h,
               const float* __restrict__ s, const float* __restrict__ b, float eps)
{
    int tok = blockIdx.x * 8 + (threadIdx.x >> 5);
    int lane = threadIdx.x & 31;
    if (tok >= TOKENS) return;
    const float4* xr = (const float4*)(x + (size_t)tok * 128);
    float4 v = xr[lane];
    float mean = warp_sum(v.x + v.y + v.z + v.w) * (1.f / 128.f);
    float dx = v.x - mean, dy = v.y - mean, dz = v.z - mean, dw = v.w - mean;
    float var = warp_sum(dx * dx + dy * dy + dz * dz + dw * dw) * (1.f / 128.f);
    float rstd = rsqrtf(var + eps);
    float4 sv = ((const float4*)s)[lane];
    float4 bv = ((const float4*)b)[lane];
    float4 o;
    o.x = dx * rstd * sv.x + bv.x;
    o.y = dy * rstd * sv.y + bv.y;
    o.z = dz * rstd * sv.z + bv.z;
    o.w = dw * rstd * sv.w + bv.w;
    ((float4*)(h + (size_t)tok * 128))[lane] = o;
}

// ---------------------------------------------------------------------------
// Hybrid attention: block per (b,h,z). Stage 1: S = Q K^T on tensor cores
// (tf32 mma, 8 warps each owning one 32-key chunk, raw S -> Ps smem).
// Stage 2: fp32 softmax + PV exactly as the proven scalar kernel.
// Key 256 handled via the scalar warp-reduce path. ~107KB smem -> 2 CTA/SM.
// ---------------------------------------------------------------------------
#define KT_OFF 0                 // u32 [257][36] tf32 K
#define VS_OFF 9252              // f32 [257][33] V
#define QT_OFF 17736             // u32 [32][36] tf32 Q tile (16B aligned)
#define PS_OFF2 18888            // f32 [32][264] S/P (16B aligned)
#define ATT_SMEM ((PS_OFF2 + 32 * 264) * 4)   // 109344 B

__global__ __launch_bounds__(256)
void attn_kernel(const float* __restrict__ qkv, float* __restrict__ o)
{
    extern __shared__ float sm[];
    uint32_t* Kt = (uint32_t*)sm;       // [257][36]
    float* Vs = sm + VS_OFF;            // [257][33]
    uint32_t* Qt = (uint32_t*)(sm + QT_OFF);  // [32][36]
    float* Ps = sm + PS_OFF2;           // [32][264]
    int b = blockIdx.x, h = blockIdx.y, z = blockIdx.z;
    int tid = threadIdx.x, w = tid >> 5, lane = tid & 31;
    const int g = lane >> 2, cl = lane & 3;
    const float* base = qkv + (size_t)b * NTOK * 384 + h * 32;

    for (int i = tid; i < 257 * 32; i += 256) {
        int m = i >> 5, d = i & 31;
        Kt[m * 36 + d] = to_tf32(base[(size_t)m * 384 + 128 + d]);
        Vs[m * 33 + d] = base[(size_t)m * 384 + 256 + d];
    }
    __syncthreads();

    const float scale = 0.17677669529663687f;  // 1/sqrt(32)
    const float k256 = __uint_as_float(Kt[256 * 36 + lane]);

    for (int t = z * 3; t < z * 3 + 3; t++) {
        if (t * 32 >= NTOK) break;

        // ---- load Q tile (tf32), zero-pad rows >= NTOK ----
        {
            int row = tid >> 3, d4 = (tid & 7) * 4;
            int q = t * 32 + row;
            float4 v = make_float4(0.f, 0.f, 0.f, 0.f);
            if (q < NTOK) v = *(const float4*)(base + (size_t)q * 384 + d4);
            Qt[row * 36 + d4 + 0] = to_tf32(v.x);
            Qt[row * 36 + d4 + 1] = to_tf32(v.y);
            Qt[row * 36 + d4 + 2] = to_tf32(v.z);
            Qt[row * 36 + d4 + 3] = to_tf32(v.w);
        }
        __syncthreads();

        // ---- stage 1: warp w computes S(32q x 32k) for keys [32w, 32w+32) ----
        {
            float s[2][4][4];
            #pragma unroll
            for (int mt = 0; mt < 2; mt++)
                #pragma unroll
                for (int nt = 0; nt < 4; nt++)
                    #pragma unroll
                    for (int r = 0; r < 4; r++) s[mt][nt][r] = 0.f;
            #pragma unroll
            for (int ks = 0; ks < 4; ks++) {
                const int kk = ks * 8;
                uint32_t aq[2][4], bk[4][2];
                #pragma unroll
                for (int mt = 0; mt < 2; mt++) {
                    int r = mt * 16 + g;
                    aq[mt][0] = Qt[r * 36 + kk + cl];
                    aq[mt][1] = Qt[(r + 8) * 36 + kk + cl];
                    aq[mt][2] = Qt[r * 36 + kk + 4 + cl];
                    aq[mt][3] = Qt[(r + 8) * 36 + kk + 4 + cl];
                }
                #pragma unroll
                for (int nt = 0; nt < 4; nt++) {
                    int kr = w * 32 + nt * 8 + g;
                    bk[nt][0] = Kt[kr * 36 + kk + cl];
                    bk[nt][1] = Kt[kr * 36 + kk + 4 + cl];
                }
                #pragma unroll
                for (int mt = 0; mt < 2; mt++)
                    #pragma unroll
                    for (int nt = 0; nt < 4; nt++)
                        mma_tf32(s[mt][nt], aq[mt], bk[nt]);
            }
            #pragma unroll
            for (int mt = 0; mt < 2; mt++) {
                int row = mt * 16 + g;
                #pragma unroll
                for (int nt = 0; nt < 4; nt++) {
                    int col = w * 32 + nt * 8 + 2 * cl;
                    Ps[row * 264 + col]           = s[mt][nt][0];
                    Ps[row * 264 + col + 1]       = s[mt][nt][1];
                    Ps[(row + 8) * 264 + col]     = s[mt][nt][2];
                    Ps[(row + 8) * 264 + col + 1] = s[mt][nt][3];
                }
            }
        }
        __syncthreads();

        // ---- stage 2: softmax + PV (fp32, proven path) ----
        int qbase = t * 32 + w * 4;
        float qd[4];
        bool val[4];
        #pragma unroll
        for (int qq = 0; qq < 4; qq++) {
            int n = qbase + qq;
            val[qq] = n < NTOK;
            qd[qq] = val[qq] ? base[(size_t)n * 384 + lane] : 0.f;
        }
        float sc[4][9];
        #pragma unroll
        for (int qq = 0; qq < 4; qq++) {
            #pragma unroll
            for (int j = 0; j < 8; j++)
                sc[qq][j] = Ps[(w * 4 + qq) * 264 + lane + 32 * j];
            sc[qq][8] = warp_sum(qd[qq] * k256);
        }

        #pragma unroll
        for (int qq = 0; qq < 4; qq++) {
            float mx = -1e30f;
            #pragma unroll
            for (int j = 0; j < 9; j++) {
                bool ok = (lane + 32 * j) < NTOK;
                sc[qq][j] = ok ? sc[qq][j] * scale : -1e30f;
                mx = fmaxf(mx, sc[qq][j]);
            }
            mx = warp_max(mx);
            float lsum = 0.f;
            #pragma unroll
            for (int j = 0; j < 9; j++) {
                bool ok = (lane + 32 * j) < NTOK;
                sc[qq][j] = ok ? __expf(sc[qq][j] - mx) : 0.f;
                lsum += sc[qq][j];
            }
            float inv = 1.f / warp_sum(lsum);
            #pragma unroll
            for (int j = 0; j < 9; j++) {
                int m = lane + 32 * j;
                if (m < NTOK) Ps[(w * 4 + qq) * 264 + m] = sc[qq][j] * inv;
            }
        }
        __syncwarp();

        float acc[4] = {0.f, 0.f, 0.f, 0.f};
        for (int m = 0; m < 256; m += 8) {
            float v0 = Vs[(m + 0) * 33 + lane];
            float v1 = Vs[(m + 1) * 33 + lane];
            float v2 = Vs[(m + 2) * 33 + lane];
            float v3 = Vs[(m + 3) * 33 + lane];
            float v4 = Vs[(m + 4) * 33 + lane];
            float v5 = Vs[(m + 5) * 33 + lane];
            float v6 = Vs[(m + 6) * 33 + lane];
            float v7 = Vs[(m + 7) * 33 + lane];
            #pragma unroll
            for (int qq = 0; qq < 4; qq++) {
                const float* pr = Ps + (w * 4 + qq) * 264 + m;
                float4 p0 = *(const float4*)pr;
                float4 p1 = *(const float4*)(pr + 4);
                acc[qq] += p0.x * v0; acc[qq] += p0.y * v1;
                acc[qq] += p0.z * v2; acc[qq] += p0.w * v3;
                acc[qq] += p1.x * v4; acc[qq] += p1.y * v5;
                acc[qq] += p1.z * v6; acc[qq] += p1.w * v7;
            }
        }
        {
            float v = Vs[256 * 33 + lane];
            #pragma unroll
            for (int qq = 0; qq < 4; qq++)
                acc[qq] += Ps[(w * 4 + qq) * 264 + 256] * v;
        }
        #pragma unroll
        for (int qq = 0; qq < 4; qq++)
            if (val[qq])
                o[((size_t)b * NTOK + qbase + qq) * 128 + h * 32 + lane] = acc[qq];
        __syncthreads();   // Ps/Qt reused next tile
    }
}

// ---------------------------------------------------------------------------
// Head: final LN (eps 1e-6) on token 0 of each batch, out_feat + fc.
// ---------------------------------------------------------------------------
__global__ __launch_bounds__(128)
void head_kernel(const float* __restrict__ x, const float* __restrict__ fns,
                 const float* __restrict__ fnb, const float* __restrict__ fcw,
                 const float* __restrict__ fcb, float* __restrict__ out)
{
    __shared__ float red[4];
    __shared__ float fsh[128];
    int b = blockIdx.x, t = threadIdx.x, w = t >> 5, lane = t & 31;
    float v = x[(size_t)b * NTOK * 128 + t];

    float s = warp_sum(v);
    if (lane == 0) red[w] = s;
    __syncthreads();
    float mean = (red[0] + red[1] + red[2] + red[3]) * (1.f / 128.f);
    __syncthreads();
    float d = v - mean;
    float sq = warp_sum(d * d);
    if (lane == 0) red[w] = sq;
    __syncthreads();
    float var = (red[0] + red[1] + red[2] + red[3]) * (1.f / 128.f);
    float rstd = rsqrtf(var + 1e-6f);
    float f = d * rstd * fns[t] + fnb[t];
    out[128 + (size_t)b * 128 + t] = f;
    fsh[t] = f;
    __syncthreads();
    if (t < 2) {
        float a = fcb[t];
        for (int e = 0; e < 128; e++) a += fsh[e] * fcw[t * 128 + e];
        out[b * 2 + t] = a;
    }
}

// ---------------------------------------------------------------------------
extern "C" void kernel_launch(void* const* d_in, const int* in_sizes, int n_in,
                              void* d_out, int out_size)
{
    const float* feat    = (const float*)d_in[0];
    const float* conv_w  = (const float*)d_in[1];
    const float* conv_b  = (const float*)d_in[2];
    const float* pos_emb = (const float*)d_in[3];
    const float* cls_tok = (const float*)d_in[4];
    const float* ln1_s   = (const float*)d_in[5];
    const float* ln1_b   = (const float*)d_in[6];
    const float* qkv_w   = (const float*)d_in[7];
    const float* qkv_b   = (const float*)d_in[8];
    const float* proj_w  = (const float*)d_in[9];
    const float* proj_b  = (const float*)d_in[10];
    const float* ln2_s   = (const float*)d_in[11];
    const float* ln2_b   = (const float*)d_in[12];
    const float* ffn1_w  = (const float*)d_in[13];
    const float* ffn1_b  = (const float*)d_in[14];
    const float* ffn2_w  = (const float*)d_in[15];
    const float* ffn2_b  = (const float*)d_in[16];
    const float* fn_s    = (const float*)d_in[17];
    const float* fn_b    = (const float*)d_in[18];
    const float* fc_w    = (const float*)d_in[19];
    const float* fc_b    = (const float*)d_in[20];
    float* out = (float*)d_out;

    float *px, *ph, *pq, *po, *pf;
    cudaGetSymbolAddress((void**)&px, g_x);
    cudaGetSymbolAddress((void**)&ph, g_h);
    cudaGetSymbolAddress((void**)&pq, g_qkv);
    cudaGetSymbolAddress((void**)&po, g_o);
    cudaGetSymbolAddress((void**)&pf, g_ffn);

    cudaFuncSetAttribute(attn_kernel, cudaFuncAttributeMaxDynamicSharedMemorySize, ATT_SMEM);

    cls_kernel<<<BATCH, 128>>>(cls_tok, pos_emb, px);
    conv_mma<<<dim3(1, 256), 256>>>(feat, conv_w, conv_b, pos_emb, px);
    // initial LN (layer 0 ln1); subsequent LNs are fused into gemm epilogues
    ln_kernel<<<TOKENS / 8, 256>>>(px, ph, ln1_s, ln1_b, 1e-5f);

    for (int l = 0; l < 12; l++) {
        gemm_mma<0><<<dim3(3, 257), 256>>>(
            ph, qkv_w + (size_t)l * 384 * 128, nullptr, nullptr,
            qkv_b + l * 384, nullptr, pq, nullptr, TOKENS, 384, 128);
        attn_kernel<<<dim3(BATCH, 4, 3), 256, ATT_SMEM>>>(pq, po);
        gemm_mma<3><<<dim3(1, 257), 256>>>(
            po, proj_w + (size_t)l * 128 * 128, ln2_s + l * 128, ln2_b + l * 128,
            proj_b + l * 128, px, px, ph, TOKENS, 128, 128);
        gemm_mma<1><<<dim3(4, 257), 256>>>(
            ph, ffn1_w + (size_t)l * 512 * 128, nullptr, nullptr,
            ffn1_b + l * 512, nullptr, pf, nullptr, TOKENS, 512, 128);
        if (l < 11) {
            gemm_mma<3><<<dim3(1, 257), 256>>>(
                pf, ffn2_w + (size_t)l * 128 * 512,
                ln1_s + (l + 1) * 128, ln1_b + (l + 1) * 128,
                ffn2_b + l * 128, px, px, ph, TOKENS, 128, 512);
        } else {
            gemm_mma<2><<<dim3(1, 257), 256>>>(
                pf, ffn2_w + (size_t)l * 128 * 512, nullptr, nullptr,
                ffn2_b + l * 128, px, px, nullptr, TOKENS, 128, 512);
        }
    }

    head_kernel<<<BATCH, 128>>>(px, fn_s, fn_b, fc_w, fc_b, out);
}

// round 9
// speedup vs baseline: 1.7928x; 1.1686x over previous
#include <cuda_runtime.h>
#include <math.h>
#include <stdint.h>

// ---------------------------------------------------------------------------
// Shapes (fixed): L=12, E=128, H=4, D=32, F=512, B=64, CIN=256, N=257
// Tokens T = B*N = 16448 = 64 * 257
// ---------------------------------------------------------------------------
#define TOKENS 16448
#define NTOK 257
#define BATCH 64

// scratch (device globals; allocation is forbidden)
__device__ float g_x  [TOKENS * 128];   // residual stream
__device__ float g_h  [TOKENS * 128];   // post-LN
__device__ float g_qkv[TOKENS * 384];
__device__ float g_o  [TOKENS * 128];   // attention output
__device__ float g_ffn[TOKENS * 512];   // ffn hidden

__device__ __forceinline__ float warp_sum(float v) {
    #pragma unroll
    for (int o = 16; o; o >>= 1) v += __shfl_xor_sync(0xffffffffu, v, o);
    return v;
}

__device__ __forceinline__ uint32_t to_tf32(float f) {
    uint32_t u;
    asm("cvt.rna.tf32.f32 %0, %1;" : "=r"(u) : "f"(f));
    return u;
}

// D = A(16x8, row) * B(8x8, col) + D, tf32 in, f32 accum
__device__ __forceinline__ void mma_tf32(float c[4], const uint32_t a[4], const uint32_t b[2]) {
    asm volatile(
        "mma.sync.aligned.m16n8k8.row.col.f32.tf32.tf32.f32 "
        "{%0,%1,%2,%3}, {%4,%5,%6,%7}, {%8,%9}, {%0,%1,%2,%3};"
        : "+f"(c[0]), "+f"(c[1]), "+f"(c[2]), "+f"(c[3])
        : "r"(a[0]), "r"(a[1]), "r"(a[2]), "r"(a[3]), "r"(b[0]), "r"(b[1]));
}

__device__ __forceinline__ void cp16(void* smem, const void* g) {
    uint32_t s = (uint32_t)__cvta_generic_to_shared(smem);
    asm volatile("cp.async.cg.shared.global [%0], [%1], 16;" :: "r"(s), "l"(g));
}
__device__ __forceinline__ void cp_commit() {
    asm volatile("cp.async.commit_group;");
}
__device__ __forceinline__ void cp_wait0() {
    asm volatile("cp.async.wait_group 0;");
}

#define SK 36   // padded k-stride: conflict-free fragment LDS

// ---------------------------------------------------------------------------
// cp.async double-buffered tensor-core GEMM. C = A @ W^T + bias, fused epi.
// MODE 0: +bias   MODE 1: gelu(+bias)   MODE 2: +bias+res
// MODE 3: +bias+res, and ALSO writes LN(C) to Hout (N must be 128 = LN axis)
// ---------------------------------------------------------------------------
template <int MODE>
__global__ __launch_bounds__(256)
void gemm_mma(const float* __restrict__ A, const float* __restrict__ W,
              const float* __restrict__ lns, const float* __restrict__ lnb,
              const float* __restrict__ bias, const float* __restrict__ res,
              float* __restrict__ C, float* __restrict__ Hout,
              int M, int N, int K)
{
    __shared__ float As[2][64][SK];
    __shared__ float Bs[2][128][SK];
    const int tid = threadIdx.x;
    const int lane = tid & 31, wid = tid >> 5;
    const int warp_m = wid >> 2, warp_n = wid & 3;
    const int m0 = blockIdx.y * 64, n0 = blockIdx.x * 128;
    const int g = lane >> 2, cl = lane & 3;

    const int arow = tid >> 3, ac4 = (tid & 7) * 4;
    const float* Ap0 = A + (size_t)(m0 + arow) * K + ac4;
    const float* Ap1 = A + (size_t)(m0 + arow + 32) * K + ac4;
    const float* Wp0 = W + (size_t)(n0 + arow) * K + ac4;
    const float* Wp1 = W + (size_t)(n0 + arow + 32) * K + ac4;
    const float* Wp2 = W + (size_t)(n0 + arow + 64) * K + ac4;
    const float* Wp3 = W + (size_t)(n0 + arow + 96) * K + ac4;

    const int nc = K >> 5;

    {
        cp16(&As[0][arow][ac4], Ap0);
        cp16(&As[0][arow + 32][ac4], Ap1);
        cp16(&Bs[0][arow][ac4], Wp0);
        cp16(&Bs[0][arow + 32][ac4], Wp1);
        cp16(&Bs[0][arow + 64][ac4], Wp2);
        cp16(&Bs[0][arow + 96][ac4], Wp3);
        cp_commit();
    }

    float acc[2][4][4];
    #pragma unroll
    for (int i = 0; i < 2; i++)
        #pragma unroll
        for (int j = 0; j < 4; j++)
            #pragma unroll
            for (int r = 0; r < 4; r++) acc[i][j][r] = 0.f;

    for (int c = 0; c < nc; c++) {
        const int buf = c & 1;
        cp_wait0();
        __syncthreads();

        if (c + 1 < nc) {
            const int nb = buf ^ 1, off = (c + 1) * 32;
            cp16(&As[nb][arow][ac4], Ap0 + off);
            cp16(&As[nb][arow + 32][ac4], Ap1 + off);
            cp16(&Bs[nb][arow][ac4], Wp0 + off);
            cp16(&Bs[nb][arow + 32][ac4], Wp1 + off);
            cp16(&Bs[nb][arow + 64][ac4], Wp2 + off);
            cp16(&Bs[nb][arow + 96][ac4], Wp3 + off);
            cp_commit();
        }

        #pragma unroll
        for (int ks = 0; ks < 4; ks++) {
            const int kk = ks * 8;
            uint32_t af[2][4], bf[4][2];
            #pragma unroll
            for (int mt = 0; mt < 2; mt++) {
                int r = warp_m * 32 + mt * 16 + g;
                af[mt][0] = to_tf32(As[buf][r][kk + cl]);
                af[mt][1] = to_tf32(As[buf][r + 8][kk + cl]);
                af[mt][2] = to_tf32(As[buf][r][kk + 4 + cl]);
                af[mt][3] = to_tf32(As[buf][r + 8][kk + 4 + cl]);
            }
            #pragma unroll
            for (int nt = 0; nt < 4; nt++) {
                int n = warp_n * 32 + nt * 8 + g;
                bf[nt][0] = to_tf32(Bs[buf][n][kk + cl]);
                bf[nt][1] = to_tf32(Bs[buf][n][kk + 4 + cl]);
            }
            #pragma unroll
            for (int mt = 0; mt < 2; mt++)
                #pragma unroll
                for (int nt = 0; nt < 4; nt++)
                    mma_tf32(acc[mt][nt], af[mt], bf[nt]);
        }
    }

    #pragma unroll
    for (int mt = 0; mt < 2; mt++) {
        int r = m0 + warp_m * 32 + mt * 16 + g;
        #pragma unroll
        for (int nt = 0; nt < 4; nt++) {
            int n = n0 + warp_n * 32 + nt * 8 + cl * 2;
            float b0 = bias[n], b1 = bias[n + 1];
            acc[mt][nt][0] += b0; acc[mt][nt][1] += b1;
            acc[mt][nt][2] += b0; acc[mt][nt][3] += b1;
            if (MODE == 1) {
                #pragma unroll
                for (int i = 0; i < 4; i++)
                    acc[mt][nt][i] = acc[mt][nt][i] * 0.5f *
                        (1.0f + erff(acc[mt][nt][i] * 0.70710678118654752f));
            }
            if (MODE >= 2) {
                float2 r0 = *(const float2*)(res + (size_t)r * N + n);
                float2 r1 = *(const float2*)(res + (size_t)(r + 8) * N + n);
                acc[mt][nt][0] += r0.x; acc[mt][nt][1] += r0.y;
                acc[mt][nt][2] += r1.x; acc[mt][nt][3] += r1.y;
            }
        }
    }

    if (MODE == 3) {
        __syncthreads();
        float* rsum = (float*)As;            // [64][17]
        float* rsq  = rsum + 64 * 17;        // [64][17]
        float* st   = rsq + 64 * 17;         // [64][2]
        const int slot = warp_n * 4 + cl;
        #pragma unroll
        for (int mt = 0; mt < 2; mt++)
            #pragma unroll
            for (int rh = 0; rh < 2; rh++) {
                int lr = warp_m * 32 + mt * 16 + rh * 8 + g;
                float s = 0.f, q = 0.f;
                #pragma unroll
                for (int nt = 0; nt < 4; nt++) {
                    float v0 = acc[mt][nt][2 * rh], v1 = acc[mt][nt][2 * rh + 1];
                    s += v0 + v1; q += v0 * v0 + v1 * v1;
                }
                rsum[lr * 17 + slot] = s;
                rsq[lr * 17 + slot] = q;
            }
        __syncthreads();
        if (tid < 64) {
            float s = 0.f, q = 0.f;
            #pragma unroll
            for (int i = 0; i < 16; i++) {
                s += rsum[tid * 17 + i];
                q += rsq[tid * 17 + i];
            }
            float mean = s * (1.f / 128.f);
            float var = q * (1.f / 128.f) - mean * mean;
            st[tid * 2]     = mean;
            st[tid * 2 + 1] = rsqrtf(var + 1e-5f);
        }
        __syncthreads();
        #pragma unroll
        for (int mt = 0; mt < 2; mt++) {
            #pragma unroll
            for (int rh = 0; rh < 2; rh++) {
                int lr = warp_m * 32 + mt * 16 + rh * 8 + g;
                int r = m0 + lr;
                float mean = st[lr * 2], rstd = st[lr * 2 + 1];
                #pragma unroll
                for (int nt = 0; nt < 4; nt++) {
                    int n = n0 + warp_n * 32 + nt * 8 + cl * 2;
                    float v0 = acc[mt][nt][2 * rh], v1 = acc[mt][nt][2 * rh + 1];
                    *(float2*)(C + (size_t)r * N + n) = make_float2(v0, v1);
                    float h0 = (v0 - mean) * rstd * lns[n] + lnb[n];
                    float h1 = (v1 - mean) * rstd * lns[n + 1] + lnb[n + 1];
                    *(float2*)(Hout + (size_t)r * N + n) = make_float2(h0, h1);
                }
            }
        }
    } else {
        #pragma unroll
        for (int mt = 0; mt < 2; mt++) {
            int r = m0 + warp_m * 32 + mt * 16 + g;
            #pragma unroll
            for (int nt = 0; nt < 4; nt++) {
                int n = n0 + warp_n * 32 + nt * 8 + cl * 2;
                *(float2*)(C + (size_t)r * N + n) =
                    make_float2(acc[mt][nt][0], acc[mt][nt][1]);
                *(float2*)(C + (size_t)(r + 8) * N + n) =
                    make_float2(acc[mt][nt][2], acc[mt][nt][3]);
            }
        }
    }
}

// ---------------------------------------------------------------------------
// Conv 3x3 s2 p1 as implicit GEMM on tensor cores: M=16384, N=128, K=2304.
// ---------------------------------------------------------------------------
__global__ __launch_bounds__(256)
void conv_mma(const float* __restrict__ feat, const float* __restrict__ W,
              const float* __restrict__ cb, const float* __restrict__ pos,
              float* __restrict__ x)
{
    __shared__ uint32_t As[64][SK];
    __shared__ uint32_t Bs[128][SK];
    const int K = 2304;
    const int tid = threadIdx.x;
    const int lane = tid & 31, wid = tid >> 5;
    const int warp_m = wid >> 2, warp_n = wid & 3;
    const int m0 = blockIdx.y * 64;
    const int g = lane >> 2, cl = lane & 3;

    float acc[2][4][4];
    #pragma unroll
    for (int i = 0; i < 2; i++)
        #pragma unroll
        for (int j = 0; j < 4; j++)
            #pragma unroll
            for (int r = 0; r < 4; r++) acc[i][j][r] = 0.f;

    for (int k0 = 0; k0 < K; k0 += 32) {
        #pragma unroll
        for (int it = 0; it < 8; it++) {
            int e = tid + it * 256;
            int ml = e >> 5, kl = e & 31;
            int m = m0 + ml;
            int k = k0 + kl;
            int b = m >> 8, p = m & 255;
            int y = p >> 4, xx = p & 15;
            int c = k / 9, rr = k - c * 9;
            int ky = rr / 3, kx = rr - ky * 3;
            int iy = y * 2 - 1 + ky;
            int ix = xx * 2 - 1 + kx;
            float v = 0.f;
            if (iy >= 0 && iy < 32 && ix >= 0 && ix < 32)
                v = feat[(((size_t)b * 256 + c) * 32 + iy) * 32 + ix];
            As[ml][kl] = to_tf32(v);
        }
        #pragma unroll
        for (int it = 0; it < 4; it++) {
            int e = tid + it * 256;
            int row = e >> 3, c4 = (e & 7) * 4;
            float4 v = *(const float4*)(W + (size_t)row * K + k0 + c4);
            Bs[row][c4 + 0] = to_tf32(v.x);
            Bs[row][c4 + 1] = to_tf32(v.y);
            Bs[row][c4 + 2] = to_tf32(v.z);
            Bs[row][c4 + 3] = to_tf32(v.w);
        }
        __syncthreads();

        #pragma unroll
        for (int ks = 0; ks < 4; ks++) {
            const int kk = ks * 8;
            uint32_t af[2][4], bf[4][2];
            #pragma unroll
            for (int mt = 0; mt < 2; mt++) {
                int r = warp_m * 32 + mt * 16 + g;
                af[mt][0] = As[r][kk + cl];
                af[mt][1] = As[r + 8][kk + cl];
                af[mt][2] = As[r][kk + 4 + cl];
                af[mt][3] = As[r + 8][kk + 4 + cl];
            }
            #pragma unroll
            for (int nt = 0; nt < 4; nt++) {
                int n = warp_n * 32 + nt * 8 + g;
                bf[nt][0] = Bs[n][kk + cl];
                bf[nt][1] = Bs[n][kk + 4 + cl];
            }
            #pragma unroll
            for (int mt = 0; mt < 2; mt++)
                #pragma unroll
                for (int nt = 0; nt < 4; nt++)
                    mma_tf32(acc[mt][nt], af[mt], bf[nt]);
        }
        __syncthreads();
    }

    #pragma unroll
    for (int mt = 0; mt < 2; mt++) {
        int r = m0 + warp_m * 32 + mt * 16 + g;
        #pragma unroll
        for (int rr = 0; rr < 2; rr++) {
            int m = r + rr * 8;
            int b = m >> 8, p = m & 255;
            float* dst = x + ((size_t)b * NTOK + p + 1) * 128;
            const float* pp = pos + (size_t)(p + 1) * 128;
            #pragma unroll
            for (int nt = 0; nt < 4; nt++) {
                int n = warp_n * 32 + nt * 8 + cl * 2;
                float v0 = acc[mt][nt][rr * 2 + 0] + cb[n] + pp[n];
                float v1 = acc[mt][nt][rr * 2 + 1] + cb[n + 1] + pp[n + 1];
                *(float2*)(dst + n) = make_float2(v0, v1);
            }
        }
    }
}

// cls token rows: x[b,0,:] = cls + pos[0]
__global__ void cls_kernel(const float* __restrict__ cls,
                           const float* __restrict__ pos, float* __restrict__ x)
{
    int b = blockIdx.x, e = threadIdx.x;
    x[(size_t)b * NTOK * 128 + e] = cls[e] + pos[e];
}

// ---------------------------------------------------------------------------
// LayerNorm over E=128 (used once, before layer 0).
// ---------------------------------------------------------------------------
__global__ __launch_bounds__(256)
void ln_kernel(const float* __restrict__ x, float* __restrict__ h,
               const float* __restrict__ s, const float* __restrict__ b, float eps)
{
    int tok = blockIdx.x * 8 + (threadIdx.x >> 5);
    int lane = threadIdx.x & 31;
    if (tok >= TOKENS) return;
    const float4* xr = (const float4*)(x + (size_t)tok * 128);
    float4 v = xr[lane];
    float mean = warp_sum(v.x + v.y + v.z + v.w) * (1.f / 128.f);
    float dx = v.x - mean, dy = v.y - mean, dz = v.z - mean, dw = v.w - mean;
    float var = warp_sum(dx * dx + dy * dy + dz * dz + dw * dw) * (1.f / 128.f);
    float rstd = rsqrtf(var + eps);
    float4 sv = ((const float4*)s)[lane];
    float4 bv = ((const float4*)b)[lane];
    float4 o;
    o.x = dx * rstd * sv.x + bv.x;
    o.y = dy * rstd * sv.y + bv.y;
    o.z = dz * rstd * sv.z + bv.z;
    o.w = dw * rstd * sv.w + bv.w;
    ((float4*)(h + (size_t)tok * 128))[lane] = o;
}

// ---------------------------------------------------------------------------
// Full tensor-core attention, block per (b,h,z), 2 CTA/SM.
// Stage 1: S = QK^T mma (each warp one 32-key chunk) -> Ps (f32).
// Stage 2: softmax-lite (no max-sub, scores bounded): p=exp(s*scale) stored
//          UNNORMALIZED as tf32 into Ps; 1/sum kept per query.
// Stage 3: PV mma: warp w computes partial O(32q x 32d) for its key chunk.
// Stage 4: partials -> smem (reusing Ps region), 8-way tree reduce,
//          + key-256 term + normalization, coalesced float4 store.
// ---------------------------------------------------------------------------
#define OFF_KT 0               // u32 [257][36]  = 9252
#define OFF_VT 9252            // u32 [32][264]  = 8448  (V^T, tf32)
#define OFF_QT 17700           // u32 [32][36]   = 1152
#define OFF_PS 18852           // f32/u32 [32][264] = 8448 ; also [8][32][33] partials
#define OFF_INV 27300          // f32 [32]
#define OFF_P256 27332         // f32 [32]
#define ATT_SMEM ((27364 + 28) * 4)   // 109568 B

__global__ __launch_bounds__(256)
void attn_kernel(const float* __restrict__ qkv, float* __restrict__ o)
{
    extern __shared__ float sm[];
    uint32_t* Kt = (uint32_t*)sm;               // [257][36]
    uint32_t* Vt = (uint32_t*)(sm + OFF_VT);    // [32][264] V^T tf32
    uint32_t* Qt = (uint32_t*)(sm + OFF_QT);    // [32][36]
    float*    Ps = sm + OFF_PS;                 // [32][264] S/P, then partials
    uint32_t* Pu = (uint32_t*)Ps;
    float*    invs = sm + OFF_INV;              // [32]
    float*    p256s = sm + OFF_P256;            // [32]

    int b = blockIdx.x, h = blockIdx.y, z = blockIdx.z;
    int tid = threadIdx.x, w = tid >> 5, lane = tid & 31;
    const int g = lane >> 2, cl = lane & 3;
    const float* base = qkv + (size_t)b * NTOK * 384 + h * 32;

    // load K (tf32, row-major) and V (tf32, transposed)
    for (int i = tid; i < 257 * 32; i += 256) {
        int m = i >> 5, d = i & 31;
        const float* p = base + (size_t)m * 384;
        Kt[m * 36 + d] = to_tf32(p[128 + d]);
        Vt[d * 264 + m] = to_tf32(p[256 + d]);
    }
    __syncthreads();

    const float scale = 0.17677669529663687f;  // 1/sqrt(32)
    const float k256 = __uint_as_float(Kt[256 * 36 + lane]);

    for (int t = z * 3; t < z * 3 + 3; t++) {
        if (t * 32 >= NTOK) break;

        // ---- load Q tile (tf32), zero-pad rows >= NTOK ----
        {
            int row = tid >> 3, d4 = (tid & 7) * 4;
            int q = t * 32 + row;
            float4 v = make_float4(0.f, 0.f, 0.f, 0.f);
            if (q < NTOK) v = *(const float4*)(base + (size_t)q * 384 + d4);
            Qt[row * 36 + d4 + 0] = to_tf32(v.x);
            Qt[row * 36 + d4 + 1] = to_tf32(v.y);
            Qt[row * 36 + d4 + 2] = to_tf32(v.z);
            Qt[row * 36 + d4 + 3] = to_tf32(v.w);
        }
        __syncthreads();

        // ---- stage 1: S(32q x 32k) per warp for keys [32w, 32w+32) ----
        {
            float s[2][4][4];
            #pragma unroll
            for (int mt = 0; mt < 2; mt++)
                #pragma unroll
                for (int nt = 0; nt < 4; nt++)
                    #pragma unroll
                    for (int r = 0; r < 4; r++) s[mt][nt][r] = 0.f;
            #pragma unroll
            for (int ks = 0; ks < 4; ks++) {
                const int kk = ks * 8;
                uint32_t aq[2][4], bk[4][2];
                #pragma unroll
                for (int mt = 0; mt < 2; mt++) {
                    int r = mt * 16 + g;
                    aq[mt][0] = Qt[r * 36 + kk + cl];
                    aq[mt][1] = Qt[(r + 8) * 36 + kk + cl];
                    aq[mt][2] = Qt[r * 36 + kk + 4 + cl];
                    aq[mt][3] = Qt[(r + 8) * 36 + kk + 4 + cl];
                }
                #pragma unroll
                for (int nt = 0; nt < 4; nt++) {
                    int kr = w * 32 + nt * 8 + g;
                    bk[nt][0] = Kt[kr * 36 + kk + cl];
                    bk[nt][1] = Kt[kr * 36 + kk + 4 + cl];
                }
                #pragma unroll
                for (int mt = 0; mt < 2; mt++)
                    #pragma unroll
                    for (int nt = 0; nt < 4; nt++)
                        mma_tf32(s[mt][nt], aq[mt], bk[nt]);
            }
            #pragma unroll
            for (int mt = 0; mt < 2; mt++) {
                int row = mt * 16 + g;
                #pragma unroll
                for (int nt = 0; nt < 4; nt++) {
                    int col = w * 32 + nt * 8 + 2 * cl;
                    Ps[row * 264 + col]           = s[mt][nt][0];
                    Ps[row * 264 + col + 1]       = s[mt][nt][1];
                    Ps[(row + 8) * 264 + col]     = s[mt][nt][2];
                    Ps[(row + 8) * 264 + col + 1] = s[mt][nt][3];
                }
            }
        }
        __syncthreads();

        // ---- stage 2: softmax-lite on own 4 query rows ----
        #pragma unroll
        for (int qq = 0; qq < 4; qq++) {
            int qloc = w * 4 + qq;
            int qglob = t * 32 + qloc;
            float qd = (qglob < NTOK) ? base[(size_t)qglob * 384 + lane] : 0.f;
            float s256 = warp_sum(qd * k256) * scale;
            float p[8];
            float ls = 0.f;
            #pragma unroll
            for (int j = 0; j < 8; j++) {
                p[j] = __expf(Ps[qloc * 264 + lane + 32 * j] * scale);
                ls += p[j];
            }
            float p256 = __expf(s256);
            ls = warp_sum(ls) + p256;
            #pragma unroll
            for (int j = 0; j < 8; j++)
                Pu[qloc * 264 + lane + 32 * j] = to_tf32(p[j]);
            if (lane == 0) {
                invs[qloc] = 1.f / ls;
                p256s[qloc] = p256;
            }
        }
        __syncthreads();

        // ---- stage 3: partial O(32q x 32d) for keys [32w, 32w+32) ----
        float pacc[2][4][4];
        #pragma unroll
        for (int mt = 0; mt < 2; mt++)
            #pragma unroll
            for (int nt = 0; nt < 4; nt++)
                #pragma unroll
                for (int r = 0; r < 4; r++) pacc[mt][nt][r] = 0.f;
        {
            const int k0 = w * 32;
            #pragma unroll
            for (int ks = 0; ks < 4; ks++) {
                const int kk = k0 + ks * 8;
                uint32_t ap[2][4], bv[4][2];
                #pragma unroll
                for (int mt = 0; mt < 2; mt++) {
                    int r = mt * 16 + g;
                    ap[mt][0] = Pu[r * 264 + kk + cl];
                    ap[mt][1] = Pu[(r + 8) * 264 + kk + cl];
                    ap[mt][2] = Pu[r * 264 + kk + 4 + cl];
                    ap[mt][3] = Pu[(r + 8) * 264 + kk + 4 + cl];
                }
                #pragma unroll
                for (int nt = 0; nt < 4; nt++) {
                    int d = nt * 8 + g;
                    bv[nt][0] = Vt[d * 264 + kk + cl];
                    bv[nt][1] = Vt[d * 264 + kk + 4 + cl];
                }
                #pragma unroll
                for (int mt = 0; mt < 2; mt++)
                    #pragma unroll
                    for (int nt = 0; nt < 4; nt++)
                        mma_tf32(pacc[mt][nt], ap[mt], bv[nt]);
            }
        }
        __syncthreads();   // all P reads done; Ps region now reusable

        // ---- stage 4a: write partials [8][32][33] into Ps region ----
        {
            float* Pr = Ps + w * 1056;   // 32*33
            #pragma unroll
            for (int mt = 0; mt < 2; mt++) {
                int row = mt * 16 + g;
                #pragma unroll
                for (int nt = 0; nt < 4; nt++) {
                    int d0 = nt * 8 + 2 * cl;
                    Pr[row * 33 + d0]           = pacc[mt][nt][0];
                    Pr[row * 33 + d0 + 1]       = pacc[mt][nt][1];
                    Pr[(row + 8) * 33 + d0]     = pacc[mt][nt][2];
                    Pr[(row + 8) * 33 + d0 + 1] = pacc[mt][nt][3];
                }
            }
        }
        __syncthreads();

        // ---- stage 4b: reduce 8 partials + key-256 + normalize, store ----
        {
            int q = tid >> 3;            // 0..31
            int d0 = (tid & 7) * 4;      // 0,4,...,28
            int qglob = t * 32 + q;
            float r0 = 0.f, r1 = 0.f, r2 = 0.f, r3 = 0.f;
            #pragma unroll
            for (int ww = 0; ww < 8; ww++) {
                const float* Pr = Ps + ww * 1056 + q * 33 + d0;
                r0 += Pr[0]; r1 += Pr[1]; r2 += Pr[2]; r3 += Pr[3];
            }
            float pk = p256s[q];
            r0 += pk * __uint_as_float(Vt[(d0 + 0) * 264 + 256]);
            r1 += pk * __uint_as_float(Vt[(d0 + 1) * 264 + 256]);
            r2 += pk * __uint_as_float(Vt[(d0 + 2) * 264 + 256]);
            r3 += pk * __uint_as_float(Vt[(d0 + 3) * 264 + 256]);
            float inv = invs[q];
            if (qglob < NTOK) {
                float4 res = make_float4(r0 * inv, r1 * inv, r2 * inv, r3 * inv);
                *(float4*)(o + ((size_t)b * NTOK + qglob) * 128 + h * 32 + d0) = res;
            }
        }
        __syncthreads();   // before next tile overwrites Qt/Ps
    }
}

// ---------------------------------------------------------------------------
// Head: final LN (eps 1e-6) on token 0 of each batch, out_feat + fc.
// ---------------------------------------------------------------------------
__global__ __launch_bounds__(128)
void head_kernel(const float* __restrict__ x, const float* __restrict__ fns,
                 const float* __restrict__ fnb, const float* __restrict__ fcw,
                 const float* __restrict__ fcb, float* __restrict__ out)
{
    __shared__ float red[4];
    __shared__ float fsh[128];
    int b = blockIdx.x, t = threadIdx.x, w = t >> 5, lane = t & 31;
    float v = x[(size_t)b * NTOK * 128 + t];

    float s = warp_sum(v);
    if (lane == 0) red[w] = s;
    __syncthreads();
    float mean = (red[0] + red[1] + red[2] + red[3]) * (1.f / 128.f);
    __syncthreads();
    float d = v - mean;
    float sq = warp_sum(d * d);
    if (lane == 0) red[w] = sq;
    __syncthreads();
    float var = (red[0] + red[1] + red[2] + red[3]) * (1.f / 128.f);
    float rstd = rsqrtf(var + 1e-6f);
    float f = d * rstd * fns[t] + fnb[t];
    out[128 + (size_t)b * 128 + t] = f;
    fsh[t] = f;
    __syncthreads();
    if (t < 2) {
        float a = fcb[t];
        for (int e = 0; e < 128; e++) a += fsh[e] * fcw[t * 128 + e];
        out[b * 2 + t] = a;
    }
}

// ---------------------------------------------------------------------------
extern "C" void kernel_launch(void* const* d_in, const int* in_sizes, int n_in,
                              void* d_out, int out_size)
{
    const float* feat    = (const float*)d_in[0];
    const float* conv_w  = (const float*)d_in[1];
    const float* conv_b  = (const float*)d_in[2];
    const float* pos_emb = (const float*)d_in[3];
    const float* cls_tok = (const float*)d_in[4];
    const float* ln1_s   = (const float*)d_in[5];
    const float* ln1_b   = (const float*)d_in[6];
    const float* qkv_w   = (const float*)d_in[7];
    const float* qkv_b   = (const float*)d_in[8];
    const float* proj_w  = (const float*)d_in[9];
    const float* proj_b  = (const float*)d_in[10];
    const float* ln2_s   = (const float*)d_in[11];
    const float* ln2_b   = (const float*)d_in[12];
    const float* ffn1_w  = (const float*)d_in[13];
    const float* ffn1_b  = (const float*)d_in[14];
    const float* ffn2_w  = (const float*)d_in[15];
    const float* ffn2_b  = (const float*)d_in[16];
    const float* fn_s    = (const float*)d_in[17];
    const float* fn_b    = (const float*)d_in[18];
    const float* fc_w    = (const float*)d_in[19];
    const float* fc_b    = (const float*)d_in[20];
    float* out = (float*)d_out;

    float *px, *ph, *pq, *po, *pf;
    cudaGetSymbolAddress((void**)&px, g_x);
    cudaGetSymbolAddress((void**)&ph, g_h);
    cudaGetSymbolAddress((void**)&pq, g_qkv);
    cudaGetSymbolAddress((void**)&po, g_o);
    cudaGetSymbolAddress((void**)&pf, g_ffn);

    cudaFuncSetAttribute(attn_kernel, cudaFuncAttributeMaxDynamicSharedMemorySize, ATT_SMEM);

    cls_kernel<<<BATCH, 128>>>(cls_tok, pos_emb, px);
    conv_mma<<<dim3(1, 256), 256>>>(feat, conv_w, conv_b, pos_emb, px);
    // initial LN (layer 0 ln1); subsequent LNs are fused into gemm epilogues
    ln_kernel<<<TOKENS / 8, 256>>>(px, ph, ln1_s, ln1_b, 1e-5f);

    for (int l = 0; l < 12; l++) {
        gemm_mma<0><<<dim3(3, 257), 256>>>(
            ph, qkv_w + (size_t)l * 384 * 128, nullptr, nullptr,
            qkv_b + l * 384, nullptr, pq, nullptr, TOKENS, 384, 128);
        attn_kernel<<<dim3(BATCH, 4, 3), 256, ATT_SMEM>>>(pq, po);
        gemm_mma<3><<<dim3(1, 257), 256>>>(
            po, proj_w + (size_t)l * 128 * 128, ln2_s + l * 128, ln2_b + l * 128,
            proj_b + l * 128, px, px, ph, TOKENS, 128, 128);
        gemm_mma<1><<<dim3(4, 257), 256>>>(
            ph, ffn1_w + (size_t)l * 512 * 128, nullptr, nullptr,
            ffn1_b + l * 512, nullptr, pf, nullptr, TOKENS, 512, 128);
        if (l < 11) {
            gemm_mma<3><<<dim3(1, 257), 256>>>(
                pf, ffn2_w + (size_t)l * 128 * 512,
                ln1_s + (l + 1) * 128, ln1_b + (l + 1) * 128,
                ffn2_b + l * 128, px, px, ph, TOKENS, 128, 512);
        } else {
            gemm_mma<2><<<dim3(1, 257), 256>>>(
                pf, ffn2_w + (size_t)l * 128 * 512, nullptr, nullptr,
                ffn2_b + l * 128, px, px, nullptr, TOKENS, 128, 512);
        }
    }

    head_kernel<<<BATCH, 128>>>(px, fn_s, fn_b, fc_w, fc_b, out);
}

// round 10
// speedup vs baseline: 1.8939x; 1.0564x over previous
#include <cuda_runtime.h>
#include <math.h>
#include <stdint.h>

// ---------------------------------------------------------------------------
// Shapes (fixed): L=12, E=128, H=4, D=32, F=512, B=64, CIN=256, N=257
// Tokens T = B*N = 16448 = 64 * 257
// ---------------------------------------------------------------------------
#define TOKENS 16448
#define NTOK 257
#define BATCH 64

// scratch (device globals; allocation is forbidden)
__device__ float g_x  [TOKENS * 128];   // residual stream (full fp32)
__device__ float g_h  [TOKENS * 128];   // post-LN (tf32-rounded bits)
__device__ float g_qkv[TOKENS * 384];   // qkv (tf32-rounded bits)
__device__ float g_o  [TOKENS * 128];   // attention out (tf32-rounded bits)
__device__ float g_ffn[TOKENS * 512];   // ffn hidden (tf32-rounded bits)
// tf32-pre-rounded weights
__device__ float g_wqkv[12 * 384 * 128];
__device__ float g_wproj[12 * 128 * 128];
__device__ float g_wf1 [12 * 512 * 128];
__device__ float g_wf2 [12 * 128 * 512];

__device__ __forceinline__ float warp_sum(float v) {
    #pragma unroll
    for (int o = 16; o; o >>= 1) v += __shfl_xor_sync(0xffffffffu, v, o);
    return v;
}

__device__ __forceinline__ uint32_t to_tf32(float f) {
    uint32_t u;
    asm("cvt.rna.tf32.f32 %0, %1;" : "=r"(u) : "f"(f));
    return u;
}
__device__ __forceinline__ float tf32f(float f) {
    return __uint_as_float(to_tf32(f));
}

// D = A(16x8, row) * B(8x8, col) + D, tf32 in, f32 accum
__device__ __forceinline__ void mma_tf32(float c[4], const uint32_t a[4], const uint32_t b[2]) {
    asm volatile(
        "mma.sync.aligned.m16n8k8.row.col.f32.tf32.tf32.f32 "
        "{%0,%1,%2,%3}, {%4,%5,%6,%7}, {%8,%9}, {%0,%1,%2,%3};"
        : "+f"(c[0]), "+f"(c[1]), "+f"(c[2]), "+f"(c[3])
        : "r"(a[0]), "r"(a[1]), "r"(a[2]), "r"(a[3]), "r"(b[0]), "r"(b[1]));
}

__device__ __forceinline__ void cp16(void* smem, const void* g) {
    uint32_t s = (uint32_t)__cvta_generic_to_shared(smem);
    asm volatile("cp.async.cg.shared.global [%0], [%1], 16;" :: "r"(s), "l"(g));
}
__device__ __forceinline__ void cp_commit() {
    asm volatile("cp.async.commit_group;");
}
__device__ __forceinline__ void cp_wait0() {
    asm volatile("cp.async.wait_group 0;");
}

#define SK 36   // padded k-stride: conflict-free fragment LDS

// ---------------------------------------------------------------------------
// Weight pre-conversion: tf32-round fp32 weights (float4 grid-stride).
// ---------------------------------------------------------------------------
__global__ __launch_bounds__(256)
void cvtw_kernel(const float4* __restrict__ src, float4* __restrict__ dst, int n4)
{
    int i = blockIdx.x * blockDim.x + threadIdx.x;
    if (i < n4) {
        float4 v = src[i];
        v.x = tf32f(v.x); v.y = tf32f(v.y); v.z = tf32f(v.z); v.w = tf32f(v.w);
        dst[i] = v;
    }
}

// ---------------------------------------------------------------------------
// cp.async double-buffered tensor-core GEMM; operands are PRE-ROUNDED tf32
// bits, so the mainloop does raw loads (no cvt).
// MODE 0: +bias (out tf32)   MODE 1: gelu(+bias) (out tf32)
// MODE 2: +bias+res (out fp32)
// MODE 3: +bias+res -> C fp32, AND LN(C) -> Hout tf32 (N==128)
// ---------------------------------------------------------------------------
template <int MODE>
__global__ __launch_bounds__(256)
void gemm_mma(const float* __restrict__ A, const float* __restrict__ W,
              const float* __restrict__ lns, const float* __restrict__ lnb,
              const float* __restrict__ bias, const float* __restrict__ res,
              float* __restrict__ C, float* __restrict__ Hout,
              int M, int N, int K)
{
    __shared__ float As[2][64][SK];
    __shared__ float Bs[2][128][SK];
    const int tid = threadIdx.x;
    const int lane = tid & 31, wid = tid >> 5;
    const int warp_m = wid >> 2, warp_n = wid & 3;
    const int m0 = blockIdx.y * 64, n0 = blockIdx.x * 128;
    const int g = lane >> 2, cl = lane & 3;

    const int arow = tid >> 3, ac4 = (tid & 7) * 4;
    const float* Ap0 = A + (size_t)(m0 + arow) * K + ac4;
    const float* Ap1 = A + (size_t)(m0 + arow + 32) * K + ac4;
    const float* Wp0 = W + (size_t)(n0 + arow) * K + ac4;
    const float* Wp1 = W + (size_t)(n0 + arow + 32) * K + ac4;
    const float* Wp2 = W + (size_t)(n0 + arow + 64) * K + ac4;
    const float* Wp3 = W + (size_t)(n0 + arow + 96) * K + ac4;

    const int nc = K >> 5;

    {
        cp16(&As[0][arow][ac4], Ap0);
        cp16(&As[0][arow + 32][ac4], Ap1);
        cp16(&Bs[0][arow][ac4], Wp0);
        cp16(&Bs[0][arow + 32][ac4], Wp1);
        cp16(&Bs[0][arow + 64][ac4], Wp2);
        cp16(&Bs[0][arow + 96][ac4], Wp3);
        cp_commit();
    }

    float acc[2][4][4];
    #pragma unroll
    for (int i = 0; i < 2; i++)
        #pragma unroll
        for (int j = 0; j < 4; j++)
            #pragma unroll
            for (int r = 0; r < 4; r++) acc[i][j][r] = 0.f;

    for (int c = 0; c < nc; c++) {
        const int buf = c & 1;
        cp_wait0();
        __syncthreads();

        if (c + 1 < nc) {
            const int nb = buf ^ 1, off = (c + 1) * 32;
            cp16(&As[nb][arow][ac4], Ap0 + off);
            cp16(&As[nb][arow + 32][ac4], Ap1 + off);
            cp16(&Bs[nb][arow][ac4], Wp0 + off);
            cp16(&Bs[nb][arow + 32][ac4], Wp1 + off);
            cp16(&Bs[nb][arow + 64][ac4], Wp2 + off);
            cp16(&Bs[nb][arow + 96][ac4], Wp3 + off);
            cp_commit();
        }

        #pragma unroll
        for (int ks = 0; ks < 4; ks++) {
            const int kk = ks * 8;
            uint32_t af[2][4], bf[4][2];
            #pragma unroll
            for (int mt = 0; mt < 2; mt++) {
                int r = warp_m * 32 + mt * 16 + g;
                af[mt][0] = __float_as_uint(As[buf][r][kk + cl]);
                af[mt][1] = __float_as_uint(As[buf][r + 8][kk + cl]);
                af[mt][2] = __float_as_uint(As[buf][r][kk + 4 + cl]);
                af[mt][3] = __float_as_uint(As[buf][r + 8][kk + 4 + cl]);
            }
            #pragma unroll
            for (int nt = 0; nt < 4; nt++) {
                int n = warp_n * 32 + nt * 8 + g;
                bf[nt][0] = __float_as_uint(Bs[buf][n][kk + cl]);
                bf[nt][1] = __float_as_uint(Bs[buf][n][kk + 4 + cl]);
            }
            #pragma unroll
            for (int mt = 0; mt < 2; mt++)
                #pragma unroll
                for (int nt = 0; nt < 4; nt++)
                    mma_tf32(acc[mt][nt], af[mt], bf[nt]);
        }
    }

    #pragma unroll
    for (int mt = 0; mt < 2; mt++) {
        int r = m0 + warp_m * 32 + mt * 16 + g;
        #pragma unroll
        for (int nt = 0; nt < 4; nt++) {
            int n = n0 + warp_n * 32 + nt * 8 + cl * 2;
            float b0 = bias[n], b1 = bias[n + 1];
            acc[mt][nt][0] += b0; acc[mt][nt][1] += b1;
            acc[mt][nt][2] += b0; acc[mt][nt][3] += b1;
            if (MODE == 1) {
                #pragma unroll
                for (int i = 0; i < 4; i++)
                    acc[mt][nt][i] = acc[mt][nt][i] * 0.5f *
                        (1.0f + erff(acc[mt][nt][i] * 0.70710678118654752f));
            }
            if (MODE >= 2) {
                float2 r0 = *(const float2*)(res + (size_t)r * N + n);
                float2 r1 = *(const float2*)(res + (size_t)(r + 8) * N + n);
                acc[mt][nt][0] += r0.x; acc[mt][nt][1] += r0.y;
                acc[mt][nt][2] += r1.x; acc[mt][nt][3] += r1.y;
            }
        }
    }

    if (MODE == 3) {
        __syncthreads();
        float* rsum = (float*)As;            // [64][17]
        float* rsq  = rsum + 64 * 17;        // [64][17]
        float* st   = rsq + 64 * 17;         // [64][2]
        const int slot = warp_n * 4 + cl;
        #pragma unroll
        for (int mt = 0; mt < 2; mt++)
            #pragma unroll
            for (int rh = 0; rh < 2; rh++) {
                int lr = warp_m * 32 + mt * 16 + rh * 8 + g;
                float s = 0.f, q = 0.f;
                #pragma unroll
                for (int nt = 0; nt < 4; nt++) {
                    float v0 = acc[mt][nt][2 * rh], v1 = acc[mt][nt][2 * rh + 1];
                    s += v0 + v1; q += v0 * v0 + v1 * v1;
                }
                rsum[lr * 17 + slot] = s;
                rsq[lr * 17 + slot] = q;
            }
        __syncthreads();
        if (tid < 64) {
            float s = 0.f, q = 0.f;
            #pragma unroll
            for (int i = 0; i < 16; i++) {
                s += rsum[tid * 17 + i];
                q += rsq[tid * 17 + i];
            }
            float mean = s * (1.f / 128.f);
            float var = q * (1.f / 128.f) - mean * mean;
            st[tid * 2]     = mean;
            st[tid * 2 + 1] = rsqrtf(var + 1e-5f);
        }
        __syncthreads();
        #pragma unroll
        for (int mt = 0; mt < 2; mt++) {
            #pragma unroll
            for (int rh = 0; rh < 2; rh++) {
                int lr = warp_m * 32 + mt * 16 + rh * 8 + g;
                int r = m0 + lr;
                float mean = st[lr * 2], rstd = st[lr * 2 + 1];
                #pragma unroll
                for (int nt = 0; nt < 4; nt++) {
                    int n = n0 + warp_n * 32 + nt * 8 + cl * 2;
                    float v0 = acc[mt][nt][2 * rh], v1 = acc[mt][nt][2 * rh + 1];
                    *(float2*)(C + (size_t)r * N + n) = make_float2(v0, v1);
                    float h0 = tf32f((v0 - mean) * rstd * lns[n] + lnb[n]);
                    float h1 = tf32f((v1 - mean) * rstd * lns[n + 1] + lnb[n + 1]);
                    *(float2*)(Hout + (size_t)r * N + n) = make_float2(h0, h1);
                }
            }
        }
    } else {
        #pragma unroll
        for (int mt = 0; mt < 2; mt++) {
            int r = m0 + warp_m * 32 + mt * 16 + g;
            #pragma unroll
            for (int nt = 0; nt < 4; nt++) {
                int n = n0 + warp_n * 32 + nt * 8 + cl * 2;
                float v0 = acc[mt][nt][0], v1 = acc[mt][nt][1];
                float v2 = acc[mt][nt][2], v3 = acc[mt][nt][3];
                if (MODE <= 1) {   // outputs feed another GEMM/attn: pre-round
                    v0 = tf32f(v0); v1 = tf32f(v1);
                    v2 = tf32f(v2); v3 = tf32f(v3);
                }
                *(float2*)(C + (size_t)r * N + n)       = make_float2(v0, v1);
                *(float2*)(C + (size_t)(r + 8) * N + n) = make_float2(v2, v3);
            }
        }
    }
}

// ---------------------------------------------------------------------------
// Conv 3x3 s2 p1 as implicit GEMM on tensor cores: M=16384, N=128, K=2304.
// ---------------------------------------------------------------------------
__global__ __launch_bounds__(256)
void conv_mma(const float* __restrict__ feat, const float* __restrict__ W,
              const float* __restrict__ cb, const float* __restrict__ pos,
              float* __restrict__ x)
{
    __shared__ uint32_t As[64][SK];
    __shared__ uint32_t Bs[128][SK];
    const int K = 2304;
    const int tid = threadIdx.x;
    const int lane = tid & 31, wid = tid >> 5;
    const int warp_m = wid >> 2, warp_n = wid & 3;
    const int m0 = blockIdx.y * 64;
    const int g = lane >> 2, cl = lane & 3;

    float acc[2][4][4];
    #pragma unroll
    for (int i = 0; i < 2; i++)
        #pragma unroll
        for (int j = 0; j < 4; j++)
            #pragma unroll
            for (int r = 0; r < 4; r++) acc[i][j][r] = 0.f;

    for (int k0 = 0; k0 < K; k0 += 32) {
        #pragma unroll
        for (int it = 0; it < 8; it++) {
            int e = tid + it * 256;
            int ml = e >> 5, kl = e & 31;
            int m = m0 + ml;
            int k = k0 + kl;
            int b = m >> 8, p = m & 255;
            int y = p >> 4, xx = p & 15;
            int c = k / 9, rr = k - c * 9;
            int ky = rr / 3, kx = rr - ky * 3;
            int iy = y * 2 - 1 + ky;
            int ix = xx * 2 - 1 + kx;
            float v = 0.f;
            if (iy >= 0 && iy < 32 && ix >= 0 && ix < 32)
                v = feat[(((size_t)b * 256 + c) * 32 + iy) * 32 + ix];
            As[ml][kl] = to_tf32(v);
        }
        #pragma unroll
        for (int it = 0; it < 4; it++) {
            int e = tid + it * 256;
            int row = e >> 3, c4 = (e & 7) * 4;
            float4 v = *(const float4*)(W + (size_t)row * K + k0 + c4);
            Bs[row][c4 + 0] = to_tf32(v.x);
            Bs[row][c4 + 1] = to_tf32(v.y);
            Bs[row][c4 + 2] = to_tf32(v.z);
            Bs[row][c4 + 3] = to_tf32(v.w);
        }
        __syncthreads();

        #pragma unroll
        for (int ks = 0; ks < 4; ks++) {
            const int kk = ks * 8;
            uint32_t af[2][4], bf[4][2];
            #pragma unroll
            for (int mt = 0; mt < 2; mt++) {
                int r = warp_m * 32 + mt * 16 + g;
                af[mt][0] = As[r][kk + cl];
                af[mt][1] = As[r + 8][kk + cl];
                af[mt][2] = As[r][kk + 4 + cl];
                af[mt][3] = As[r + 8][kk + 4 + cl];
            }
            #pragma unroll
            for (int nt = 0; nt < 4; nt++) {
                int n = warp_n * 32 + nt * 8 + g;
                bf[nt][0] = Bs[n][kk + cl];
                bf[nt][1] = Bs[n][kk + 4 + cl];
            }
            #pragma unroll
            for (int mt = 0; mt < 2; mt++)
                #pragma unroll
                for (int nt = 0; nt < 4; nt++)
                    mma_tf32(acc[mt][nt], af[mt], bf[nt]);
        }
        __syncthreads();
    }

    #pragma unroll
    for (int mt = 0; mt < 2; mt++) {
        int r = m0 + warp_m * 32 + mt * 16 + g;
        #pragma unroll
        for (int rr = 0; rr < 2; rr++) {
            int m = r + rr * 8;
            int b = m >> 8, p = m & 255;
            float* dst = x + ((size_t)b * NTOK + p + 1) * 128;
            const float* pp = pos + (size_t)(p + 1) * 128;
            #pragma unroll
            for (int nt = 0; nt < 4; nt++) {
                int n = warp_n * 32 + nt * 8 + cl * 2;
                float v0 = acc[mt][nt][rr * 2 + 0] + cb[n] + pp[n];
                float v1 = acc[mt][nt][rr * 2 + 1] + cb[n + 1] + pp[n + 1];
                *(float2*)(dst + n) = make_float2(v0, v1);
            }
        }
    }
}

// cls token rows: x[b,0,:] = cls + pos[0]
__global__ void cls_kernel(const float* __restrict__ cls,
                           const float* __restrict__ pos, float* __restrict__ x)
{
    int b = blockIdx.x, e = threadIdx.x;
    x[(size_t)b * NTOK * 128 + e] = cls[e] + pos[e];
}

// ---------------------------------------------------------------------------
// LayerNorm over E=128 (used once, before layer 0). Output tf32-rounded.
// ---------------------------------------------------------------------------
__global__ __launch_bounds__(256)
void ln_kernel(const float* __restrict__ x, float* __restrict__ h,
               const float* __restrict__ s, const float* __restrict__ b, float eps)
{
    int tok = blockIdx.x * 8 + (threadIdx.x >> 5);
    int lane = threadIdx.x & 31;
    if (tok >= TOKENS) return;
    const float4* xr = (const float4*)(x + (size_t)tok * 128);
    float4 v = xr[lane];
    float mean = warp_sum(v.x + v.y + v.z + v.w) * (1.f / 128.f);
    float dx = v.x - mean, dy = v.y - mean, dz = v.z - mean, dw = v.w - mean;
    float var = warp_sum(dx * dx + dy * dy + dz * dz + dw * dw) * (1.f / 128.f);
    float rstd = rsqrtf(var + eps);
    float4 sv = ((const float4*)s)[lane];
    float4 bv = ((const float4*)b)[lane];
    float4 o;
    o.x = tf32f(dx * rstd * sv.x + bv.x);
    o.y = tf32f(dy * rstd * sv.y + bv.y);
    o.z = tf32f(dz * rstd * sv.z + bv.z);
    o.w = tf32f(dw * rstd * sv.w + bv.w);
    ((float4*)(h + (size_t)tok * 128))[lane] = o;
}

// ---------------------------------------------------------------------------
// Full tensor-core attention (R9 structure). qkv is tf32-pre-rounded, so the
// K/V/Q preloads are raw bit copies (no cvt).
// ---------------------------------------------------------------------------
#define OFF_KT 0               // u32 [257][36]  = 9252
#define OFF_VT 9252            // u32 [32][264]  = 8448  (V^T, tf32)
#define OFF_QT 17700           // u32 [32][36]   = 1152
#define OFF_PS 18852           // f32/u32 [32][264] = 8448 ; also [8][32][33] partials
#define OFF_INV 27300          // f32 [32]
#define OFF_P256 27332         // f32 [32]
#define ATT_SMEM ((27364 + 28) * 4)   // 109568 B

__global__ __launch_bounds__(256)
void attn_kernel(const float* __restrict__ qkv, float* __restrict__ o)
{
    extern __shared__ float sm[];
    uint32_t* Kt = (uint32_t*)sm;               // [257][36]
    uint32_t* Vt = (uint32_t*)(sm + OFF_VT);    // [32][264] V^T
    uint32_t* Qt = (uint32_t*)(sm + OFF_QT);    // [32][36]
    float*    Ps = sm + OFF_PS;                 // [32][264] S/P, then partials
    uint32_t* Pu = (uint32_t*)Ps;
    float*    invs = sm + OFF_INV;              // [32]
    float*    p256s = sm + OFF_P256;            // [32]

    int b = blockIdx.x, h = blockIdx.y, z = blockIdx.z;
    int tid = threadIdx.x, w = tid >> 5, lane = tid & 31;
    const int g = lane >> 2, cl = lane & 3;
    const float* base = qkv + (size_t)b * NTOK * 384 + h * 32;

    for (int i = tid; i < 257 * 32; i += 256) {
        int m = i >> 5, d = i & 31;
        const float* p = base + (size_t)m * 384;
        Kt[m * 36 + d] = __float_as_uint(p[128 + d]);
        Vt[d * 264 + m] = __float_as_uint(p[256 + d]);
    }
    __syncthreads();

    const float scale = 0.17677669529663687f;  // 1/sqrt(32)
    const float k256 = __uint_as_float(Kt[256 * 36 + lane]);

    for (int t = z * 3; t < z * 3 + 3; t++) {
        if (t * 32 >= NTOK) break;

        {
            int row = tid >> 3, d4 = (tid & 7) * 4;
            int q = t * 32 + row;
            float4 v = make_float4(0.f, 0.f, 0.f, 0.f);
            if (q < NTOK) v = *(const float4*)(base + (size_t)q * 384 + d4);
            Qt[row * 36 + d4 + 0] = __float_as_uint(v.x);
            Qt[row * 36 + d4 + 1] = __float_as_uint(v.y);
            Qt[row * 36 + d4 + 2] = __float_as_uint(v.z);
            Qt[row * 36 + d4 + 3] = __float_as_uint(v.w);
        }
        __syncthreads();

        // ---- stage 1: S(32q x 32k) per warp for keys [32w, 32w+32) ----
        {
            float s[2][4][4];
            #pragma unroll
            for (int mt = 0; mt < 2; mt++)
                #pragma unroll
                for (int nt = 0; nt < 4; nt++)
                    #pragma unroll
                    for (int r = 0; r < 4; r++) s[mt][nt][r] = 0.f;
            #pragma unroll
            for (int ks = 0; ks < 4; ks++) {
                const int kk = ks * 8;
                uint32_t aq[2][4], bk[4][2];
                #pragma unroll
                for (int mt = 0; mt < 2; mt++) {
                    int r = mt * 16 + g;
                    aq[mt][0] = Qt[r * 36 + kk + cl];
                    aq[mt][1] = Qt[(r + 8) * 36 + kk + cl];
                    aq[mt][2] = Qt[r * 36 + kk + 4 + cl];
                    aq[mt][3] = Qt[(r + 8) * 36 + kk + 4 + cl];
                }
                #pragma unroll
                for (int nt = 0; nt < 4; nt++) {
                    int kr = w * 32 + nt * 8 + g;
                    bk[nt][0] = Kt[kr * 36 + kk + cl];
                    bk[nt][1] = Kt[kr * 36 + kk + 4 + cl];
                }
                #pragma unroll
                for (int mt = 0; mt < 2; mt++)
                    #pragma unroll
                    for (int nt = 0; nt < 4; nt++)
                        mma_tf32(s[mt][nt], aq[mt], bk[nt]);
            }
            #pragma unroll
            for (int mt = 0; mt < 2; mt++) {
                int row = mt * 16 + g;
                #pragma unroll
                for (int nt = 0; nt < 4; nt++) {
                    int col = w * 32 + nt * 8 + 2 * cl;
                    Ps[row * 264 + col]           = s[mt][nt][0];
                    Ps[row * 264 + col + 1]       = s[mt][nt][1];
                    Ps[(row + 8) * 264 + col]     = s[mt][nt][2];
                    Ps[(row + 8) * 264 + col + 1] = s[mt][nt][3];
                }
            }
        }
        __syncthreads();

        // ---- stage 2: softmax-lite on own 4 query rows ----
        #pragma unroll
        for (int qq = 0; qq < 4; qq++) {
            int qloc = w * 4 + qq;
            int qglob = t * 32 + qloc;
            float qd = (qglob < NTOK) ? base[(size_t)qglob * 384 + lane] : 0.f;
            float s256 = warp_sum(qd * k256) * scale;
            float p[8];
            float ls = 0.f;
            #pragma unroll
            for (int j = 0; j < 8; j++) {
                p[j] = __expf(Ps[qloc * 264 + lane + 32 * j] * scale);
                ls += p[j];
            }
            float p256 = __expf(s256);
            ls = warp_sum(ls) + p256;
            #pragma unroll
            for (int j = 0; j < 8; j++)
                Pu[qloc * 264 + lane + 32 * j] = to_tf32(p[j]);
            if (lane == 0) {
                invs[qloc] = 1.f / ls;
                p256s[qloc] = p256;
            }
        }
        __syncthreads();

        // ---- stage 3: partial O(32q x 32d) for keys [32w, 32w+32) ----
        float pacc[2][4][4];
        #pragma unroll
        for (int mt = 0; mt < 2; mt++)
            #pragma unroll
            for (int nt = 0; nt < 4; nt++)
                #pragma unroll
                for (int r = 0; r < 4; r++) pacc[mt][nt][r] = 0.f;
        {
            const int k0 = w * 32;
            #pragma unroll
            for (int ks = 0; ks < 4; ks++) {
                const int kk = k0 + ks * 8;
                uint32_t ap[2][4], bv[4][2];
                #pragma unroll
                for (int mt = 0; mt < 2; mt++) {
                    int r = mt * 16 + g;
                    ap[mt][0] = Pu[r * 264 + kk + cl];
                    ap[mt][1] = Pu[(r + 8) * 264 + kk + cl];
                    ap[mt][2] = Pu[r * 264 + kk + 4 + cl];
                    ap[mt][3] = Pu[(r + 8) * 264 + kk + 4 + cl];
                }
                #pragma unroll
                for (int nt = 0; nt < 4; nt++) {
                    int d = nt * 8 + g;
                    bv[nt][0] = Vt[d * 264 + kk + cl];
                    bv[nt][1] = Vt[d * 264 + kk + 4 + cl];
                }
                #pragma unroll
                for (int mt = 0; mt < 2; mt++)
                    #pragma unroll
                    for (int nt = 0; nt < 4; nt++)
                        mma_tf32(pacc[mt][nt], ap[mt], bv[nt]);
            }
        }
        __syncthreads();

        // ---- stage 4a: write partials [8][32][33] into Ps region ----
        {
            float* Pr = Ps + w * 1056;
            #pragma unroll
            for (int mt = 0; mt < 2; mt++) {
                int row = mt * 16 + g;
                #pragma unroll
                for (int nt = 0; nt < 4; nt++) {
                    int d0 = nt * 8 + 2 * cl;
                    Pr[row * 33 + d0]           = pacc[mt][nt][0];
                    Pr[row * 33 + d0 + 1]       = pacc[mt][nt][1];
                    Pr[(row + 8) * 33 + d0]     = pacc[mt][nt][2];
                    Pr[(row + 8) * 33 + d0 + 1] = pacc[mt][nt][3];
                }
            }
        }
        __syncthreads();

        // ---- stage 4b: reduce + key-256 + normalize, tf32 store ----
        {
            int q = tid >> 3;
            int d0 = (tid & 7) * 4;
            int qglob = t * 32 + q;
            float r0 = 0.f, r1 = 0.f, r2 = 0.f, r3 = 0.f;
            #pragma unroll
            for (int ww = 0; ww < 8; ww++) {
                const float* Pr = Ps + ww * 1056 + q * 33 + d0;
                r0 += Pr[0]; r1 += Pr[1]; r2 += Pr[2]; r3 += Pr[3];
            }
            float pk = p256s[q];
            r0 += pk * __uint_as_float(Vt[(d0 + 0) * 264 + 256]);
            r1 += pk * __uint_as_float(Vt[(d0 + 1) * 264 + 256]);
            r2 += pk * __uint_as_float(Vt[(d0 + 2) * 264 + 256]);
            r3 += pk * __uint_as_float(Vt[(d0 + 3) * 264 + 256]);
            float inv = invs[q];
            if (qglob < NTOK) {
                float4 res = make_float4(tf32f(r0 * inv), tf32f(r1 * inv),
                                         tf32f(r2 * inv), tf32f(r3 * inv));
                *(float4*)(o + ((size_t)b * NTOK + qglob) * 128 + h * 32 + d0) = res;
            }
        }
        __syncthreads();
    }
}

// ---------------------------------------------------------------------------
// Head: final LN (eps 1e-6) on token 0 of each batch, out_feat + fc.
// ---------------------------------------------------------------------------
__global__ __launch_bounds__(128)
void head_kernel(const float* __restrict__ x, const float* __restrict__ fns,
                 const float* __restrict__ fnb, const float* __restrict__ fcw,
                 const float* __restrict__ fcb, float* __restrict__ out)
{
    __shared__ float red[4];
    __shared__ float fsh[128];
    int b = blockIdx.x, t = threadIdx.x, w = t >> 5, lane = t & 31;
    float v = x[(size_t)b * NTOK * 128 + t];

    float s = warp_sum(v);
    if (lane == 0) red[w] = s;
    __syncthreads();
    float mean = (red[0] + red[1] + red[2] + red[3]) * (1.f / 128.f);
    __syncthreads();
    float d = v - mean;
    float sq = warp_sum(d * d);
    if (lane == 0) red[w] = sq;
    __syncthreads();
    float var = (red[0] + red[1] + red[2] + red[3]) * (1.f / 128.f);
    float rstd = rsqrtf(var + 1e-6f);
    float f = d * rstd * fns[t] + fnb[t];
    out[128 + (size_t)b * 128 + t] = f;
    fsh[t] = f;
    __syncthreads();
    if (t < 2) {
        float a = fcb[t];
        for (int e = 0; e < 128; e++) a += fsh[e] * fcw[t * 128 + e];
        out[b * 2 + t] = a;
    }
}

// ---------------------------------------------------------------------------
extern "C" void kernel_launch(void* const* d_in, const int* in_sizes, int n_in,
                              void* d_out, int out_size)
{
    const float* feat    = (const float*)d_in[0];
    const float* conv_w  = (const float*)d_in[1];
    const float* conv_b  = (const float*)d_in[2];
    const float* pos_emb = (const float*)d_in[3];
    const float* cls_tok = (const float*)d_in[4];
    const float* ln1_s   = (const float*)d_in[5];
    const float* ln1_b   = (const float*)d_in[6];
    const float* qkv_w   = (const float*)d_in[7];
    const float* qkv_b   = (const float*)d_in[8];
    const float* proj_w  = (const float*)d_in[9];
    const float* proj_b  = (const float*)d_in[10];
    const float* ln2_s   = (const float*)d_in[11];
    const float* ln2_b   = (const float*)d_in[12];
    const float* ffn1_w  = (const float*)d_in[13];
    const float* ffn1_b  = (const float*)d_in[14];
    const float* ffn2_w  = (const float*)d_in[15];
    const float* ffn2_b  = (const float*)d_in[16];
    const float* fn_s    = (const float*)d_in[17];
    const float* fn_b    = (const float*)d_in[18];
    const float* fc_w    = (const float*)d_in[19];
    const float* fc_b    = (const float*)d_in[20];
    float* out = (float*)d_out;

    float *px, *ph, *pq, *po, *pf, *wq, *wp, *w1, *w2;
    cudaGetSymbolAddress((void**)&px, g_x);
    cudaGetSymbolAddress((void**)&ph, g_h);
    cudaGetSymbolAddress((void**)&pq, g_qkv);
    cudaGetSymbolAddress((void**)&po, g_o);
    cudaGetSymbolAddress((void**)&pf, g_ffn);
    cudaGetSymbolAddress((void**)&wq, g_wqkv);
    cudaGetSymbolAddress((void**)&wp, g_wproj);
    cudaGetSymbolAddress((void**)&w1, g_wf1);
    cudaGetSymbolAddress((void**)&w2, g_wf2);

    cudaFuncSetAttribute(attn_kernel, cudaFuncAttributeMaxDynamicSharedMemorySize, ATT_SMEM);

    // weight pre-conversion (tf32 rounding, once per replay, ~5us)
    {
        int nq = 12 * 384 * 128 / 4, np = 12 * 128 * 128 / 4;
        int n1 = 12 * 512 * 128 / 4, n2 = 12 * 128 * 512 / 4;
        cvtw_kernel<<<(nq + 255) / 256, 256>>>((const float4*)qkv_w, (float4*)wq, nq);
        cvtw_kernel<<<(np + 255) / 256, 256>>>((const float4*)proj_w, (float4*)wp, np);
        cvtw_kernel<<<(n1 + 255) / 256, 256>>>((const float4*)ffn1_w, (float4*)w1, n1);
        cvtw_kernel<<<(n2 + 255) / 256, 256>>>((const float4*)ffn2_w, (float4*)w2, n2);
    }

    cls_kernel<<<BATCH, 128>>>(cls_tok, pos_emb, px);
    conv_mma<<<dim3(1, 256), 256>>>(feat, conv_w, conv_b, pos_emb, px);
    ln_kernel<<<TOKENS / 8, 256>>>(px, ph, ln1_s, ln1_b, 1e-5f);

    for (int l = 0; l < 12; l++) {
        gemm_mma<0><<<dim3(3, 257), 256>>>(
            ph, wq + (size_t)l * 384 * 128, nullptr, nullptr,
            qkv_b + l * 384, nullptr, pq, nullptr, TOKENS, 384, 128);
        attn_kernel<<<dim3(BATCH, 4, 3), 256, ATT_SMEM>>>(pq, po);
        gemm_mma<3><<<dim3(1, 257), 256>>>(
            po, wp + (size_t)l * 128 * 128, ln2_s + l * 128, ln2_b + l * 128,
            proj_b + l * 128, px, px, ph, TOKENS, 128, 128);
        gemm_mma<1><<<dim3(4, 257), 256>>>(
            ph, w1 + (size_t)l * 512 * 128, nullptr, nullptr,
            ffn1_b + l * 512, nullptr, pf, nullptr, TOKENS, 512, 128);
        if (l < 11) {
            gemm_mma<3><<<dim3(1, 257), 256>>>(
                pf, w2 + (size_t)l * 128 * 512,
                ln1_s + (l + 1) * 128, ln1_b + (l + 1) * 128,
                ffn2_b + l * 128, px, px, ph, TOKENS, 128, 512);
        } else {
            gemm_mma<2><<<dim3(1, 257), 256>>>(
                pf, w2 + (size_t)l * 128 * 512, nullptr, nullptr,
                ffn2_b + l * 128, px, px, nullptr, TOKENS, 128, 512);
        }
    }

    head_kernel<<<BATCH, 128>>>(px, fn_s, fn_b, fc_w, fc_b, out);
}

// round 11
// speedup vs baseline: 2.0199x; 1.0665x over previous
#include <cuda_runtime.h>
#include <math.h>
#include <stdint.h>

// ---------------------------------------------------------------------------
// Shapes (fixed): L=12, E=128, H=4, D=32, F=512, B=64, CIN=256, N=257
// Tokens T = B*N = 16448 = 64 * 257
// ---------------------------------------------------------------------------
#define TOKENS 16448
#define NTOK 257
#define BATCH 64

// scratch (device globals; allocation is forbidden)
__device__ float g_x  [TOKENS * 128];   // residual stream (full fp32)
__device__ float g_h  [TOKENS * 128];   // post-LN (tf32-rounded bits)
__device__ float g_qkv[TOKENS * 384];   // qkv (tf32-rounded bits)
__device__ float g_o  [TOKENS * 128];   // attention out (tf32-rounded bits)
__device__ float g_ffn[TOKENS * 512];   // ffn hidden (tf32-rounded bits)
// tf32-pre-rounded weights
__device__ float g_wqkv[12 * 384 * 128];
__device__ float g_wproj[12 * 128 * 128];
__device__ float g_wf1 [12 * 512 * 128];
__device__ float g_wf2 [12 * 128 * 512];

__device__ __forceinline__ float warp_sum(float v) {
    #pragma unroll
    for (int o = 16; o; o >>= 1) v += __shfl_xor_sync(0xffffffffu, v, o);
    return v;
}

__device__ __forceinline__ uint32_t to_tf32(float f) {
    uint32_t u;
    asm("cvt.rna.tf32.f32 %0, %1;" : "=r"(u) : "f"(f));
    return u;
}
__device__ __forceinline__ float tf32f(float f) {
    return __uint_as_float(to_tf32(f));
}

// D = A(16x8, row) * B(8x8, col) + D, tf32 in, f32 accum
__device__ __forceinline__ void mma_tf32(float c[4], const uint32_t a[4], const uint32_t b[2]) {
    asm volatile(
        "mma.sync.aligned.m16n8k8.row.col.f32.tf32.tf32.f32 "
        "{%0,%1,%2,%3}, {%4,%5,%6,%7}, {%8,%9}, {%0,%1,%2,%3};"
        : "+f"(c[0]), "+f"(c[1]), "+f"(c[2]), "+f"(c[3])
        : "r"(a[0]), "r"(a[1]), "r"(a[2]), "r"(a[3]), "r"(b[0]), "r"(b[1]));
}

// ldmatrix x4: four 8x8 b16 tiles; used to fetch tf32 fragments in one shot.
__device__ __forceinline__ void ldsm4(uint32_t& r0, uint32_t& r1,
                                      uint32_t& r2, uint32_t& r3, const void* p) {
    uint32_t a = (uint32_t)__cvta_generic_to_shared(p);
    asm volatile("ldmatrix.sync.aligned.m8n8.x4.shared.b16 {%0,%1,%2,%3}, [%4];"
        : "=r"(r0), "=r"(r1), "=r"(r2), "=r"(r3) : "r"(a));
}

__device__ __forceinline__ void cp16(void* smem, const void* g) {
    uint32_t s = (uint32_t)__cvta_generic_to_shared(smem);
    asm volatile("cp.async.cg.shared.global [%0], [%1], 16;" :: "r"(s), "l"(g));
}
__device__ __forceinline__ void cp_commit() {
    asm volatile("cp.async.commit_group;");
}
__device__ __forceinline__ void cp_wait0() {
    asm volatile("cp.async.wait_group 0;");
}

#define SK 36   // padded k-stride: conflict-free LDSM (36 mod 32 = 4)

// ---------------------------------------------------------------------------
// Weight pre-conversion: tf32-round fp32 weights (float4 grid-stride).
// ---------------------------------------------------------------------------
__global__ __launch_bounds__(256)
void cvtw_kernel(const float4* __restrict__ src, float4* __restrict__ dst, int n4)
{
    int i = blockIdx.x * blockDim.x + threadIdx.x;
    if (i < n4) {
        float4 v = src[i];
        v.x = tf32f(v.x); v.y = tf32f(v.y); v.z = tf32f(v.z); v.w = tf32f(v.w);
        dst[i] = v;
    }
}

// ---------------------------------------------------------------------------
// cp.async double-buffered tensor-core GEMM; operands PRE-ROUNDED tf32 bits;
// fragments fetched via ldmatrix (8 LDSM per chunk instead of 64 LDS).
// MODE 0: +bias (out tf32)   MODE 1: gelu(+bias) (out tf32)
// MODE 2: +bias+res (out fp32)
// MODE 3: +bias+res -> C fp32, AND LN(C) -> Hout tf32 (N==128)
// ---------------------------------------------------------------------------
template <int MODE>
__global__ __launch_bounds__(256)
void gemm_mma(const float* __restrict__ A, const float* __restrict__ W,
              const float* __restrict__ lns, const float* __restrict__ lnb,
              const float* __restrict__ bias, const float* __restrict__ res,
              float* __restrict__ C, float* __restrict__ Hout,
              int M, int N, int K)
{
    __shared__ float As[2][64][SK];
    __shared__ float Bs[2][128][SK];
    const int tid = threadIdx.x;
    const int lane = tid & 31, wid = tid >> 5;
    const int warp_m = wid >> 2, warp_n = wid & 3;
    const int m0 = blockIdx.y * 64, n0 = blockIdx.x * 128;
    const int g = lane >> 2, cl = lane & 3;

    // ldmatrix per-lane source coordinates
    const int a_row = warp_m * 32 + (lane & 15);
    const int a_col = (lane >> 4) << 2;                        // 0 | 4
    const int b_row = warp_n * 32 + (lane & 7) + ((lane & 16) >> 1);
    const int b_col = ((lane >> 3) & 1) << 2;                  // 0 | 4

    const int arow = tid >> 3, ac4 = (tid & 7) * 4;
    const float* Ap0 = A + (size_t)(m0 + arow) * K + ac4;
    const float* Ap1 = A + (size_t)(m0 + arow + 32) * K + ac4;
    const float* Wp0 = W + (size_t)(n0 + arow) * K + ac4;
    const float* Wp1 = W + (size_t)(n0 + arow + 32) * K + ac4;
    const float* Wp2 = W + (size_t)(n0 + arow + 64) * K + ac4;
    const float* Wp3 = W + (size_t)(n0 + arow + 96) * K + ac4;

    const int nc = K >> 5;

    {
        cp16(&As[0][arow][ac4], Ap0);
        cp16(&As[0][arow + 32][ac4], Ap1);
        cp16(&Bs[0][arow][ac4], Wp0);
        cp16(&Bs[0][arow + 32][ac4], Wp1);
        cp16(&Bs[0][arow + 64][ac4], Wp2);
        cp16(&Bs[0][arow + 96][ac4], Wp3);
        cp_commit();
    }

    float acc[2][4][4];
    #pragma unroll
    for (int i = 0; i < 2; i++)
        #pragma unroll
        for (int j = 0; j < 4; j++)
            #pragma unroll
            for (int r = 0; r < 4; r++) acc[i][j][r] = 0.f;

    for (int c = 0; c < nc; c++) {
        const int buf = c & 1;
        cp_wait0();
        __syncthreads();

        if (c + 1 < nc) {
            const int nb = buf ^ 1, off = (c + 1) * 32;
            cp16(&As[nb][arow][ac4], Ap0 + off);
            cp16(&As[nb][arow + 32][ac4], Ap1 + off);
            cp16(&Bs[nb][arow][ac4], Wp0 + off);
            cp16(&Bs[nb][arow + 32][ac4], Wp1 + off);
            cp16(&Bs[nb][arow + 64][ac4], Wp2 + off);
            cp16(&Bs[nb][arow + 96][ac4], Wp3 + off);
            cp_commit();
        }

        #pragma unroll
        for (int ks = 0; ks < 4; ks++) {
            const int kk = ks * 8;
            uint32_t af[2][4], bf[4][2];
            ldsm4(af[0][0], af[0][1], af[0][2], af[0][3],
                  &As[buf][a_row][kk + a_col]);
            ldsm4(af[1][0], af[1][1], af[1][2], af[1][3],
                  &As[buf][a_row + 16][kk + a_col]);
            ldsm4(bf[0][0], bf[0][1], bf[1][0], bf[1][1],
                  &Bs[buf][b_row][kk + b_col]);
            ldsm4(bf[2][0], bf[2][1], bf[3][0], bf[3][1],
                  &Bs[buf][b_row + 16][kk + b_col]);
            #pragma unroll
            for (int mt = 0; mt < 2; mt++)
                #pragma unroll
                for (int nt = 0; nt < 4; nt++)
                    mma_tf32(acc[mt][nt], af[mt], bf[nt]);
        }
    }

    #pragma unroll
    for (int mt = 0; mt < 2; mt++) {
        int r = m0 + warp_m * 32 + mt * 16 + g;
        #pragma unroll
        for (int nt = 0; nt < 4; nt++) {
            int n = n0 + warp_n * 32 + nt * 8 + cl * 2;
            float b0 = bias[n], b1 = bias[n + 1];
            acc[mt][nt][0] += b0; acc[mt][nt][1] += b1;
            acc[mt][nt][2] += b0; acc[mt][nt][3] += b1;
            if (MODE == 1) {
                #pragma unroll
                for (int i = 0; i < 4; i++)
                    acc[mt][nt][i] = acc[mt][nt][i] * 0.5f *
                        (1.0f + erff(acc[mt][nt][i] * 0.70710678118654752f));
            }
            if (MODE >= 2) {
                float2 r0 = *(const float2*)(res + (size_t)r * N + n);
                float2 r1 = *(const float2*)(res + (size_t)(r + 8) * N + n);
                acc[mt][nt][0] += r0.x; acc[mt][nt][1] += r0.y;
                acc[mt][nt][2] += r1.x; acc[mt][nt][3] += r1.y;
            }
        }
    }

    if (MODE == 3) {
        __syncthreads();
        float* rsum = (float*)As;            // [64][17]
        float* rsq  = rsum + 64 * 17;        // [64][17]
        float* st   = rsq + 64 * 17;         // [64][2]
        const int slot = warp_n * 4 + cl;
        #pragma unroll
        for (int mt = 0; mt < 2; mt++)
            #pragma unroll
            for (int rh = 0; rh < 2; rh++) {
                int lr = warp_m * 32 + mt * 16 + rh * 8 + g;
                float s = 0.f, q = 0.f;
                #pragma unroll
                for (int nt = 0; nt < 4; nt++) {
                    float v0 = acc[mt][nt][2 * rh], v1 = acc[mt][nt][2 * rh + 1];
                    s += v0 + v1; q += v0 * v0 + v1 * v1;
                }
                rsum[lr * 17 + slot] = s;
                rsq[lr * 17 + slot] = q;
            }
        __syncthreads();
        if (tid < 64) {
            float s = 0.f, q = 0.f;
            #pragma unroll
            for (int i = 0; i < 16; i++) {
                s += rsum[tid * 17 + i];
                q += rsq[tid * 17 + i];
            }
            float mean = s * (1.f / 128.f);
            float var = q * (1.f / 128.f) - mean * mean;
            st[tid * 2]     = mean;
            st[tid * 2 + 1] = rsqrtf(var + 1e-5f);
        }
        __syncthreads();
        #pragma unroll
        for (int mt = 0; mt < 2; mt++) {
            #pragma unroll
            for (int rh = 0; rh < 2; rh++) {
                int lr = warp_m * 32 + mt * 16 + rh * 8 + g;
                int r = m0 + lr;
                float mean = st[lr * 2], rstd = st[lr * 2 + 1];
                #pragma unroll
                for (int nt = 0; nt < 4; nt++) {
                    int n = n0 + warp_n * 32 + nt * 8 + cl * 2;
                    float v0 = acc[mt][nt][2 * rh], v1 = acc[mt][nt][2 * rh + 1];
                    *(float2*)(C + (size_t)r * N + n) = make_float2(v0, v1);
                    float h0 = tf32f((v0 - mean) * rstd * lns[n] + lnb[n]);
                    float h1 = tf32f((v1 - mean) * rstd * lns[n + 1] + lnb[n + 1]);
                    *(float2*)(Hout + (size_t)r * N + n) = make_float2(h0, h1);
                }
            }
        }
    } else {
        #pragma unroll
        for (int mt = 0; mt < 2; mt++) {
            int r = m0 + warp_m * 32 + mt * 16 + g;
            #pragma unroll
            for (int nt = 0; nt < 4; nt++) {
                int n = n0 + warp_n * 32 + nt * 8 + cl * 2;
                float v0 = acc[mt][nt][0], v1 = acc[mt][nt][1];
                float v2 = acc[mt][nt][2], v3 = acc[mt][nt][3];
                if (MODE <= 1) {
                    v0 = tf32f(v0); v1 = tf32f(v1);
                    v2 = tf32f(v2); v3 = tf32f(v3);
                }
                *(float2*)(C + (size_t)r * N + n)       = make_float2(v0, v1);
                *(float2*)(C + (size_t)(r + 8) * N + n) = make_float2(v2, v3);
            }
        }
    }
}

// ---------------------------------------------------------------------------
// Conv 3x3 s2 p1 as implicit GEMM on tensor cores: M=16384, N=128, K=2304.
// (unchanged; ~100us once)
// ---------------------------------------------------------------------------
__global__ __launch_bounds__(256)
void conv_mma(const float* __restrict__ feat, const float* __restrict__ W,
              const float* __restrict__ cb, const float* __restrict__ pos,
              float* __restrict__ x)
{
    __shared__ uint32_t As[64][SK];
    __shared__ uint32_t Bs[128][SK];
    const int K = 2304;
    const int tid = threadIdx.x;
    const int lane = tid & 31, wid = tid >> 5;
    const int warp_m = wid >> 2, warp_n = wid & 3;
    const int m0 = blockIdx.y * 64;
    const int g = lane >> 2, cl = lane & 3;

    float acc[2][4][4];
    #pragma unroll
    for (int i = 0; i < 2; i++)
        #pragma unroll
        for (int j = 0; j < 4; j++)
            #pragma unroll
            for (int r = 0; r < 4; r++) acc[i][j][r] = 0.f;

    for (int k0 = 0; k0 < K; k0 += 32) {
        #pragma unroll
        for (int it = 0; it < 8; it++) {
            int e = tid + it * 256;
            int ml = e >> 5, kl = e & 31;
            int m = m0 + ml;
            int k = k0 + kl;
            int b = m >> 8, p = m & 255;
            int y = p >> 4, xx = p & 15;
            int c = k / 9, rr = k - c * 9;
            int ky = rr / 3, kx = rr - ky * 3;
            int iy = y * 2 - 1 + ky;
            int ix = xx * 2 - 1 + kx;
            float v = 0.f;
            if (iy >= 0 && iy < 32 && ix >= 0 && ix < 32)
                v = feat[(((size_t)b * 256 + c) * 32 + iy) * 32 + ix];
            As[ml][kl] = to_tf32(v);
        }
        #pragma unroll
        for (int it = 0; it < 4; it++) {
            int e = tid + it * 256;
            int row = e >> 3, c4 = (e & 7) * 4;
            float4 v = *(const float4*)(W + (size_t)row * K + k0 + c4);
            Bs[row][c4 + 0] = to_tf32(v.x);
            Bs[row][c4 + 1] = to_tf32(v.y);
            Bs[row][c4 + 2] = to_tf32(v.z);
            Bs[row][c4 + 3] = to_tf32(v.w);
        }
        __syncthreads();

        #pragma unroll
        for (int ks = 0; ks < 4; ks++) {
            const int kk = ks * 8;
            uint32_t af[2][4], bf[4][2];
            #pragma unroll
            for (int mt = 0; mt < 2; mt++) {
                int r = warp_m * 32 + mt * 16 + g;
                af[mt][0] = As[r][kk + cl];
                af[mt][1] = As[r + 8][kk + cl];
                af[mt][2] = As[r][kk + 4 + cl];
                af[mt][3] = As[r + 8][kk + 4 + cl];
            }
            #pragma unroll
            for (int nt = 0; nt < 4; nt++) {
                int n = warp_n * 32 + nt * 8 + g;
                bf[nt][0] = Bs[n][kk + cl];
                bf[nt][1] = Bs[n][kk + 4 + cl];
            }
            #pragma unroll
            for (int mt = 0; mt < 2; mt++)
                #pragma unroll
                for (int nt = 0; nt < 4; nt++)
                    mma_tf32(acc[mt][nt], af[mt], bf[nt]);
        }
        __syncthreads();
    }

    #pragma unroll
    for (int mt = 0; mt < 2; mt++) {
        int r = m0 + warp_m * 32 + mt * 16 + g;
        #pragma unroll
        for (int rr = 0; rr < 2; rr++) {
            int m = r + rr * 8;
            int b = m >> 8, p = m & 255;
            float* dst = x + ((size_t)b * NTOK + p + 1) * 128;
            const float* pp = pos + (size_t)(p + 1) * 128;
            #pragma unroll
            for (int nt = 0; nt < 4; nt++) {
                int n = warp_n * 32 + nt * 8 + cl * 2;
                float v0 = acc[mt][nt][rr * 2 + 0] + cb[n] + pp[n];
                float v1 = acc[mt][nt][rr * 2 + 1] + cb[n + 1] + pp[n + 1];
                *(float2*)(dst + n) = make_float2(v0, v1);
            }
        }
    }
}

// cls token rows: x[b,0,:] = cls + pos[0]
__global__ void cls_kernel(const float* __restrict__ cls,
                           const float* __restrict__ pos, float* __restrict__ x)
{
    int b = blockIdx.x, e = threadIdx.x;
    x[(size_t)b * NTOK * 128 + e] = cls[e] + pos[e];
}

// ---------------------------------------------------------------------------
// LayerNorm over E=128 (used once, before layer 0). Output tf32-rounded.
// ---------------------------------------------------------------------------
__global__ __launch_bounds__(256)
void ln_kernel(const float* __restrict__ x, float* __restrict__ h,
               const float* __restrict__ s, const float* __restrict__ b, float eps)
{
    int tok = blockIdx.x * 8 + (threadIdx.x >> 5);
    int lane = threadIdx.x & 31;
    if (tok >= TOKENS) return;
    const float4* xr = (const float4*)(x + (size_t)tok * 128);
    float4 v = xr[lane];
    float mean = warp_sum(v.x + v.y + v.z + v.w) * (1.f / 128.f);
    float dx = v.x - mean, dy = v.y - mean, dz = v.z - mean, dw = v.w - mean;
    float var = warp_sum(dx * dx + dy * dy + dz * dz + dw * dw) * (1.f / 128.f);
    float rstd = rsqrtf(var + eps);
    float4 sv = ((const float4*)s)[lane];
    float4 bv = ((const float4*)b)[lane];
    float4 o;
    o.x = tf32f(dx * rstd * sv.x + bv.x);
    o.y = tf32f(dy * rstd * sv.y + bv.y);
    o.z = tf32f(dz * rstd * sv.z + bv.z);
    o.w = tf32f(dw * rstd * sv.w + bv.w);
    ((float4*)(h + (size_t)tok * 128))[lane] = o;
}

// ---------------------------------------------------------------------------
// Full tensor-core attention; fragments via ldmatrix. Ps/Vt row stride 268
// (268 mod 32 = 12 -> conflict-free LDSM, rows 16B-aligned).
// ---------------------------------------------------------------------------
#define VSTR 268
#define OFF_VT 9252             // u32 [32][268]
#define OFF_QT 17828            // u32 [32][36]
#define OFF_PS 18980            // f32/u32 [32][268]; also [8][32][33] partials
#define OFF_INV 27556           // f32 [32]
#define OFF_P256 27588          // f32 [32]
#define ATT_SMEM ((27620 + 28) * 4)   // 110592 B

__global__ __launch_bounds__(256)
void attn_kernel(const float* __restrict__ qkv, float* __restrict__ o)
{
    extern __shared__ float sm[];
    uint32_t* Kt = (uint32_t*)sm;               // [257][36]
    uint32_t* Vt = (uint32_t*)(sm + OFF_VT);    // [32][268] V^T
    uint32_t* Qt = (uint32_t*)(sm + OFF_QT);    // [32][36]
    float*    Ps = sm + OFF_PS;                 // [32][268] S/P, then partials
    uint32_t* Pu = (uint32_t*)Ps;
    float*    invs = sm + OFF_INV;              // [32]
    float*    p256s = sm + OFF_P256;            // [32]

    int b = blockIdx.x, h = blockIdx.y, z = blockIdx.z;
    int tid = threadIdx.x, w = tid >> 5, lane = tid & 31;
    const int g = lane >> 2, cl = lane & 3;
    const float* base = qkv + (size_t)b * NTOK * 384 + h * 32;

    // ldmatrix per-lane coordinates (same mapping as gemm)
    const int la_row = lane & 15;                       // A-fragment row
    const int la_col = (lane >> 4) << 2;                // 0 | 4
    const int lb_row = (lane & 7) + ((lane & 16) >> 1); // B-fragment row
    const int lb_col = ((lane >> 3) & 1) << 2;          // 0 | 4

    for (int i = tid; i < 257 * 32; i += 256) {
        int m = i >> 5, d = i & 31;
        const float* p = base + (size_t)m * 384;
        Kt[m * 36 + d] = __float_as_uint(p[128 + d]);
        Vt[d * VSTR + m] = __float_as_uint(p[256 + d]);
    }
    __syncthreads();

    const float scale = 0.17677669529663687f;  // 1/sqrt(32)
    const float k256 = __uint_as_float(Kt[256 * 36 + lane]);

    for (int t = z * 3; t < z * 3 + 3; t++) {
        if (t * 32 >= NTOK) break;

        {
            int row = tid >> 3, d4 = (tid & 7) * 4;
            int q = t * 32 + row;
            float4 v = make_float4(0.f, 0.f, 0.f, 0.f);
            if (q < NTOK) v = *(const float4*)(base + (size_t)q * 384 + d4);
            Qt[row * 36 + d4 + 0] = __float_as_uint(v.x);
            Qt[row * 36 + d4 + 1] = __float_as_uint(v.y);
            Qt[row * 36 + d4 + 2] = __float_as_uint(v.z);
            Qt[row * 36 + d4 + 3] = __float_as_uint(v.w);
        }
        __syncthreads();

        // ---- stage 1: S(32q x 32k) per warp for keys [32w, 32w+32) ----
        {
            float s[2][4][4];
            #pragma unroll
            for (int mt = 0; mt < 2; mt++)
                #pragma unroll
                for (int nt = 0; nt < 4; nt++)
                    #pragma unroll
                    for (int r = 0; r < 4; r++) s[mt][nt][r] = 0.f;
            #pragma unroll
            for (int ks = 0; ks < 4; ks++) {
                const int kk = ks * 8;
                uint32_t aq[2][4], bk[4][2];
                ldsm4(aq[0][0], aq[0][1], aq[0][2], aq[0][3],
                      &Qt[la_row * 36 + kk + la_col]);
                ldsm4(aq[1][0], aq[1][1], aq[1][2], aq[1][3],
                      &Qt[(la_row + 16) * 36 + kk + la_col]);
                ldsm4(bk[0][0], bk[0][1], bk[1][0], bk[1][1],
                      &Kt[(w * 32 + lb_row) * 36 + kk + lb_col]);
                ldsm4(bk[2][0], bk[2][1], bk[3][0], bk[3][1],
                      &Kt[(w * 32 + lb_row + 16) * 36 + kk + lb_col]);
                #pragma unroll
                for (int mt = 0; mt < 2; mt++)
                    #pragma unroll
                    for (int nt = 0; nt < 4; nt++)
                        mma_tf32(s[mt][nt], aq[mt], bk[nt]);
            }
            #pragma unroll
            for (int mt = 0; mt < 2; mt++) {
                int row = mt * 16 + g;
                #pragma unroll
                for (int nt = 0; nt < 4; nt++) {
                    int col = w * 32 + nt * 8 + 2 * cl;
                    Ps[row * VSTR + col]           = s[mt][nt][0];
                    Ps[row * VSTR + col + 1]       = s[mt][nt][1];
                    Ps[(row + 8) * VSTR + col]     = s[mt][nt][2];
                    Ps[(row + 8) * VSTR + col + 1] = s[mt][nt][3];
                }
            }
        }
        __syncthreads();

        // ---- stage 2: softmax-lite on own 4 query rows ----
        #pragma unroll
        for (int qq = 0; qq < 4; qq++) {
            int qloc = w * 4 + qq;
            int qglob = t * 32 + qloc;
            float qd = (qglob < NTOK) ? base[(size_t)qglob * 384 + lane] : 0.f;
            float s256 = warp_sum(qd * k256) * scale;
            float p[8];
            float ls = 0.f;
            #pragma unroll
            for (int j = 0; j < 8; j++) {
                p[j] = __expf(Ps[qloc * VSTR + lane + 32 * j] * scale);
                ls += p[j];
            }
            float p256 = __expf(s256);
            ls = warp_sum(ls) + p256;
            #pragma unroll
            for (int j = 0; j < 8; j++)
                Pu[qloc * VSTR + lane + 32 * j] = to_tf32(p[j]);
            if (lane == 0) {
                invs[qloc] = 1.f / ls;
                p256s[qloc] = p256;
            }
        }
        __syncthreads();

        // ---- stage 3: partial O(32q x 32d) for keys [32w, 32w+32) ----
        float pacc[2][4][4];
        #pragma unroll
        for (int mt = 0; mt < 2; mt++)
            #pragma unroll
            for (int nt = 0; nt < 4; nt++)
                #pragma unroll
                for (int r = 0; r < 4; r++) pacc[mt][nt][r] = 0.f;
        {
            const int k0 = w * 32;
            #pragma unroll
            for (int ks = 0; ks < 4; ks++) {
                const int kk = k0 + ks * 8;
                uint32_t ap[2][4], bv[4][2];
                ldsm4(ap[0][0], ap[0][1], ap[0][2], ap[0][3],
                      &Pu[la_row * VSTR + kk + la_col]);
                ldsm4(ap[1][0], ap[1][1], ap[1][2], ap[1][3],
                      &Pu[(la_row + 16) * VSTR + kk + la_col]);
                ldsm4(bv[0][0], bv[0][1], bv[1][0], bv[1][1],
                      &Vt[lb_row * VSTR + kk + lb_col]);
                ldsm4(bv[2][0], bv[2][1], bv[3][0], bv[3][1],
                      &Vt[(lb_row + 16) * VSTR + kk + lb_col]);
                #pragma unroll
                for (int mt = 0; mt < 2; mt++)
                    #pragma unroll
                    for (int nt = 0; nt < 4; nt++)
                        mma_tf32(pacc[mt][nt], ap[mt], bv[nt]);
            }
        }
        __syncthreads();

        // ---- stage 4a: write partials [8][32][33] into Ps region ----
        {
            float* Pr = Ps + w * 1056;
            #pragma unroll
            for (int mt = 0; mt < 2; mt++) {
                int row = mt * 16 + g;
                #pragma unroll
                for (int nt = 0; nt < 4; nt++) {
                    int d0 = nt * 8 + 2 * cl;
                    Pr[row * 33 + d0]           = pacc[mt][nt][0];
                    Pr[row * 33 + d0 + 1]       = pacc[mt][nt][1];
                    Pr[(row + 8) * 33 + d0]     = pacc[mt][nt][2];
                    Pr[(row + 8) * 33 + d0 + 1] = pacc[mt][nt][3];
                }
            }
        }
        __syncthreads();

        // ---- stage 4b: reduce + key-256 + normalize, tf32 store ----
        {
            int q = tid >> 3;
            int d0 = (tid & 7) * 4;
            int qglob = t * 32 + q;
            float r0 = 0.f, r1 = 0.f, r2 = 0.f, r3 = 0.f;
            #pragma unroll
            for (int ww = 0; ww < 8; ww++) {
                const float* Pr = Ps + ww * 1056 + q * 33 + d0;
                r0 += Pr[0]; r1 += Pr[1]; r2 += Pr[2]; r3 += Pr[3];
            }
            float pk = p256s[q];
            r0 += pk * __uint_as_float(Vt[(d0 + 0) * VSTR + 256]);
            r1 += pk * __uint_as_float(Vt[(d0 + 1) * VSTR + 256]);
            r2 += pk * __uint_as_float(Vt[(d0 + 2) * VSTR + 256]);
            r3 += pk * __uint_as_float(Vt[(d0 + 3) * VSTR + 256]);
            float inv = invs[q];
            if (qglob < NTOK) {
                float4 res = make_float4(tf32f(r0 * inv), tf32f(r1 * inv),
                                         tf32f(r2 * inv), tf32f(r3 * inv));
                *(float4*)(o + ((size_t)b * NTOK + qglob) * 128 + h * 32 + d0) = res;
            }
        }
        __syncthreads();
    }
}

// ---------------------------------------------------------------------------
// Head: final LN (eps 1e-6) on token 0 of each batch, out_feat + fc.
// ---------------------------------------------------------------------------
__global__ __launch_bounds__(128)
void head_kernel(const float* __restrict__ x, const float* __restrict__ fns,
                 const float* __restrict__ fnb, const float* __restrict__ fcw,
                 const float* __restrict__ fcb, float* __restrict__ out)
{
    __shared__ float red[4];
    __shared__ float fsh[128];
    int b = blockIdx.x, t = threadIdx.x, w = t >> 5, lane = t & 31;
    float v = x[(size_t)b * NTOK * 128 + t];

    float s = warp_sum(v);
    if (lane == 0) red[w] = s;
    __syncthreads();
    float mean = (red[0] + red[1] + red[2] + red[3]) * (1.f / 128.f);
    __syncthreads();
    float d = v - mean;
    float sq = warp_sum(d * d);
    if (lane == 0) red[w] = sq;
    __syncthreads();
    float var = (red[0] + red[1] + red[2] + red[3]) * (1.f / 128.f);
    float rstd = rsqrtf(var + 1e-6f);
    float f = d * rstd * fns[t] + fnb[t];
    out[128 + (size_t)b * 128 + t] = f;
    fsh[t] = f;
    __syncthreads();
    if (t < 2) {
        float a = fcb[t];
        for (int e = 0; e < 128; e++) a += fsh[e] * fcw[t * 128 + e];
        out[b * 2 + t] = a;
    }
}

// ---------------------------------------------------------------------------
extern "C" void kernel_launch(void* const* d_in, const int* in_sizes, int n_in,
                              void* d_out, int out_size)
{
    const float* feat    = (const float*)d_in[0];
    const float* conv_w  = (const float*)d_in[1];
    const float* conv_b  = (const float*)d_in[2];
    const float* pos_emb = (const float*)d_in[3];
    const float* cls_tok = (const float*)d_in[4];
    const float* ln1_s   = (const float*)d_in[5];
    const float* ln1_b   = (const float*)d_in[6];
    const float* qkv_w   = (const float*)d_in[7];
    const float* qkv_b   = (const float*)d_in[8];
    const float* proj_w  = (const float*)d_in[9];
    const float* proj_b  = (const float*)d_in[10];
    const float* ln2_s   = (const float*)d_in[11];
    const float* ln2_b   = (const float*)d_in[12];
    const float* ffn1_w  = (const float*)d_in[13];
    const float* ffn1_b  = (const float*)d_in[14];
    const float* ffn2_w  = (const float*)d_in[15];
    const float* ffn2_b  = (const float*)d_in[16];
    const float* fn_s    = (const float*)d_in[17];
    const float* fn_b    = (const float*)d_in[18];
    const float* fc_w    = (const float*)d_in[19];
    const float* fc_b    = (const float*)d_in[20];
    float* out = (float*)d_out;

    float *px, *ph, *pq, *po, *pf, *wq, *wp, *w1, *w2;
    cudaGetSymbolAddress((void**)&px, g_x);
    cudaGetSymbolAddress((void**)&ph, g_h);
    cudaGetSymbolAddress((void**)&pq, g_qkv);
    cudaGetSymbolAddress((void**)&po, g_o);
    cudaGetSymbolAddress((void**)&pf, g_ffn);
    cudaGetSymbolAddress((void**)&wq, g_wqkv);
    cudaGetSymbolAddress((void**)&wp, g_wproj);
    cudaGetSymbolAddress((void**)&w1, g_wf1);
    cudaGetSymbolAddress((void**)&w2, g_wf2);

    cudaFuncSetAttribute(attn_kernel, cudaFuncAttributeMaxDynamicSharedMemorySize, ATT_SMEM);

    // weight pre-conversion (tf32 rounding, ~5us)
    {
        int nq = 12 * 384 * 128 / 4, np = 12 * 128 * 128 / 4;
        int n1 = 12 * 512 * 128 / 4, n2 = 12 * 128 * 512 / 4;
        cvtw_kernel<<<(nq + 255) / 256, 256>>>((const float4*)qkv_w, (float4*)wq, nq);
        cvtw_kernel<<<(np + 255) / 256, 256>>>((const float4*)proj_w, (float4*)wp, np);
        cvtw_kernel<<<(n1 + 255) / 256, 256>>>((const float4*)ffn1_w, (float4*)w1, n1);
        cvtw_kernel<<<(n2 + 255) / 256, 256>>>((const float4*)ffn2_w, (float4*)w2, n2);
    }

    cls_kernel<<<BATCH, 128>>>(cls_tok, pos_emb, px);
    conv_mma<<<dim3(1, 256), 256>>>(feat, conv_w, conv_b, pos_emb, px);
    ln_kernel<<<TOKENS / 8, 256>>>(px, ph, ln1_s, ln1_b, 1e-5f);

    for (int l = 0; l < 12; l++) {
        gemm_mma<0><<<dim3(3, 257), 256>>>(
            ph, wq + (size_t)l * 384 * 128, nullptr, nullptr,
            qkv_b + l * 384, nullptr, pq, nullptr, TOKENS, 384, 128);
        attn_kernel<<<dim3(BATCH, 4, 3), 256, ATT_SMEM>>>(pq, po);
        gemm_mma<3><<<dim3(1, 257), 256>>>(
            po, wp + (size_t)l * 128 * 128, ln2_s + l * 128, ln2_b + l * 128,
            proj_b + l * 128, px, px, ph, TOKENS, 128, 128);
        gemm_mma<1><<<dim3(4, 257), 256>>>(
            ph, w1 + (size_t)l * 512 * 128, nullptr, nullptr,
            ffn1_b + l * 512, nullptr, pf, nullptr, TOKENS, 512, 128);
        if (l < 11) {
            gemm_mma<3><<<dim3(1, 257), 256>>>(
                pf, w2 + (size_t)l * 128 * 512,
                ln1_s + (l + 1) * 128, ln1_b + (l + 1) * 128,
                ffn2_b + l * 128, px, px, ph, TOKENS, 128, 512);
        } else {
            gemm_mma<2><<<dim3(1, 257), 256>>>(
                pf, w2 + (size_t)l * 128 * 512, nullptr, nullptr,
                ffn2_b + l * 128, px, px, nullptr, TOKENS, 128, 512);
        }
    }

    head_kernel<<<BATCH, 128>>>(px, fn_s, fn_b, fc_w, fc_b, out);
}

// round 13
// speedup vs baseline: 2.0406x; 1.0103x over previous
#include <cuda_runtime.h>
#include <math.h>
#include <stdint.h>

// ---------------------------------------------------------------------------
// Shapes (fixed): L=12, E=128, H=4, D=32, F=512, B=64, CIN=256, N=257
// Tokens T = B*N = 16448 = 64 * 257
// ---------------------------------------------------------------------------
#define TOKENS 16448
#define NTOK 257
#define BATCH 64

// scratch (device globals; allocation is forbidden)
__device__ float g_x  [TOKENS * 128];   // residual stream (full fp32)
__device__ float g_h  [TOKENS * 128];   // post-LN (tf32-rounded bits)
__device__ float g_qkv[TOKENS * 384];   // qkv (tf32-rounded bits)
__device__ float g_o  [TOKENS * 128];   // attention out (tf32-rounded bits)
__device__ float g_ffn[TOKENS * 512];   // ffn hidden (tf32-rounded bits)
// tf32-pre-rounded weights
__device__ float g_wqkv[12 * 384 * 128];
__device__ float g_wproj[12 * 128 * 128];
__device__ float g_wf1 [12 * 512 * 128];
__device__ float g_wf2 [12 * 128 * 512];

__device__ __forceinline__ float warp_sum(float v) {
    #pragma unroll
    for (int o = 16; o; o >>= 1) v += __shfl_xor_sync(0xffffffffu, v, o);
    return v;
}

__device__ __forceinline__ uint32_t to_tf32(float f) {
    uint32_t u;
    asm("cvt.rna.tf32.f32 %0, %1;" : "=r"(u) : "f"(f));
    return u;
}
__device__ __forceinline__ float tf32f(float f) {
    return __uint_as_float(to_tf32(f));
}

// D = A(16x8, row) * B(8x8, col) + D, tf32 in, f32 accum
__device__ __forceinline__ void mma_tf32(float c[4], const uint32_t a[4], const uint32_t b[2]) {
    asm volatile(
        "mma.sync.aligned.m16n8k8.row.col.f32.tf32.tf32.f32 "
        "{%0,%1,%2,%3}, {%4,%5,%6,%7}, {%8,%9}, {%0,%1,%2,%3};"
        : "+f"(c[0]), "+f"(c[1]), "+f"(c[2]), "+f"(c[3])
        : "r"(a[0]), "r"(a[1]), "r"(a[2]), "r"(a[3]), "r"(b[0]), "r"(b[1]));
}

// ldmatrix x4: four 8x8 b16 tiles; used to fetch tf32 fragments in one shot.
__device__ __forceinline__ void ldsm4(uint32_t& r0, uint32_t& r1,
                                      uint32_t& r2, uint32_t& r3, const void* p) {
    uint32_t a = (uint32_t)__cvta_generic_to_shared(p);
    asm volatile("ldmatrix.sync.aligned.m8n8.x4.shared.b16 {%0,%1,%2,%3}, [%4];"
        : "=r"(r0), "=r"(r1), "=r"(r2), "=r"(r3) : "r"(a));
}

__device__ __forceinline__ void cp16(void* smem, const void* g) {
    uint32_t s = (uint32_t)__cvta_generic_to_shared(smem);
    asm volatile("cp.async.cg.shared.global [%0], [%1], 16;" :: "r"(s), "l"(g));
}
__device__ __forceinline__ void cp_commit() {
    asm volatile("cp.async.commit_group;");
}
__device__ __forceinline__ void cp_wait0() {
    asm volatile("cp.async.wait_group 0;");
}

#define SK 36   // padded k-stride: conflict-free LDSM (36 mod 32 = 4)

// ---------------------------------------------------------------------------
// Weight pre-conversion: tf32-round fp32 weights (float4 grid-stride).
// ---------------------------------------------------------------------------
__global__ __launch_bounds__(256)
void cvtw_kernel(const float4* __restrict__ src, float4* __restrict__ dst, int n4)
{
    int i = blockIdx.x * blockDim.x + threadIdx.x;
    if (i < n4) {
        float4 v = src[i];
        v.x = tf32f(v.x); v.y = tf32f(v.y); v.z = tf32f(v.z); v.w = tf32f(v.w);
        dst[i] = v;
    }
}

// ---------------------------------------------------------------------------
// cp.async double-buffered tensor-core GEMM; operands PRE-ROUNDED tf32 bits;
// fragments via ldmatrix. __launch_bounds__(256,3): 3 CTA/SM (regs<=84,
// smem 55.3KB*3 = 166KB < 228KB).
// MODE 0: +bias (out tf32)   MODE 1: gelu(+bias) (out tf32)
// MODE 2: +bias+res (out fp32)
// MODE 3: +bias+res -> C fp32, AND LN(C) -> Hout tf32 (N==128)
// ---------------------------------------------------------------------------
template <int MODE>
__global__ __launch_bounds__(256, 3)
void gemm_mma(const float* __restrict__ A, const float* __restrict__ W,
              const float* __restrict__ lns, const float* __restrict__ lnb,
              const float* __restrict__ bias, const float* __restrict__ res,
              float* __restrict__ C, float* __restrict__ Hout,
              int M, int N, int K)
{
    __shared__ float As[2][64][SK];
    __shared__ float Bs[2][128][SK];
    const int tid = threadIdx.x;
    const int lane = tid & 31, wid = tid >> 5;
    const int warp_m = wid >> 2, warp_n = wid & 3;
    const int m0 = blockIdx.y * 64, n0 = blockIdx.x * 128;
    const int g = lane >> 2, cl = lane & 3;

    // ldmatrix per-lane source coordinates
    const int a_row = warp_m * 32 + (lane & 15);
    const int a_col = (lane >> 4) << 2;                        // 0 | 4
    const int b_row = warp_n * 32 + (lane & 7) + ((lane & 16) >> 1);
    const int b_col = ((lane >> 3) & 1) << 2;                  // 0 | 4

    const int arow = tid >> 3, ac4 = (tid & 7) * 4;
    const float* Ap0 = A + (size_t)(m0 + arow) * K + ac4;
    const float* Ap1 = A + (size_t)(m0 + arow + 32) * K + ac4;
    const float* Wp0 = W + (size_t)(n0 + arow) * K + ac4;
    const float* Wp1 = W + (size_t)(n0 + arow + 32) * K + ac4;
    const float* Wp2 = W + (size_t)(n0 + arow + 64) * K + ac4;
    const float* Wp3 = W + (size_t)(n0 + arow + 96) * K + ac4;

    const int nc = K >> 5;

    {
        cp16(&As[0][arow][ac4], Ap0);
        cp16(&As[0][arow + 32][ac4], Ap1);
        cp16(&Bs[0][arow][ac4], Wp0);
        cp16(&Bs[0][arow + 32][ac4], Wp1);
        cp16(&Bs[0][arow + 64][ac4], Wp2);
        cp16(&Bs[0][arow + 96][ac4], Wp3);
        cp_commit();
    }

    float acc[2][4][4];
    #pragma unroll
    for (int i = 0; i < 2; i++)
        #pragma unroll
        for (int j = 0; j < 4; j++)
            #pragma unroll
            for (int r = 0; r < 4; r++) acc[i][j][r] = 0.f;

    for (int c = 0; c < nc; c++) {
        const int buf = c & 1;
        cp_wait0();
        __syncthreads();

        if (c + 1 < nc) {
            const int nb = buf ^ 1, off = (c + 1) * 32;
            cp16(&As[nb][arow][ac4], Ap0 + off);
            cp16(&As[nb][arow + 32][ac4], Ap1 + off);
            cp16(&Bs[nb][arow][ac4], Wp0 + off);
            cp16(&Bs[nb][arow + 32][ac4], Wp1 + off);
            cp16(&Bs[nb][arow + 64][ac4], Wp2 + off);
            cp16(&Bs[nb][arow + 96][ac4], Wp3 + off);
            cp_commit();
        }

        #pragma unroll
        for (int ks = 0; ks < 4; ks++) {
            const int kk = ks * 8;
            uint32_t af[2][4], bf[4][2];
            ldsm4(af[0][0], af[0][1], af[0][2], af[0][3],
                  &As[buf][a_row][kk + a_col]);
            ldsm4(af[1][0], af[1][1], af[1][2], af[1][3],
                  &As[buf][a_row + 16][kk + a_col]);
            ldsm4(bf[0][0], bf[0][1], bf[1][0], bf[1][1],
                  &Bs[buf][b_row][kk + b_col]);
            ldsm4(bf[2][0], bf[2][1], bf[3][0], bf[3][1],
                  &Bs[buf][b_row + 16][kk + b_col]);
            #pragma unroll
            for (int mt = 0; mt < 2; mt++)
                #pragma unroll
                for (int nt = 0; nt < 4; nt++)
                    mma_tf32(acc[mt][nt], af[mt], bf[nt]);
        }
    }

    #pragma unroll
    for (int mt = 0; mt < 2; mt++) {
        int r = m0 + warp_m * 32 + mt * 16 + g;
        #pragma unroll
        for (int nt = 0; nt < 4; nt++) {
            int n = n0 + warp_n * 32 + nt * 8 + cl * 2;
            float b0 = bias[n], b1 = bias[n + 1];
            acc[mt][nt][0] += b0; acc[mt][nt][1] += b1;
            acc[mt][nt][2] += b0; acc[mt][nt][3] += b1;
            if (MODE == 1) {
                #pragma unroll
                for (int i = 0; i < 4; i++)
                    acc[mt][nt][i] = acc[mt][nt][i] * 0.5f *
                        (1.0f + erff(acc[mt][nt][i] * 0.70710678118654752f));
            }
            if (MODE >= 2) {
                float2 r0 = *(const float2*)(res + (size_t)r * N + n);
                float2 r1 = *(const float2*)(res + (size_t)(r + 8) * N + n);
                acc[mt][nt][0] += r0.x; acc[mt][nt][1] += r0.y;
                acc[mt][nt][2] += r1.x; acc[mt][nt][3] += r1.y;
            }
        }
    }

    if (MODE == 3) {
        __syncthreads();
        float* rsum = (float*)As;            // [64][17]
        float* rsq  = rsum + 64 * 17;        // [64][17]
        float* st   = rsq + 64 * 17;         // [64][2]
        const int slot = warp_n * 4 + cl;
        #pragma unroll
        for (int mt = 0; mt < 2; mt++)
            #pragma unroll
            for (int rh = 0; rh < 2; rh++) {
                int lr = warp_m * 32 + mt * 16 + rh * 8 + g;
                float s = 0.f, q = 0.f;
                #pragma unroll
                for (int nt = 0; nt < 4; nt++) {
                    float v0 = acc[mt][nt][2 * rh], v1 = acc[mt][nt][2 * rh + 1];
                    s += v0 + v1; q += v0 * v0 + v1 * v1;
                }
                rsum[lr * 17 + slot] = s;
                rsq[lr * 17 + slot] = q;
            }
        __syncthreads();
        if (tid < 64) {
            float s = 0.f, q = 0.f;
            #pragma unroll
            for (int i = 0; i < 16; i++) {
                s += rsum[tid * 17 + i];
                q += rsq[tid * 17 + i];
            }
            float mean = s * (1.f / 128.f);
            float var = q * (1.f / 128.f) - mean * mean;
            st[tid * 2]     = mean;
            st[tid * 2 + 1] = rsqrtf(var + 1e-5f);
        }
        __syncthreads();
        #pragma unroll
        for (int mt = 0; mt < 2; mt++) {
            #pragma unroll
            for (int rh = 0; rh < 2; rh++) {
                int lr = warp_m * 32 + mt * 16 + rh * 8 + g;
                int r = m0 + lr;
                float mean = st[lr * 2], rstd = st[lr * 2 + 1];
                #pragma unroll
                for (int nt = 0; nt < 4; nt++) {
                    int n = n0 + warp_n * 32 + nt * 8 + cl * 2;
                    float v0 = acc[mt][nt][2 * rh], v1 = acc[mt][nt][2 * rh + 1];
                    *(float2*)(C + (size_t)r * N + n) = make_float2(v0, v1);
                    float h0 = tf32f((v0 - mean) * rstd * lns[n] + lnb[n]);
                    float h1 = tf32f((v1 - mean) * rstd * lns[n + 1] + lnb[n + 1]);
                    *(float2*)(Hout + (size_t)r * N + n) = make_float2(h0, h1);
                }
            }
        }
    } else {
        #pragma unroll
        for (int mt = 0; mt < 2; mt++) {
            int r = m0 + warp_m * 32 + mt * 16 + g;
            #pragma unroll
            for (int nt = 0; nt < 4; nt++) {
                int n = n0 + warp_n * 32 + nt * 8 + cl * 2;
                float v0 = acc[mt][nt][0], v1 = acc[mt][nt][1];
                float v2 = acc[mt][nt][2], v3 = acc[mt][nt][3];
                if (MODE <= 1) {
                    v0 = tf32f(v0); v1 = tf32f(v1);
                    v2 = tf32f(v2); v3 = tf32f(v3);
                }
                *(float2*)(C + (size_t)r * N + n)       = make_float2(v0, v1);
                *(float2*)(C + (size_t)(r + 8) * N + n) = make_float2(v2, v3);
            }
        }
    }
}

// ---------------------------------------------------------------------------
// Conv 3x3 s2 p1 as implicit GEMM on tensor cores: M=16384, N=128, K=2304.
// ---------------------------------------------------------------------------
__global__ __launch_bounds__(256)
void conv_mma(const float* __restrict__ feat, const float* __restrict__ W,
              const float* __restrict__ cb, const float* __restrict__ pos,
              float* __restrict__ x)
{
    __shared__ uint32_t As[64][SK];
    __shared__ uint32_t Bs[128][SK];
    const int K = 2304;
    const int tid = threadIdx.x;
    const int lane = tid & 31, wid = tid >> 5;
    const int warp_m = wid >> 2, warp_n = wid & 3;
    const int m0 = blockIdx.y * 64;
    const int g = lane >> 2, cl = lane & 3;

    float acc[2][4][4];
    #pragma unroll
    for (int i = 0; i < 2; i++)
        #pragma unroll
        for (int j = 0; j < 4; j++)
            #pragma unroll
            for (int r = 0; r < 4; r++) acc[i][j][r] = 0.f;

    for (int k0 = 0; k0 < K; k0 += 32) {
        #pragma unroll
        for (int it = 0; it < 8; it++) {
            int e = tid + it * 256;
            int ml = e >> 5, kl = e & 31;
            int m = m0 + ml;
            int k = k0 + kl;
            int b = m >> 8, p = m & 255;
            int y = p >> 4, xx = p & 15;
            int c = k / 9, rr = k - c * 9;
            int ky = rr / 3, kx = rr - ky * 3;
            int iy = y * 2 - 1 + ky;
            int ix = xx * 2 - 1 + kx;
            float v = 0.f;
            if (iy >= 0 && iy < 32 && ix >= 0 && ix < 32)
                v = feat[(((size_t)b * 256 + c) * 32 + iy) * 32 + ix];
            As[ml][kl] = to_tf32(v);
        }
        #pragma unroll
        for (int it = 0; it < 4; it++) {
            int e = tid + it * 256;
            int row = e >> 3, c4 = (e & 7) * 4;
            float4 v = *(const float4*)(W + (size_t)row * K + k0 + c4);
            Bs[row][c4 + 0] = to_tf32(v.x);
            Bs[row][c4 + 1] = to_tf32(v.y);
            Bs[row][c4 + 2] = to_tf32(v.z);
            Bs[row][c4 + 3] = to_tf32(v.w);
        }
        __syncthreads();

        #pragma unroll
        for (int ks = 0; ks < 4; ks++) {
            const int kk = ks * 8;
            uint32_t af[2][4], bf[4][2];
            #pragma unroll
            for (int mt = 0; mt < 2; mt++) {
                int r = warp_m * 32 + mt * 16 + g;
                af[mt][0] = As[r][kk + cl];
                af[mt][1] = As[r + 8][kk + cl];
                af[mt][2] = As[r][kk + 4 + cl];
                af[mt][3] = As[r + 8][kk + 4 + cl];
            }
            #pragma unroll
            for (int nt = 0; nt < 4; nt++) {
                int n = warp_n * 32 + nt * 8 + g;
                bf[nt][0] = Bs[n][kk + cl];
                bf[nt][1] = Bs[n][kk + 4 + cl];
            }
            #pragma unroll
            for (int mt = 0; mt < 2; mt++)
                #pragma unroll
                for (int nt = 0; nt < 4; nt++)
                    mma_tf32(acc[mt][nt], af[mt], bf[nt]);
        }
        __syncthreads();
    }

    #pragma unroll
    for (int mt = 0; mt < 2; mt++) {
        int r = m0 + warp_m * 32 + mt * 16 + g;
        #pragma unroll
        for (int rr = 0; rr < 2; rr++) {
            int m = r + rr * 8;
            int b = m >> 8, p = m & 255;
            float* dst = x + ((size_t)b * NTOK + p + 1) * 128;
            const float* pp = pos + (size_t)(p + 1) * 128;
            #pragma unroll
            for (int nt = 0; nt < 4; nt++) {
                int n = warp_n * 32 + nt * 8 + cl * 2;
                float v0 = acc[mt][nt][rr * 2 + 0] + cb[n] + pp[n];
                float v1 = acc[mt][nt][rr * 2 + 1] + cb[n + 1] + pp[n + 1];
                *(float2*)(dst + n) = make_float2(v0, v1);
            }
        }
    }
}

// cls token rows: x[b,0,:] = cls + pos[0]
__global__ void cls_kernel(const float* __restrict__ cls,
                           const float* __restrict__ pos, float* __restrict__ x)
{
    int b = blockIdx.x, e = threadIdx.x;
    x[(size_t)b * NTOK * 128 + e] = cls[e] + pos[e];
}

// ---------------------------------------------------------------------------
// LayerNorm over E=128 (used once, before layer 0). Output tf32-rounded.
// ---------------------------------------------------------------------------
__global__ __launch_bounds__(256)
void ln_kernel(const float* __restrict__ x, float* __restrict__ h,
               const float* __restrict__ s, const float* __restrict__ b, float eps)
{
    int tok = blockIdx.x * 8 + (threadIdx.x >> 5);
    int lane = threadIdx.x & 31;
    if (tok >= TOKENS) return;
    const float4* xr = (const float4*)(x + (size_t)tok * 128);
    float4 v = xr[lane];
    float mean = warp_sum(v.x + v.y + v.z + v.w) * (1.f / 128.f);
    float dx = v.x - mean, dy = v.y - mean, dz = v.z - mean, dw = v.w - mean;
    float var = warp_sum(dx * dx + dy * dy + dz * dz + dw * dw) * (1.f / 128.f);
    float rstd = rsqrtf(var + eps);
    float4 sv = ((const float4*)s)[lane];
    float4 bv = ((const float4*)b)[lane];
    float4 o;
    o.x = tf32f(dx * rstd * sv.x + bv.x);
    o.y = tf32f(dy * rstd * sv.y + bv.y);
    o.z = tf32f(dz * rstd * sv.z + bv.z);
    o.w = tf32f(dw * rstd * sv.w + bv.w);
    ((float4*)(h + (size_t)tok * 128))[lane] = o;
}

// ---------------------------------------------------------------------------
// Full tensor-core attention; fragments via ldmatrix; stage-2 Q read from
// smem (identical tf32 bits to global). Ps/Vt row stride 268 (conflict-free).
// ---------------------------------------------------------------------------
#define VSTR 268
#define OFF_VT 9252             // u32 [32][268]
#define OFF_QT 17828            // u32 [32][36]
#define OFF_PS 18980            // f32/u32 [32][268]; also [8][32][33] partials
#define OFF_INV 27556           // f32 [32]
#define OFF_P256 27588          // f32 [32]
#define ATT_SMEM ((27620 + 28) * 4)   // 110592 B

__global__ __launch_bounds__(256)
void attn_kernel(const float* __restrict__ qkv, float* __restrict__ o)
{
    extern __shared__ float sm[];
    uint32_t* Kt = (uint32_t*)sm;               // [257][36]
    uint32_t* Vt = (uint32_t*)(sm + OFF_VT);    // [32][268] V^T
    uint32_t* Qt = (uint32_t*)(sm + OFF_QT);    // [32][36]
    float*    Ps = sm + OFF_PS;                 // [32][268] S/P, then partials
    uint32_t* Pu = (uint32_t*)Ps;
    float*    invs = sm + OFF_INV;              // [32]
    float*    p256s = sm + OFF_P256;            // [32]

    int b = blockIdx.x, h = blockIdx.y, z = blockIdx.z;
    int tid = threadIdx.x, w = tid >> 5, lane = tid & 31;
    const int g = lane >> 2, cl = lane & 3;
    const float* base = qkv + (size_t)b * NTOK * 384 + h * 32;

    const int la_row = lane & 15;
    const int la_col = (lane >> 4) << 2;
    const int lb_row = (lane & 7) + ((lane & 16) >> 1);
    const int lb_col = ((lane >> 3) & 1) << 2;

    for (int i = tid; i < 257 * 32; i += 256) {
        int m = i >> 5, d = i & 31;
        const float* p = base + (size_t)m * 384;
        Kt[m * 36 + d] = __float_as_uint(p[128 + d]);
        Vt[d * VSTR + m] = __float_as_uint(p[256 + d]);
    }
    __syncthreads();

    const float scale = 0.17677669529663687f;  // 1/sqrt(32)
    const float k256 = __uint_as_float(Kt[256 * 36 + lane]);

    for (int t = z * 3; t < z * 3 + 3; t++) {
        if (t * 32 >= NTOK) break;

        {
            int row = tid >> 3, d4 = (tid & 7) * 4;
            int q = t * 32 + row;
            float4 v = make_float4(0.f, 0.f, 0.f, 0.f);
            if (q < NTOK) v = *(const float4*)(base + (size_t)q * 384 + d4);
            Qt[row * 36 + d4 + 0] = __float_as_uint(v.x);
            Qt[row * 36 + d4 + 1] = __float_as_uint(v.y);
            Qt[row * 36 + d4 + 2] = __float_as_uint(v.z);
            Qt[row * 36 + d4 + 3] = __float_as_uint(v.w);
        }
        __syncthreads();

        // ---- stage 1: S(32q x 32k) per warp for keys [32w, 32w+32) ----
        {
            float s[2][4][4];
            #pragma unroll
            for (int mt = 0; mt < 2; mt++)
                #pragma unroll
                for (int nt = 0; nt < 4; nt++)
                    #pragma unroll
                    for (int r = 0; r < 4; r++) s[mt][nt][r] = 0.f;
            #pragma unroll
            for (int ks = 0; ks < 4; ks++) {
                const int kk = ks * 8;
                uint32_t aq[2][4], bk[4][2];
                ldsm4(aq[0][0], aq[0][1], aq[0][2], aq[0][3],
                      &Qt[la_row * 36 + kk + la_col]);
                ldsm4(aq[1][0], aq[1][1], aq[1][2], aq[1][3],
                      &Qt[(la_row + 16) * 36 + kk + la_col]);
                ldsm4(bk[0][0], bk[0][1], bk[1][0], bk[1][1],
                      &Kt[(w * 32 + lb_row) * 36 + kk + lb_col]);
                ldsm4(bk[2][0], bk[2][1], bk[3][0], bk[3][1],
                      &Kt[(w * 32 + lb_row + 16) * 36 + kk + lb_col]);
                #pragma unroll
                for (int mt = 0; mt < 2; mt++)
                    #pragma unroll
                    for (int nt = 0; nt < 4; nt++)
                        mma_tf32(s[mt][nt], aq[mt], bk[nt]);
            }
            #pragma unroll
            for (int mt = 0; mt < 2; mt++) {
                int row = mt * 16 + g;
                #pragma unroll
                for (int nt = 0; nt < 4; nt++) {
                    int col = w * 32 + nt * 8 + 2 * cl;
                    Ps[row * VSTR + col]           = s[mt][nt][0];
                    Ps[row * VSTR + col + 1]       = s[mt][nt][1];
                    Ps[(row + 8) * VSTR + col]     = s[mt][nt][2];
                    Ps[(row + 8) * VSTR + col + 1] = s[mt][nt][3];
                }
            }
        }
        __syncthreads();

        // ---- stage 2: softmax-lite on own 4 query rows (Q from smem) ----
        #pragma unroll
        for (int qq = 0; qq < 4; qq++) {
            int qloc = w * 4 + qq;
            float qd = __uint_as_float(Qt[qloc * 36 + lane]);  // same bits as global
            float s256 = warp_sum(qd * k256) * scale;
            float p[8];
            float ls = 0.f;
            #pragma unroll
            for (int j = 0; j < 8; j++) {
                p[j] = __expf(Ps[qloc * VSTR + lane + 32 * j] * scale);
                ls += p[j];
            }
            float p256 = __expf(s256);
            ls = warp_sum(ls) + p256;
            #pragma unroll
            for (int j = 0; j < 8; j++)
                Pu[qloc * VSTR + lane + 32 * j] = to_tf32(p[j]);
            if (lane == 0) {
                invs[qloc] = 1.f / ls;
                p256s[qloc] = p256;
            }
        }
        __syncthreads();

        // ---- stage 3: partial O(32q x 32d) for keys [32w, 32w+32) ----
        float pacc[2][4][4];
        #pragma unroll
        for (int mt = 0; mt < 2; mt++)
            #pragma unroll
            for (int nt = 0; nt < 4; nt++)
                #pragma unroll
                for (int r = 0; r < 4; r++) pacc[mt][nt][r] = 0.f;
        {
            const int k0 = w * 32;
            #pragma unroll
            for (int ks = 0; ks < 4; ks++) {
                const int kk = k0 + ks * 8;
                uint32_t ap[2][4], bv[4][2];
                ldsm4(ap[0][0], ap[0][1], ap[0][2], ap[0][3],
                      &Pu[la_row * VSTR + kk + la_col]);
                ldsm4(ap[1][0], ap[1][1], ap[1][2], ap[1][3],
                      &Pu[(la_row + 16) * VSTR + kk + la_col]);
                ldsm4(bv[0][0], bv[0][1], bv[1][0], bv[1][1],
                      &Vt[lb_row * VSTR + kk + lb_col]);
                ldsm4(bv[2][0], bv[2][1], bv[3][0], bv[3][1],
                      &Vt[(lb_row + 16) * VSTR + kk + lb_col]);
                #pragma unroll
                for (int mt = 0; mt < 2; mt++)
                    #pragma unroll
                    for (int nt = 0; nt < 4; nt++)
                        mma_tf32(pacc[mt][nt], ap[mt], bv[nt]);
            }
        }
        __syncthreads();

        // ---- stage 4a: write partials [8][32][33] into Ps region ----
        {
            float* Pr = Ps + w * 1056;
            #pragma unroll
            for (int mt = 0; mt < 2; mt++) {
                int row = mt * 16 + g;
                #pragma unroll
                for (int nt = 0; nt < 4; nt++) {
                    int d0 = nt * 8 + 2 * cl;
                    Pr[row * 33 + d0]           = pacc[mt][nt][0];
                    Pr[row * 33 + d0 + 1]       = pacc[mt][nt][1];
                    Pr[(row + 8) * 33 + d0]     = pacc[mt][nt][2];
                    Pr[(row + 8) * 33 + d0 + 1] = pacc[mt][nt][3];
                }
            }
        }
        __syncthreads();

        // ---- stage 4b: reduce + key-256 + normalize, tf32 store ----
        {
            int q = tid >> 3;
            int d0 = (tid & 7) * 4;
            int qglob = t * 32 + q;
            float r0 = 0.f, r1 = 0.f, r2 = 0.f, r3 = 0.f;
            #pragma unroll
            for (int ww = 0; ww < 8; ww++) {
                const float* Pr = Ps + ww * 1056 + q * 33 + d0;
                r0 += Pr[0]; r1 += Pr[1]; r2 += Pr[2]; r3 += Pr[3];
            }
            float pk = p256s[q];
            r0 += pk * __uint_as_float(Vt[(d0 + 0) * VSTR + 256]);
            r1 += pk * __uint_as_float(Vt[(d0 + 1) * VSTR + 256]);
            r2 += pk * __uint_as_float(Vt[(d0 + 2) * VSTR + 256]);
            r3 += pk * __uint_as_float(Vt[(d0 + 3) * VSTR + 256]);
            float inv = invs[q];
            if (qglob < NTOK) {
                float4 res = make_float4(tf32f(r0 * inv), tf32f(r1 * inv),
                                         tf32f(r2 * inv), tf32f(r3 * inv));
                *(float4*)(o + ((size_t)b * NTOK + qglob) * 128 + h * 32 + d0) = res;
            }
        }
        __syncthreads();
    }
}

// ---------------------------------------------------------------------------
// Head: final LN (eps 1e-6) on token 0 of each batch, out_feat + fc.
// ---------------------------------------------------------------------------
__global__ __launch_bounds__(128)
void head_kernel(const float* __restrict__ x, const float* __restrict__ fns,
                 const float* __restrict__ fnb, const float* __restrict__ fcw,
                 const float* __restrict__ fcb, float* __restrict__ out)
{
    __shared__ float red[4];
    __shared__ float fsh[128];
    int b = blockIdx.x, t = threadIdx.x, w = t >> 5, lane = t & 31;
    float v = x[(size_t)b * NTOK * 128 + t];

    float s = warp_sum(v);
    if (lane == 0) red[w] = s;
    __syncthreads();
    float mean = (red[0] + red[1] + red[2] + red[3]) * (1.f / 128.f);
    __syncthreads();
    float d = v - mean;
    float sq = warp_sum(d * d);
    if (lane == 0) red[w] = sq;
    __syncthreads();
    float var = (red[0] + red[1] + red[2] + red[3]) * (1.f / 128.f);
    float rstd = rsqrtf(var + 1e-6f);
    float f = d * rstd * fns[t] + fnb[t];
    out[128 + (size_t)b * 128 + t] = f;
    fsh[t] = f;
    __syncthreads();
    if (t < 2) {
        float a = fcb[t];
        for (int e = 0; e < 128; e++) a += fsh[e] * fcw[t * 128 + e];
        out[b * 2 + t] = a;
    }
}

// ---------------------------------------------------------------------------
extern "C" void kernel_launch(void* const* d_in, const int* in_sizes, int n_in,
                              void* d_out, int out_size)
{
    const float* feat    = (const float*)d_in[0];
    const float* conv_w  = (const float*)d_in[1];
    const float* conv_b  = (const float*)d_in[2];
    const float* pos_emb = (const float*)d_in[3];
    const float* cls_tok = (const float*)d_in[4];
    const float* ln1_s   = (const float*)d_in[5];
    const float* ln1_b   = (const float*)d_in[6];
    const float* qkv_w   = (const float*)d_in[7];
    const float* qkv_b   = (const float*)d_in[8];
    const float* proj_w  = (const float*)d_in[9];
    const float* proj_b  = (const float*)d_in[10];
    const float* ln2_s   = (const float*)d_in[11];
    const float* ln2_b   = (const float*)d_in[12];
    const float* ffn1_w  = (const float*)d_in[13];
    const float* ffn1_b  = (const float*)d_in[14];
    const float* ffn2_w  = (const float*)d_in[15];
    const float* ffn2_b  = (const float*)d_in[16];
    const float* fn_s    = (const float*)d_in[17];
    const float* fn_b    = (const float*)d_in[18];
    const float* fc_w    = (const float*)d_in[19];
    const float* fc_b    = (const float*)d_in[20];
    float* out = (float*)d_out;

    float *px, *ph, *pq, *po, *pf, *wq, *wp, *w1, *w2;
    cudaGetSymbolAddress((void**)&px, g_x);
    cudaGetSymbolAddress((void**)&ph, g_h);
    cudaGetSymbolAddress((void**)&pq, g_qkv);
    cudaGetSymbolAddress((void**)&po, g_o);
    cudaGetSymbolAddress((void**)&pf, g_ffn);
    cudaGetSymbolAddress((void**)&wq, g_wqkv);
    cudaGetSymbolAddress((void**)&wp, g_wproj);
    cudaGetSymbolAddress((void**)&w1, g_wf1);
    cudaGetSymbolAddress((void**)&w2, g_wf2);

    cudaFuncSetAttribute(attn_kernel, cudaFuncAttributeMaxDynamicSharedMemorySize, ATT_SMEM);

    // weight pre-conversion (tf32 rounding, ~5us)
    {
        int nq = 12 * 384 * 128 / 4, np = 12 * 128 * 128 / 4;
        int n1 = 12 * 512 * 128 / 4, n2 = 12 * 128 * 512 / 4;
        cvtw_kernel<<<(nq + 255) / 256, 256>>>((const float4*)qkv_w, (float4*)wq, nq);
        cvtw_kernel<<<(np + 255) / 256, 256>>>((const float4*)proj_w, (float4*)wp, np);
        cvtw_kernel<<<(n1 + 255) / 256, 256>>>((const float4*)ffn1_w, (float4*)w1, n1);
        cvtw_kernel<<<(n2 + 255) / 256, 256>>>((const float4*)ffn2_w, (float4*)w2, n2);
    }

    cls_kernel<<<BATCH, 128>>>(cls_tok, pos_emb, px);
    conv_mma<<<dim3(1, 256), 256>>>(feat, conv_w, conv_b, pos_emb, px);
    ln_kernel<<<TOKENS / 8, 256>>>(px, ph, ln1_s, ln1_b, 1e-5f);

    for (int l = 0; l < 12; l++) {
        gemm_mma<0><<<dim3(3, 257), 256>>>(
            ph, wq + (size_t)l * 384 * 128, nullptr, nullptr,
            qkv_b + l * 384, nullptr, pq, nullptr, TOKENS, 384, 128);
        attn_kernel<<<dim3(BATCH, 4, 3), 256, ATT_SMEM>>>(pq, po);
        gemm_mma<3><<<dim3(1, 257), 256>>>(
            po, wp + (size_t)l * 128 * 128, ln2_s + l * 128, ln2_b + l * 128,
            proj_b + l * 128, px, px, ph, TOKENS, 128, 128);
        gemm_mma<1><<<dim3(4, 257), 256>>>(
            ph, w1 + (size_t)l * 512 * 128, nullptr, nullptr,
            ffn1_b + l * 512, nullptr, pf, nullptr, TOKENS, 512, 128);
        if (l < 11) {
            gemm_mma<3><<<dim3(1, 257), 256>>>(
                pf, w2 + (size_t)l * 128 * 512,
                ln1_s + (l + 1) * 128, ln1_b + (l + 1) * 128,
                ffn2_b + l * 128, px, px, ph, TOKENS, 128, 512);
        } else {
            gemm_mma<2><<<dim3(1, 257), 256>>>(
                pf, w2 + (size_t)l * 128 * 512, nullptr, nullptr,
                ffn2_b + l * 128, px, px, nullptr, TOKENS, 128, 512);
        }
    }

    head_kernel<<<BATCH, 128>>>(px, fn_s, fn_b, fc_w, fc_b, out);
}